// round 10
// baseline (speedup 1.0000x reference)
#include <cuda_runtime.h>
#include <cstdint>
#include <math.h>

// ---------------- problem constants ----------------
#define NA 50000
#define NP 50000
#define EDG 400000
#define KH 8
#define DH 32
#define KD 256
#define SLOPE 0.2f

// GEMM tiling: block 128(M) x 128(N), 8 warps (4m x 2n), warp tile 32x64, BK=16 (tf32)
// 2 CTAs/SM for latency hiding.
#define BM 128
#define BN 128
#define BK 16
#define NKT (KD / BK)      // 16
#define LDA 132            // As [k][m] stride (u32)
#define LDB 132            // Bs [k][n] stride (u32)

#define NBLK 196           // ceil(50000/256)

// ---------------- device scratch ----------------
__device__ float g_PA[NA * KD];
__device__ float g_PP[NP * KD];

__device__ float g_elA_aA[NA * KH];
__device__ float g_erP_aA[NP * KH];
__device__ float g_elP_aP[NP * KH];
__device__ float g_erA_aP[NA * KH];
__device__ float g_erP_aP[NP * KH];

__device__ float g_ft_w[NP * KD];
__device__ float g_ft_wb[NA * KD];
__device__ float g_ft_c[NP * KD];

__device__ float g_rf_w[NP * KD];
__device__ float g_rf_c[NP * KD];
__device__ float g_nodeP[NP * KD];

// CSR scratch, one set per relation
__device__ int g_counts[3][50000];
__device__ int g_cursor[3][50000];
__device__ int g_offsets[3][50001];
__device__ int g_partials[3][NBLK + 1];
__device__ int g_ssort[3][EDG];

// ---------------- helpers ----------------
__device__ __forceinline__ float leaky(float v) {
    return v > 0.f ? v : SLOPE * v;
}
__device__ __forceinline__ uint32_t f2tf32(float f) {
    uint32_t r;
    asm("cvt.rna.tf32.f32 %0, %1;" : "=r"(r) : "f"(f));
    return r;
}
__device__ __forceinline__ void mma_tf32(float c[4], uint32_t a0, uint32_t a1,
                                         uint32_t a2, uint32_t a3,
                                         uint32_t b0, uint32_t b1) {
    asm volatile(
        "mma.sync.aligned.m16n8k8.row.col.f32.tf32.tf32.f32 "
        "{%0,%1,%2,%3}, {%4,%5,%6,%7}, {%8,%9}, {%0,%1,%2,%3};"
        : "+f"(c[0]), "+f"(c[1]), "+f"(c[2]), "+f"(c[3])
        : "r"(a0), "r"(a1), "r"(a2), "r"(a3), "r"(b0), "r"(b1));
}

struct GemmJob {
    const float* A;
    const float* B;
    float*       C;
    const float* bias;
    const float* gate;
    const float* av0; float* ao0;   // fused attn dots: atomicAdd partials (zeroed beforehand)
    const float* av1; float* ao1;
    const float* av2; float* ao2;
};

// ---------------- multi-job tf32 GEMM, 128x128 block, 2 CTAs/SM ----------------
__global__ void __launch_bounds__(256, 2) gemm_multi(
    GemmJob j0, GemmJob j1, GemmJob j2, int nb, int M)
{
    __shared__ uint32_t As[2][BK][LDA];   // [k][m]
    __shared__ uint32_t Bs[2][BK][LDB];   // [k][n]

    const int tid = threadIdx.x;
    const int lane = tid & 31;
    const int wid = tid >> 5;
    const int wm = (wid & 3) * 32;
    const int wn = (wid >> 2) * 64;
    const int n0 = blockIdx.x * BN;
    const int m0 = blockIdx.y * BM;

    const int qr = lane >> 2;
    const int qc = lane & 3;

    const int am = tid >> 1;           // A row 0..127
    const int aq = (tid & 1) * 8;      // A k offset 0 or 8
    const int bkr = tid >> 4;          // B k row 0..15
    const int bnc = (tid & 15) * 8;    // B n offset 0..120

    float4 rA[2], rB[2];

    auto g_load = [&](int kt, const float* __restrict__ A, const float* __restrict__ B) {
        const int k0 = kt * BK;
        int row = m0 + am;
        if (row < M) {
            rA[0] = *(const float4*)&A[(size_t)row * KD + k0 + aq];
            rA[1] = *(const float4*)&A[(size_t)row * KD + k0 + aq + 4];
        } else {
            rA[0] = make_float4(0.f, 0.f, 0.f, 0.f);
            rA[1] = rA[0];
        }
        const float* bp = &B[(size_t)(k0 + bkr) * KD + n0 + bnc];
        rB[0] = *(const float4*)&bp[0];
        rB[1] = *(const float4*)&bp[4];
    };
    auto s_store = [&](int buf) {
        As[buf][aq + 0][am] = f2tf32(rA[0].x);
        As[buf][aq + 1][am] = f2tf32(rA[0].y);
        As[buf][aq + 2][am] = f2tf32(rA[0].z);
        As[buf][aq + 3][am] = f2tf32(rA[0].w);
        As[buf][aq + 4][am] = f2tf32(rA[1].x);
        As[buf][aq + 5][am] = f2tf32(rA[1].y);
        As[buf][aq + 6][am] = f2tf32(rA[1].z);
        As[buf][aq + 7][am] = f2tf32(rA[1].w);
        uint4 w0, w1;
        w0.x = f2tf32(rB[0].x); w0.y = f2tf32(rB[0].y);
        w0.z = f2tf32(rB[0].z); w0.w = f2tf32(rB[0].w);
        w1.x = f2tf32(rB[1].x); w1.y = f2tf32(rB[1].y);
        w1.z = f2tf32(rB[1].z); w1.w = f2tf32(rB[1].w);
        *(uint4*)&Bs[buf][bkr][bnc + 0] = w0;
        *(uint4*)&Bs[buf][bkr][bnc + 4] = w1;
    };

#pragma unroll
    for (int o = 0; o < 3; o++) {
        if (o >= nb) break;
        const GemmJob J = (o == 0) ? j0 : (o == 1) ? j1 : j2;

        float acc[2][8][4];
#pragma unroll
        for (int mi = 0; mi < 2; mi++)
#pragma unroll
            for (int ni = 0; ni < 8; ni++)
#pragma unroll
                for (int r = 0; r < 4; r++) acc[mi][ni][r] = 0.f;

        g_load(0, J.A, J.B);
        s_store(0);
        __syncthreads();

        for (int kt = 0; kt < NKT; kt++) {
            const int cur = kt & 1;
            if (kt + 1 < NKT) g_load(kt + 1, J.A, J.B);

#pragma unroll
            for (int ks = 0; ks < BK; ks += 8) {
                uint32_t a[2][4], b[8][2];
#pragma unroll
                for (int mi = 0; mi < 2; mi++) {
                    int mb = wm + mi * 16;
                    a[mi][0] = As[cur][ks + qc][mb + qr];
                    a[mi][1] = As[cur][ks + qc][mb + qr + 8];
                    a[mi][2] = As[cur][ks + qc + 4][mb + qr];
                    a[mi][3] = As[cur][ks + qc + 4][mb + qr + 8];
                }
#pragma unroll
                for (int ni = 0; ni < 8; ni++) {
                    int nb2 = wn + ni * 8;
                    b[ni][0] = Bs[cur][ks + qc][nb2 + qr];
                    b[ni][1] = Bs[cur][ks + qc + 4][nb2 + qr];
                }
#pragma unroll
                for (int mi = 0; mi < 2; mi++)
#pragma unroll
                    for (int ni = 0; ni < 8; ni++)
                        mma_tf32(acc[mi][ni], a[mi][0], a[mi][1], a[mi][2], a[mi][3],
                                 b[ni][0], b[ni][1]);
            }

            if (kt + 1 < NKT) {
                s_store(1 - cur);
                __syncthreads();
            }
        }

        // ---- fused attention dots: partial over this block's 128 cols, atomicAdd ----
        if (J.av0) {
            const float* avs[3] = { J.av0, J.av1, J.av2 };
            float*       aos[3] = { J.ao0, J.ao1, J.ao2 };
            const int h0 = (n0 + wn) >> 5;   // first head covered by this warp
#pragma unroll
            for (int t = 0; t < 3; t++) {
                const float* av = avs[t];
                if (!av) break;
                float* ao = aos[t];
                float c0[8], c1[8];
#pragma unroll
                for (int ni = 0; ni < 8; ni++) {
                    int col = n0 + wn + ni * 8 + qc * 2;
                    int idx = (col >> 5) * 64 + (col & 31);
                    c0[ni] = av[idx];
                    c1[ni] = av[idx + 1];
                }
#pragma unroll
                for (int mi = 0; mi < 2; mi++) {
#pragma unroll
                    for (int half = 0; half < 2; half++) {
                        float pa = 0.f, pb = 0.f;
#pragma unroll
                        for (int ni = 0; ni < 4; ni++)
                            pa += acc[mi][ni][half * 2] * c0[ni]
                                + acc[mi][ni][half * 2 + 1] * c1[ni];
#pragma unroll
                        for (int ni = 4; ni < 8; ni++)
                            pb += acc[mi][ni][half * 2] * c0[ni]
                                + acc[mi][ni][half * 2 + 1] * c1[ni];
                        pa += __shfl_xor_sync(0xffffffffu, pa, 1);
                        pa += __shfl_xor_sync(0xffffffffu, pa, 2);
                        pb += __shfl_xor_sync(0xffffffffu, pb, 1);
                        pb += __shfl_xor_sync(0xffffffffu, pb, 2);
                        int row = m0 + wm + mi * 16 + qr + half * 8;
                        if (qc == 0 && row < M) {
                            atomicAdd(&ao[row * KH + h0],     pa);
                            atomicAdd(&ao[row * KH + h0 + 1], pb);
                        }
                    }
                }
            }
        }

        float g = 0.f;
        if (J.gate) g = 1.f / (1.f + __expf(-J.gate[0]));

        // ---- C epilogue ----
#pragma unroll
        for (int mi = 0; mi < 2; mi++) {
#pragma unroll
            for (int half = 0; half < 2; half++) {
                int row = m0 + wm + mi * 16 + qr + half * 8;
                if (row >= M) continue;
                float* dst = &J.C[(size_t)row * KD + n0 + wn];
#pragma unroll
                for (int ni = 0; ni < 8; ni++) {
                    int col = ni * 8 + qc * 2;
                    float2 v;
                    v.x = acc[mi][ni][half * 2 + 0];
                    v.y = acc[mi][ni][half * 2 + 1];
                    if (J.bias) {
                        v.x += J.bias[n0 + wn + col + 0];
                        v.y += J.bias[n0 + wn + col + 1];
                    }
                    if (J.gate) {
                        float2 prev = *(const float2*)&dst[col];
                        v.x = g * v.x + (1.f - g) * prev.x;
                        v.y = g * v.y + (1.f - g) * prev.y;
                    }
                    *(float2*)&dst[col] = v;
                }
            }
        }
        __syncthreads();
    }
}

// ---------------- CSR build ----------------
__global__ void csr_hist(const int* __restrict__ dst, int* __restrict__ counts)
{
    int e = blockIdx.x * blockDim.x + threadIdx.x;
    if (e < EDG) atomicAdd(&counts[dst[e]], 1);
}

__global__ void scan_block(const int* __restrict__ in, int* __restrict__ out,
                           int* __restrict__ partials, int n)
{
    __shared__ int wsum[8];
    int i = blockIdx.x * 256 + threadIdx.x;
    int lane = threadIdx.x & 31, wid = threadIdx.x >> 5;
    int v = (i < n) ? in[i] : 0;
    int x = v;
#pragma unroll
    for (int o = 1; o < 32; o <<= 1) {
        int t = __shfl_up_sync(0xffffffffu, x, o);
        if (lane >= o) x += t;
    }
    if (lane == 31) wsum[wid] = x;
    __syncthreads();
    if (wid == 0) {
        int w = (lane < 8) ? wsum[lane] : 0;
#pragma unroll
        for (int o = 1; o < 8; o <<= 1) {
            int t = __shfl_up_sync(0xffffffffu, w, o);
            if (lane >= o) w += t;
        }
        if (lane < 8) wsum[lane] = w;
    }
    __syncthreads();
    int wpre = (wid > 0) ? wsum[wid - 1] : 0;
    if (i < n) out[i] = wpre + x - v;
    if (threadIdx.x == 0) partials[blockIdx.x] = wsum[7];
}

__global__ void scan_top(int* __restrict__ partials, int nb)
{
    __shared__ int wsum[8];
    int i = threadIdx.x;
    int lane = i & 31, wid = i >> 5;
    int v = (i < nb) ? partials[i] : 0;
    int x = v;
#pragma unroll
    for (int o = 1; o < 32; o <<= 1) {
        int t = __shfl_up_sync(0xffffffffu, x, o);
        if (lane >= o) x += t;
    }
    if (lane == 31) wsum[wid] = x;
    __syncthreads();
    if (wid == 0) {
        int w = (lane < 8) ? wsum[lane] : 0;
#pragma unroll
        for (int o = 1; o < 8; o <<= 1) {
            int t = __shfl_up_sync(0xffffffffu, w, o);
            if (lane >= o) w += t;
        }
        if (lane < 8) wsum[lane] = w;
    }
    __syncthreads();
    int wpre = (wid > 0) ? wsum[wid - 1] : 0;
    if (i < nb) partials[i] = wpre + x - v;
    if (i == 0) partials[nb] = wsum[7];
}

__global__ void scan_add(int* __restrict__ offsets, const int* __restrict__ partials, int n)
{
    int i = blockIdx.x * 256 + threadIdx.x;
    if (i < n) offsets[i] += partials[blockIdx.x];
    if (i == 0) offsets[n] = partials[gridDim.x];
}

__global__ void csr_scatter(const int* __restrict__ src, const int* __restrict__ dst,
                            const int* __restrict__ offsets, int* __restrict__ cursor,
                            int* __restrict__ ssort)
{
    int e = blockIdx.x * blockDim.x + threadIdx.x;
    if (e >= EDG) return;
    int d = dst[e];
    int pos = offsets[d] + atomicAdd(&cursor[d], 1);
    ssort[pos] = src[e];
}

// ---------------- fused micro gather ----------------
__global__ void micro_gather(const int* __restrict__ ssort, const int* __restrict__ offsets,
                             const float* __restrict__ el, const float* __restrict__ er,
                             const float* __restrict__ Psrc, float* __restrict__ ft, int n_dst)
{
    int d = (blockIdx.x * blockDim.x + threadIdx.x) >> 5;
    int lane = threadIdx.x & 31;
    if (d >= n_dst) return;
    int beg = offsets[d], end = offsets[d + 1];
    float* dstp = &ft[(size_t)d * KD + lane * 8];
    if (beg == end) {
        float4 z = make_float4(0.f, 0.f, 0.f, 0.f);
        *(float4*)dstp = z;
        *(float4*)(dstp + 4) = z;
        return;
    }
    const int h8 = lane & 7;
    float erh = er[d * KH + h8];

    float mx = -1e30f;
    {
        int sub = lane >> 3;
        for (int i = beg; i < end; i += 4) {
            int e = i + sub;
            if (e < end) {
                int s = ssort[e];
                mx = fmaxf(mx, leaky(el[s * KH + h8] + erh));
            }
        }
        mx = fmaxf(mx, __shfl_xor_sync(0xffffffffu, mx, 8));
        mx = fmaxf(mx, __shfl_xor_sync(0xffffffffu, mx, 16));
    }

    const int hk = lane >> 2;
    float acc[8] = {0.f, 0.f, 0.f, 0.f, 0.f, 0.f, 0.f, 0.f};
    float se = 0.f;
    int i = beg;
    for (; i + 2 <= end; i += 2) {
        int s0 = ssort[i], s1 = ssort[i + 1];
        float w0 = 0.f, w1 = 0.f;
        if (lane < KH) {
            w0 = __expf(leaky(el[s0 * KH + lane] + erh) - mx);
            w1 = __expf(leaky(el[s1 * KH + lane] + erh) - mx);
            se += w0 + w1;
        }
        float wk0 = __shfl_sync(0xffffffffu, w0, hk);
        float wk1 = __shfl_sync(0xffffffffu, w1, hk);
        const float4* p0 = (const float4*)&Psrc[(size_t)s0 * KD + lane * 8];
        const float4* p1 = (const float4*)&Psrc[(size_t)s1 * KD + lane * 8];
        float4 a0 = p0[0], a1 = p0[1], b0 = p1[0], b1 = p1[1];
        acc[0] = fmaf(wk0, a0.x, acc[0]); acc[0] = fmaf(wk1, b0.x, acc[0]);
        acc[1] = fmaf(wk0, a0.y, acc[1]); acc[1] = fmaf(wk1, b0.y, acc[1]);
        acc[2] = fmaf(wk0, a0.z, acc[2]); acc[2] = fmaf(wk1, b0.z, acc[2]);
        acc[3] = fmaf(wk0, a0.w, acc[3]); acc[3] = fmaf(wk1, b0.w, acc[3]);
        acc[4] = fmaf(wk0, a1.x, acc[4]); acc[4] = fmaf(wk1, b1.x, acc[4]);
        acc[5] = fmaf(wk0, a1.y, acc[5]); acc[5] = fmaf(wk1, b1.y, acc[5]);
        acc[6] = fmaf(wk0, a1.z, acc[6]); acc[6] = fmaf(wk1, b1.z, acc[6]);
        acc[7] = fmaf(wk0, a1.w, acc[7]); acc[7] = fmaf(wk1, b1.w, acc[7]);
    }
    if (i < end) {
        int s0 = ssort[i];
        float w0 = 0.f;
        if (lane < KH) {
            w0 = __expf(leaky(el[s0 * KH + lane] + erh) - mx);
            se += w0;
        }
        float wk0 = __shfl_sync(0xffffffffu, w0, hk);
        const float4* p0 = (const float4*)&Psrc[(size_t)s0 * KD + lane * 8];
        float4 a0 = p0[0], a1 = p0[1];
        acc[0] = fmaf(wk0, a0.x, acc[0]);
        acc[1] = fmaf(wk0, a0.y, acc[1]);
        acc[2] = fmaf(wk0, a0.z, acc[2]);
        acc[3] = fmaf(wk0, a0.w, acc[3]);
        acc[4] = fmaf(wk0, a1.x, acc[4]);
        acc[5] = fmaf(wk0, a1.y, acc[5]);
        acc[6] = fmaf(wk0, a1.z, acc[6]);
        acc[7] = fmaf(wk0, a1.w, acc[7]);
    }
    float inv = 1.f / __shfl_sync(0xffffffffu, se, hk);
    float4 o0, o1;
    o0.x = fmaxf(acc[0] * inv, 0.f);
    o0.y = fmaxf(acc[1] * inv, 0.f);
    o0.z = fmaxf(acc[2] * inv, 0.f);
    o0.w = fmaxf(acc[3] * inv, 0.f);
    o1.x = fmaxf(acc[4] * inv, 0.f);
    o1.y = fmaxf(acc[5] * inv, 0.f);
    o1.z = fmaxf(acc[6] * inv, 0.f);
    o1.w = fmaxf(acc[7] * inv, 0.f);
    *(float4*)dstp = o0;
    *(float4*)(dstp + 4) = o1;
}

// ---------------- final paper ----------------
__global__ void final_paper(const float* __restrict__ rfw, const float* __restrict__ rfc,
                            const float* __restrict__ nodep, const float* __restrict__ attnM,
                            const float* __restrict__ resw, float* __restrict__ out)
{
    int n = blockIdx.x;
    int k = threadIdx.x >> 5;
    int lane = threadIdx.x & 31;
    size_t idx = (size_t)n * KD + k * DH + lane;
    float np = nodep[idx], rw = rfw[idx], rc = rfc[idx];
    float a1 = attnM[k * 64 + lane];
    float a2 = attnM[k * 64 + 32 + lane];
    float sw = a1 * np + a2 * rw;
    float sc = a1 * np + a2 * rc;
#pragma unroll
    for (int s = 16; s > 0; s >>= 1) {
        sw += __shfl_xor_sync(0xffffffffu, sw, s);
        sc += __shfl_xor_sync(0xffffffffu, sc, s);
    }
    sw = leaky(sw);
    sc = leaky(sc);
    float mx = fmaxf(sw, sc);
    float ew = __expf(sw - mx), ec = __expf(sc - mx);
    float aw = ew / (ew + ec);
    float val = aw * rw + (1.f - aw) * rc;
    float g = 1.f / (1.f + __expf(-resw[0]));
    size_t o = (size_t)NA * KD + idx;
    out[o] = g * val + (1.f - g) * out[o];
}

// ---------------- launch ----------------
extern "C" void kernel_launch(void* const* d_in, const int* in_sizes, int n_in,
                              void* d_out, int out_size)
{
    const float* feats_author    = (const float*)d_in[0];
    const float* feats_paper     = (const float*)d_in[1];
    const float* W_micro_author  = (const float*)d_in[2];
    const float* W_micro_paper   = (const float*)d_in[3];
    const float* attn_micro_a    = (const float*)d_in[4];
    const float* attn_micro_p    = (const float*)d_in[5];
    const float* W_macro_node_p  = (const float*)d_in[7];
    const float* W_rel_writes    = (const float*)d_in[8];
    const float* W_rel_wb        = (const float*)d_in[9];
    const float* W_rel_cites     = (const float*)d_in[10];
    const float* attn_macro      = (const float*)d_in[11];
    const float* W_res_author    = (const float*)d_in[12];
    const float* b_res_author    = (const float*)d_in[13];
    const float* W_res_paper     = (const float*)d_in[14];
    const float* b_res_paper     = (const float*)d_in[15];
    const float* res_w_author    = (const float*)d_in[16];
    const float* res_w_paper     = (const float*)d_in[17];
    const int*   writes_src      = (const int*)d_in[18];
    const int*   writes_dst      = (const int*)d_in[19];
    const int*   wb_src          = (const int*)d_in[20];
    const int*   wb_dst          = (const int*)d_in[21];
    const int*   cites_src       = (const int*)d_in[22];
    const int*   cites_dst       = (const int*)d_in[23];
    float* out = (float*)d_out;

    float *PA, *PP, *elA_aA, *erP_aA, *elP_aP, *erA_aP, *erP_aP;
    float *ft_w, *ft_wb, *ft_c, *rf_w, *rf_c, *nodeP;
    int *counts, *cursor, *offsets, *partials, *ssort;
    cudaGetSymbolAddress((void**)&PA, g_PA);
    cudaGetSymbolAddress((void**)&PP, g_PP);
    cudaGetSymbolAddress((void**)&elA_aA, g_elA_aA);
    cudaGetSymbolAddress((void**)&erP_aA, g_erP_aA);
    cudaGetSymbolAddress((void**)&elP_aP, g_elP_aP);
    cudaGetSymbolAddress((void**)&erA_aP, g_erA_aP);
    cudaGetSymbolAddress((void**)&erP_aP, g_erP_aP);
    cudaGetSymbolAddress((void**)&ft_w, g_ft_w);
    cudaGetSymbolAddress((void**)&ft_wb, g_ft_wb);
    cudaGetSymbolAddress((void**)&ft_c, g_ft_c);
    cudaGetSymbolAddress((void**)&rf_w, g_rf_w);
    cudaGetSymbolAddress((void**)&rf_c, g_rf_c);
    cudaGetSymbolAddress((void**)&nodeP, g_nodeP);
    cudaGetSymbolAddress((void**)&counts, g_counts);
    cudaGetSymbolAddress((void**)&cursor, g_cursor);
    cudaGetSymbolAddress((void**)&offsets, g_offsets);
    cudaGetSymbolAddress((void**)&partials, g_partials);
    cudaGetSymbolAddress((void**)&ssort, g_ssort);

    static cudaStream_t s2 = nullptr;
    static cudaEvent_t evFork = nullptr, evA = nullptr, evG0 = nullptr,
                       evG2 = nullptr, evS2 = nullptr, evRes = nullptr;
    if (!s2) {
        cudaStreamCreateWithFlags(&s2, cudaStreamNonBlocking);
        cudaEventCreateWithFlags(&evFork, cudaEventDisableTiming);
        cudaEventCreateWithFlags(&evA, cudaEventDisableTiming);
        cudaEventCreateWithFlags(&evG0, cudaEventDisableTiming);
        cudaEventCreateWithFlags(&evG2, cudaEventDisableTiming);
        cudaEventCreateWithFlags(&evS2, cudaEventDisableTiming);
        cudaEventCreateWithFlags(&evRes, cudaEventDisableTiming);
    }

    const dim3 GG2(KD / BN, (NA + BM - 1) / BM);   // (2, 391)
    const int EB = (EDG + 255) / 256;
    const int GB = (NA * 32 + 255) / 256;

    GemmJob jz = {};

    struct Rel { const int* src; const int* dst; };
    Rel rels[3] = {
        { writes_src, writes_dst },
        { wb_src,     wb_dst     },
        { cites_src,  cites_dst  },
    };

    // ---- fork: s2 runs CSR builds for all 3 relations ----
    cudaEventRecord(evFork, 0);
    cudaStreamWaitEvent(s2, evFork, 0);
    for (int r = 0; r < 3; r++) {
        Rel& R = rels[r];
        int* cnt = counts  + r * 50000;
        int* cur = cursor  + r * 50000;
        int* off = offsets + r * 50001;
        int* par = partials + r * (NBLK + 1);
        int* srt = ssort   + r * EDG;
        cudaMemsetAsync(cnt, 0, 50000 * sizeof(int), s2);
        cudaMemsetAsync(cur, 0, 50000 * sizeof(int), s2);
        csr_hist<<<EB, 256, 0, s2>>>(R.dst, cnt);
        scan_block<<<NBLK, 256, 0, s2>>>(cnt, off, par, 50000);
        scan_top<<<1, 256, 0, s2>>>(par, NBLK);
        scan_add<<<NBLK, 256, 0, s2>>>(off, par, 50000);
        csr_scatter<<<EB, 256, 0, s2>>>(R.src, R.dst, off, cur, srt);
    }

    // ---- main: zero author attn-dot outputs, then author micro GEMM ----
    cudaMemsetAsync(elA_aA, 0, NA * KH * sizeof(float), 0);
    cudaMemsetAsync(erA_aP, 0, NA * KH * sizeof(float), 0);
    {
        GemmJob ja = { feats_author, W_micro_author, PA, nullptr, nullptr,
                       attn_micro_a + 0,  elA_aA,
                       attn_micro_p + 32, erA_aP,
                       nullptr, nullptr };
        gemm_multi<<<GG2, 256>>>(ja, jz, jz, 1, NA);
    }
    cudaEventRecord(evA, 0);

    // ---- s2: zero paper attn-dot outputs, paper micro GEMM (waits for CSR drain in-stream) ----
    cudaMemsetAsync(erP_aA, 0, NP * KH * sizeof(float), s2);
    cudaMemsetAsync(elP_aP, 0, NP * KH * sizeof(float), s2);
    cudaMemsetAsync(erP_aP, 0, NP * KH * sizeof(float), s2);
    {
        GemmJob ja = { feats_paper, W_micro_paper, PP, nullptr, nullptr,
                       attn_micro_a + 32, erP_aA,
                       attn_micro_p + 0,  elP_aP,
                       attn_micro_p + 32, erP_aP };
        gemm_multi<<<GG2, 256, 0, s2>>>(ja, jz, jz, 1, NP);
    }

    // ---- s2: gather cites (paper-only deps) ----
    micro_gather<<<GB, 256, 0, s2>>>(ssort + 2 * EDG, offsets + 2 * 50001,
                                     elP_aP, erP_aP, PP, ft_c, NP);
    cudaEventRecord(evG2, s2);

    // ---- s2: remaining gathers need author micro ----
    cudaStreamWaitEvent(s2, evA, 0);
    micro_gather<<<GB, 256, 0, s2>>>(ssort + 0 * EDG, offsets + 0 * 50001,
                                     elA_aA, erP_aA, PA, ft_w, NP);
    cudaEventRecord(evG0, s2);
    micro_gather<<<GB, 256, 0, s2>>>(ssort + 1 * EDG, offsets + 1 * 50001,
                                     elP_aP, erA_aP, PP, ft_wb, NA);

    // ---- main: 3-job GEMM (res_author, nodeP, res_paper) overlapping gathers ----
    {
        GemmJob ja = { feats_author, W_res_author, out, b_res_author, nullptr,
                       nullptr, nullptr, nullptr, nullptr, nullptr, nullptr };
        GemmJob jb = { feats_paper, W_macro_node_p, nodeP, nullptr, nullptr,
                       nullptr, nullptr, nullptr, nullptr, nullptr, nullptr };
        GemmJob jc = { feats_paper, W_res_paper, out + (size_t)NA * KD, b_res_paper, nullptr,
                       nullptr, nullptr, nullptr, nullptr, nullptr, nullptr };
        gemm_multi<<<GG2, 256>>>(ja, jb, jc, 3, NA);
    }
    cudaEventRecord(evRes, 0);

    // ---- s2: wb gated GEMM (needs ft_wb in-stream + out[:NA] residual from main) ----
    cudaStreamWaitEvent(s2, evRes, 0);
    {
        GemmJob ja = { ft_wb, W_rel_wb, out, nullptr, res_w_author,
                       nullptr, nullptr, nullptr, nullptr, nullptr, nullptr };
        gemm_multi<<<GG2, 256, 0, s2>>>(ja, jz, jz, 1, NA);
    }
    cudaEventRecord(evS2, s2);

    // ---- main: rf_w + rf_c in one 2-job launch, concurrent with s2's wb GEMM ----
    cudaStreamWaitEvent(0, evG0, 0);
    cudaStreamWaitEvent(0, evG2, 0);
    {
        GemmJob ja = { ft_w, W_rel_writes, rf_w, nullptr, nullptr,
                       nullptr, nullptr, nullptr, nullptr, nullptr, nullptr };
        GemmJob jb = { ft_c, W_rel_cites, rf_c, nullptr, nullptr,
                       nullptr, nullptr, nullptr, nullptr, nullptr, nullptr };
        gemm_multi<<<GG2, 256>>>(ja, jb, jz, 2, NP);
    }

    // ---- join s2, then final paper fusion ----
    cudaStreamWaitEvent(0, evS2, 0);
    final_paper<<<NP, 256>>>(rf_w, rf_c, nodeP, attn_macro, res_w_paper, out);
}

// round 11
// speedup vs baseline: 1.1191x; 1.1191x over previous
#include <cuda_runtime.h>
#include <cstdint>
#include <math.h>

// ---------------- problem constants ----------------
#define NA 50000
#define NP 50000
#define EDG 400000
#define KH 8
#define DH 32
#define KD 256
#define SLOPE 0.2f

// GEMM tiling: block 128(M) x 256(N), 8 warps (2m x 4n), warp tile 64x64, BK=16 (tf32)
#define BM 128
#define BK 16
#define NKT (KD / BK)      // 16
#define LDK 20
#define LDBN 264
#define ASZ (128 * LDK)
#define BSZ (BK * LDBN)
#define SMEM_BYTES ((2 * ASZ + 2 * BSZ) * 4)     // 54272
#define RFLD 260
#define FUSE_SMEM (SMEM_BYTES + 128 * RFLD * 4)  // 54272 + 133120 = 187392

#define NBLK 196           // ceil(50000/256)

// ---------------- device scratch ----------------
__device__ float g_PA[NA * KD];
__device__ float g_PP[NP * KD];

__device__ float g_elA_aA[NA * KH];
__device__ float g_erP_aA[NP * KH];
__device__ float g_elP_aP[NP * KH];
__device__ float g_erA_aP[NA * KH];
__device__ float g_erP_aP[NP * KH];

__device__ float g_ft_w[NP * KD];
__device__ float g_ft_wb[NA * KD];
__device__ float g_ft_c[NP * KD];

__device__ float g_nodeP[NP * KD];

// CSR scratch, one set per relation
__device__ int g_counts[3][50000];
__device__ int g_cursor[3][50000];
__device__ int g_offsets[3][50001];
__device__ int g_partials[3][NBLK + 1];
__device__ int g_ssort[3][EDG];

// ---------------- helpers ----------------
__device__ __forceinline__ float leaky(float v) {
    return v > 0.f ? v : SLOPE * v;
}
__device__ __forceinline__ uint32_t f2tf32(float f) {
    uint32_t r;
    asm("cvt.rna.tf32.f32 %0, %1;" : "=r"(r) : "f"(f));
    return r;
}
__device__ __forceinline__ void mma_tf32(float c[4], uint32_t a0, uint32_t a1,
                                         uint32_t a2, uint32_t a3,
                                         uint32_t b0, uint32_t b1) {
    asm volatile(
        "mma.sync.aligned.m16n8k8.row.col.f32.tf32.tf32.f32 "
        "{%0,%1,%2,%3}, {%4,%5,%6,%7}, {%8,%9}, {%0,%1,%2,%3};"
        : "+f"(c[0]), "+f"(c[1]), "+f"(c[2]), "+f"(c[3])
        : "r"(a0), "r"(a1), "r"(a2), "r"(a3), "r"(b0), "r"(b1));
}

struct GemmJob {
    const float* A;
    const float* B;
    float*       C;
    const float* bias;
    const float* gate;
    const float* av0; float* ao0;
    const float* av1; float* ao1;
    const float* av2; float* ao2;
};

// ================= R9-proven multi-job tf32 GEMM (128x256 block) =================
__global__ void __launch_bounds__(256, 1) gemm_multi(
    GemmJob j0, GemmJob j1, GemmJob j2, int nb, int M)
{
    extern __shared__ uint32_t smem[];
    const int tid = threadIdx.x;
    const int lane = tid & 31;
    const int wid = tid >> 5;
    const int wm = (wid & 1) * 64;
    const int wn = (wid >> 1) * 64;
    const int m0 = blockIdx.x * BM;

    const int qr = lane >> 2;
    const int qc = lane & 3;

    const int am = tid >> 1;
    const int aq = (tid & 1) * 8;
    const int bkr = tid >> 4;
    const int bnc = (tid & 15) * 16;

    float4 rA[2], rB[4];

    auto g_load = [&](int kt, const float* __restrict__ A, const float* __restrict__ B) {
        const int k0 = kt * BK;
        int row = m0 + am;
        if (row < M) {
            rA[0] = *(const float4*)&A[(size_t)row * KD + k0 + aq];
            rA[1] = *(const float4*)&A[(size_t)row * KD + k0 + aq + 4];
        } else {
            rA[0] = make_float4(0.f, 0.f, 0.f, 0.f);
            rA[1] = rA[0];
        }
        const float* bp = &B[(size_t)(k0 + bkr) * KD + bnc];
        rB[0] = *(const float4*)&bp[0];
        rB[1] = *(const float4*)&bp[4];
        rB[2] = *(const float4*)&bp[8];
        rB[3] = *(const float4*)&bp[12];
    };
    auto s_store = [&](int buf) {
        uint32_t* as = &smem[buf * ASZ + am * LDK + aq];
        uint4 v0, v1;
        v0.x = f2tf32(rA[0].x); v0.y = f2tf32(rA[0].y);
        v0.z = f2tf32(rA[0].z); v0.w = f2tf32(rA[0].w);
        v1.x = f2tf32(rA[1].x); v1.y = f2tf32(rA[1].y);
        v1.z = f2tf32(rA[1].z); v1.w = f2tf32(rA[1].w);
        *(uint4*)&as[0] = v0;
        *(uint4*)&as[4] = v1;
        uint32_t* bs = &smem[2 * ASZ + buf * BSZ + bkr * LDBN + bnc];
#pragma unroll
        for (int q = 0; q < 4; q++) {
            uint4 w;
            w.x = f2tf32(((const float*)&rB[q])[0]);
            w.y = f2tf32(((const float*)&rB[q])[1]);
            w.z = f2tf32(((const float*)&rB[q])[2]);
            w.w = f2tf32(((const float*)&rB[q])[3]);
            *(uint4*)&bs[q * 4] = w;
        }
    };

#pragma unroll
    for (int o = 0; o < 3; o++) {
        if (o >= nb) break;
        const GemmJob J = (o == 0) ? j0 : (o == 1) ? j1 : j2;

        float acc[4][8][4];
#pragma unroll
        for (int mi = 0; mi < 4; mi++)
#pragma unroll
            for (int ni = 0; ni < 8; ni++)
#pragma unroll
                for (int r = 0; r < 4; r++) acc[mi][ni][r] = 0.f;

        g_load(0, J.A, J.B);
        s_store(0);
        __syncthreads();

        for (int kt = 0; kt < NKT; kt++) {
            const int cur = kt & 1;
            if (kt + 1 < NKT) g_load(kt + 1, J.A, J.B);

            const uint32_t* asb = &smem[cur * ASZ];
            const uint32_t* bsb = &smem[2 * ASZ + cur * BSZ];
#pragma unroll
            for (int ks = 0; ks < BK; ks += 8) {
                uint32_t a[4][4], b[8][2];
#pragma unroll
                for (int mi = 0; mi < 4; mi++) {
                    int r0 = wm + mi * 16 + qr;
                    a[mi][0] = asb[r0 * LDK + ks + qc];
                    a[mi][1] = asb[(r0 + 8) * LDK + ks + qc];
                    a[mi][2] = asb[r0 * LDK + ks + qc + 4];
                    a[mi][3] = asb[(r0 + 8) * LDK + ks + qc + 4];
                }
#pragma unroll
                for (int ni = 0; ni < 8; ni++) {
                    int c0 = wn + ni * 8 + qr;
                    b[ni][0] = bsb[(ks + qc) * LDBN + c0];
                    b[ni][1] = bsb[(ks + qc + 4) * LDBN + c0];
                }
#pragma unroll
                for (int mi = 0; mi < 4; mi++)
#pragma unroll
                    for (int ni = 0; ni < 8; ni++)
                        mma_tf32(acc[mi][ni], a[mi][0], a[mi][1], a[mi][2], a[mi][3],
                                 b[ni][0], b[ni][1]);
            }

            if (kt + 1 < NKT) {
                s_store(1 - cur);
                __syncthreads();
            }
        }

        if (J.av0) {
            const float* avs[3] = { J.av0, J.av1, J.av2 };
            float*       aos[3] = { J.ao0, J.ao1, J.ao2 };
            const int h0 = wn >> 5;
#pragma unroll
            for (int t = 0; t < 3; t++) {
                const float* av = avs[t];
                if (!av) break;
                float* ao = aos[t];
                float c0[8], c1[8];
#pragma unroll
                for (int ni = 0; ni < 8; ni++) {
                    int col = wn + ni * 8 + qc * 2;
                    int idx = (col >> 5) * 64 + (col & 31);
                    c0[ni] = av[idx];
                    c1[ni] = av[idx + 1];
                }
#pragma unroll
                for (int mi = 0; mi < 4; mi++) {
#pragma unroll
                    for (int half = 0; half < 2; half++) {
                        float pa = 0.f, pb = 0.f;
#pragma unroll
                        for (int ni = 0; ni < 4; ni++)
                            pa += acc[mi][ni][half * 2] * c0[ni]
                                + acc[mi][ni][half * 2 + 1] * c1[ni];
#pragma unroll
                        for (int ni = 4; ni < 8; ni++)
                            pb += acc[mi][ni][half * 2] * c0[ni]
                                + acc[mi][ni][half * 2 + 1] * c1[ni];
                        pa += __shfl_xor_sync(0xffffffffu, pa, 1);
                        pa += __shfl_xor_sync(0xffffffffu, pa, 2);
                        pb += __shfl_xor_sync(0xffffffffu, pb, 1);
                        pb += __shfl_xor_sync(0xffffffffu, pb, 2);
                        int row = m0 + wm + mi * 16 + qr + half * 8;
                        if (qc == 0 && row < M) {
                            ao[row * KH + h0]     = pa;
                            ao[row * KH + h0 + 1] = pb;
                        }
                    }
                }
            }
        }

        float g = 0.f;
        if (J.gate) g = 1.f / (1.f + __expf(-J.gate[0]));

#pragma unroll
        for (int mi = 0; mi < 4; mi++) {
#pragma unroll
            for (int half = 0; half < 2; half++) {
                int row = m0 + wm + mi * 16 + qr + half * 8;
                if (row >= M) continue;
                float* dst = &J.C[(size_t)row * KD + wn];
#pragma unroll
                for (int ni = 0; ni < 8; ni++) {
                    int col = ni * 8 + qc * 2;
                    float2 v;
                    v.x = acc[mi][ni][half * 2 + 0];
                    v.y = acc[mi][ni][half * 2 + 1];
                    if (J.bias) {
                        v.x += J.bias[wn + col + 0];
                        v.y += J.bias[wn + col + 1];
                    }
                    if (J.gate) {
                        float2 prev = *(const float2*)&dst[col];
                        v.x = g * v.x + (1.f - g) * prev.x;
                        v.y = g * v.y + (1.f - g) * prev.y;
                    }
                    *(float2*)&dst[col] = v;
                }
            }
        }
        __syncthreads();
    }
}

// ================= fused rf_w + rf_c GEMM + semantic attention + gated residual =================
// job0: rfw = ft_w @ W_writes -> smem buffer (same thread writes/reads its own frags)
// job1: rfc = ft_c @ W_cites -> registers; epilogue fuses final_paper into out[NA:].
__global__ void __launch_bounds__(256, 1) gemm_rf_fused(
    const float* __restrict__ Aw, const float* __restrict__ Bw,
    const float* __restrict__ Ac, const float* __restrict__ Bc,
    const float* __restrict__ nodep, const float* __restrict__ attnM,
    const float* __restrict__ resw, float* __restrict__ outP, int M)
{
    extern __shared__ uint32_t smem[];
    float* rfbuf = (float*)(smem + 2 * ASZ + 2 * BSZ);   // [128][RFLD]

    const int tid = threadIdx.x;
    const int lane = tid & 31;
    const int wid = tid >> 5;
    const int wm = (wid & 1) * 64;
    const int wn = (wid >> 1) * 64;
    const int m0 = blockIdx.x * BM;

    const int qr = lane >> 2;
    const int qc = lane & 3;

    const int am = tid >> 1;
    const int aq = (tid & 1) * 8;
    const int bkr = tid >> 4;
    const int bnc = (tid & 15) * 16;

    float4 rA[2], rB[4];

    auto g_load = [&](int kt, const float* __restrict__ A, const float* __restrict__ B) {
        const int k0 = kt * BK;
        int row = m0 + am;
        if (row < M) {
            rA[0] = *(const float4*)&A[(size_t)row * KD + k0 + aq];
            rA[1] = *(const float4*)&A[(size_t)row * KD + k0 + aq + 4];
        } else {
            rA[0] = make_float4(0.f, 0.f, 0.f, 0.f);
            rA[1] = rA[0];
        }
        const float* bp = &B[(size_t)(k0 + bkr) * KD + bnc];
        rB[0] = *(const float4*)&bp[0];
        rB[1] = *(const float4*)&bp[4];
        rB[2] = *(const float4*)&bp[8];
        rB[3] = *(const float4*)&bp[12];
    };
    auto s_store = [&](int buf) {
        uint32_t* as = &smem[buf * ASZ + am * LDK + aq];
        uint4 v0, v1;
        v0.x = f2tf32(rA[0].x); v0.y = f2tf32(rA[0].y);
        v0.z = f2tf32(rA[0].z); v0.w = f2tf32(rA[0].w);
        v1.x = f2tf32(rA[1].x); v1.y = f2tf32(rA[1].y);
        v1.z = f2tf32(rA[1].z); v1.w = f2tf32(rA[1].w);
        *(uint4*)&as[0] = v0;
        *(uint4*)&as[4] = v1;
        uint32_t* bs = &smem[2 * ASZ + buf * BSZ + bkr * LDBN + bnc];
#pragma unroll
        for (int q = 0; q < 4; q++) {
            uint4 w;
            w.x = f2tf32(((const float*)&rB[q])[0]);
            w.y = f2tf32(((const float*)&rB[q])[1]);
            w.z = f2tf32(((const float*)&rB[q])[2]);
            w.w = f2tf32(((const float*)&rB[q])[3]);
            *(uint4*)&bs[q * 4] = w;
        }
    };

#pragma unroll
    for (int o = 0; o < 2; o++) {
        const float* A = (o == 0) ? Aw : Ac;
        const float* B = (o == 0) ? Bw : Bc;

        float acc[4][8][4];
#pragma unroll
        for (int mi = 0; mi < 4; mi++)
#pragma unroll
            for (int ni = 0; ni < 8; ni++)
#pragma unroll
                for (int r = 0; r < 4; r++) acc[mi][ni][r] = 0.f;

        g_load(0, A, B);
        s_store(0);
        __syncthreads();

        for (int kt = 0; kt < NKT; kt++) {
            const int cur = kt & 1;
            if (kt + 1 < NKT) g_load(kt + 1, A, B);

            const uint32_t* asb = &smem[cur * ASZ];
            const uint32_t* bsb = &smem[2 * ASZ + cur * BSZ];
#pragma unroll
            for (int ks = 0; ks < BK; ks += 8) {
                uint32_t a[4][4], b[8][2];
#pragma unroll
                for (int mi = 0; mi < 4; mi++) {
                    int r0 = wm + mi * 16 + qr;
                    a[mi][0] = asb[r0 * LDK + ks + qc];
                    a[mi][1] = asb[(r0 + 8) * LDK + ks + qc];
                    a[mi][2] = asb[r0 * LDK + ks + qc + 4];
                    a[mi][3] = asb[(r0 + 8) * LDK + ks + qc + 4];
                }
#pragma unroll
                for (int ni = 0; ni < 8; ni++) {
                    int c0 = wn + ni * 8 + qr;
                    b[ni][0] = bsb[(ks + qc) * LDBN + c0];
                    b[ni][1] = bsb[(ks + qc + 4) * LDBN + c0];
                }
#pragma unroll
                for (int mi = 0; mi < 4; mi++)
#pragma unroll
                    for (int ni = 0; ni < 8; ni++)
                        mma_tf32(acc[mi][ni], a[mi][0], a[mi][1], a[mi][2], a[mi][3],
                                 b[ni][0], b[ni][1]);
            }

            if (kt + 1 < NKT) {
                s_store(1 - cur);
                __syncthreads();
            }
        }

        if (o == 0) {
            // stash rf_w tile in smem (thread-private positions)
#pragma unroll
            for (int mi = 0; mi < 4; mi++)
#pragma unroll
                for (int half = 0; half < 2; half++) {
                    int lr = wm + mi * 16 + qr + half * 8;
                    float* dst = &rfbuf[lr * RFLD + wn];
#pragma unroll
                    for (int ni = 0; ni < 8; ni++) {
                        int col = ni * 8 + qc * 2;
                        dst[col]     = acc[mi][ni][half * 2 + 0];
                        dst[col + 1] = acc[mi][ni][half * 2 + 1];
                    }
                }
            __syncthreads();   // A/B buffers reused next job (rfbuf untouched by fills)
            continue;
        }

        // ---- fusion epilogue: semantic attention over {rfw (smem), rfc (acc)} ----
        const float g = 1.f / (1.f + __expf(-resw[0]));
        float cn0[8], cn1[8], cr0[8], cr1[8];
#pragma unroll
        for (int ni = 0; ni < 8; ni++) {
            int col = wn + ni * 8 + qc * 2;
            int base = (col >> 5) * 64 + (col & 31);
            cn0[ni] = attnM[base];
            cn1[ni] = attnM[base + 1];
            cr0[ni] = attnM[base + 32];
            cr1[ni] = attnM[base + 33];
        }

#pragma unroll
        for (int mi = 0; mi < 4; mi++) {
#pragma unroll
            for (int half = 0; half < 2; half++) {
                int lr = wm + mi * 16 + qr + half * 8;
                int row = m0 + lr;
                if (row >= M) continue;
                const float* nprow = &nodep[(size_t)row * KD + wn];
                const float* rwrow = &rfbuf[lr * RFLD + wn];
                float* orow = &outP[(size_t)row * KD + wn];

                // pass 1: per-head scores
                float swa = 0.f, sca = 0.f, swb = 0.f, scb = 0.f;
#pragma unroll
                for (int ni = 0; ni < 8; ni++) {
                    int col = ni * 8 + qc * 2;
                    float2 np = *(const float2*)&nprow[col];
                    float rw0 = rwrow[col], rw1 = rwrow[col + 1];
                    float rc0 = acc[mi][ni][half * 2], rc1 = acc[mi][ni][half * 2 + 1];
                    float npart = np.x * cn0[ni] + np.y * cn1[ni];
                    float wpart = npart + rw0 * cr0[ni] + rw1 * cr1[ni];
                    float cpart = npart + rc0 * cr0[ni] + rc1 * cr1[ni];
                    if (ni < 4) { swa += wpart; sca += cpart; }
                    else        { swb += wpart; scb += cpart; }
                }
                swa += __shfl_xor_sync(0xffffffffu, swa, 1);
                swa += __shfl_xor_sync(0xffffffffu, swa, 2);
                sca += __shfl_xor_sync(0xffffffffu, sca, 1);
                sca += __shfl_xor_sync(0xffffffffu, sca, 2);
                swb += __shfl_xor_sync(0xffffffffu, swb, 1);
                swb += __shfl_xor_sync(0xffffffffu, swb, 2);
                scb += __shfl_xor_sync(0xffffffffu, scb, 1);
                scb += __shfl_xor_sync(0xffffffffu, scb, 2);

                swa = leaky(swa); sca = leaky(sca);
                swb = leaky(swb); scb = leaky(scb);
                float ma = fmaxf(swa, sca);
                float ea = __expf(swa - ma), eca = __expf(sca - ma);
                float awa = ea / (ea + eca);
                float mb = fmaxf(swb, scb);
                float eb = __expf(swb - mb), ecb = __expf(scb - mb);
                float awb = eb / (eb + ecb);

                // pass 2: blend + gated residual, write out
#pragma unroll
                for (int ni = 0; ni < 8; ni++) {
                    int col = ni * 8 + qc * 2;
                    float aw = (ni < 4) ? awa : awb;
                    float rw0 = rwrow[col], rw1 = rwrow[col + 1];
                    float rc0 = acc[mi][ni][half * 2], rc1 = acc[mi][ni][half * 2 + 1];
                    float2 prev = *(const float2*)&orow[col];
                    float2 v;
                    v.x = g * (aw * rw0 + (1.f - aw) * rc0) + (1.f - g) * prev.x;
                    v.y = g * (aw * rw1 + (1.f - aw) * rc1) + (1.f - g) * prev.y;
                    *(float2*)&orow[col] = v;
                }
            }
        }
    }
}

// trailing join node (cross-stream dependency terminator)
__global__ void join_k() {}

// ---------------- CSR build ----------------
__global__ void csr_hist(const int* __restrict__ dst, int* __restrict__ counts)
{
    int e = blockIdx.x * blockDim.x + threadIdx.x;
    if (e < EDG) atomicAdd(&counts[dst[e]], 1);
}

__global__ void scan_block(const int* __restrict__ in, int* __restrict__ out,
                           int* __restrict__ partials, int n)
{
    __shared__ int wsum[8];
    int i = blockIdx.x * 256 + threadIdx.x;
    int lane = threadIdx.x & 31, wid = threadIdx.x >> 5;
    int v = (i < n) ? in[i] : 0;
    int x = v;
#pragma unroll
    for (int o = 1; o < 32; o <<= 1) {
        int t = __shfl_up_sync(0xffffffffu, x, o);
        if (lane >= o) x += t;
    }
    if (lane == 31) wsum[wid] = x;
    __syncthreads();
    if (wid == 0) {
        int w = (lane < 8) ? wsum[lane] : 0;
#pragma unroll
        for (int o = 1; o < 8; o <<= 1) {
            int t = __shfl_up_sync(0xffffffffu, w, o);
            if (lane >= o) w += t;
        }
        if (lane < 8) wsum[lane] = w;
    }
    __syncthreads();
    int wpre = (wid > 0) ? wsum[wid - 1] : 0;
    if (i < n) out[i] = wpre + x - v;
    if (threadIdx.x == 0) partials[blockIdx.x] = wsum[7];
}

__global__ void scan_top(int* __restrict__ partials, int nb)
{
    __shared__ int wsum[8];
    int i = threadIdx.x;
    int lane = i & 31, wid = i >> 5;
    int v = (i < nb) ? partials[i] : 0;
    int x = v;
#pragma unroll
    for (int o = 1; o < 32; o <<= 1) {
        int t = __shfl_up_sync(0xffffffffu, x, o);
        if (lane >= o) x += t;
    }
    if (lane == 31) wsum[wid] = x;
    __syncthreads();
    if (wid == 0) {
        int w = (lane < 8) ? wsum[lane] : 0;
#pragma unroll
        for (int o = 1; o < 8; o <<= 1) {
            int t = __shfl_up_sync(0xffffffffu, w, o);
            if (lane >= o) w += t;
        }
        if (lane < 8) wsum[lane] = w;
    }
    __syncthreads();
    int wpre = (wid > 0) ? wsum[wid - 1] : 0;
    if (i < nb) partials[i] = wpre + x - v;
    if (i == 0) partials[nb] = wsum[7];
}

__global__ void scan_add(int* __restrict__ offsets, const int* __restrict__ partials, int n)
{
    int i = blockIdx.x * 256 + threadIdx.x;
    if (i < n) offsets[i] += partials[blockIdx.x];
    if (i == 0) offsets[n] = partials[gridDim.x];
}

__global__ void csr_scatter(const int* __restrict__ src, const int* __restrict__ dst,
                            const int* __restrict__ offsets, int* __restrict__ cursor,
                            int* __restrict__ ssort)
{
    int e = blockIdx.x * blockDim.x + threadIdx.x;
    if (e >= EDG) return;
    int d = dst[e];
    int pos = offsets[d] + atomicAdd(&cursor[d], 1);
    ssort[pos] = src[e];
}

// ---------------- fused micro gather ----------------
__global__ void micro_gather(const int* __restrict__ ssort, const int* __restrict__ offsets,
                             const float* __restrict__ el, const float* __restrict__ er,
                             const float* __restrict__ Psrc, float* __restrict__ ft, int n_dst)
{
    int d = (blockIdx.x * blockDim.x + threadIdx.x) >> 5;
    int lane = threadIdx.x & 31;
    if (d >= n_dst) return;
    int beg = offsets[d], end = offsets[d + 1];
    float* dstp = &ft[(size_t)d * KD + lane * 8];
    if (beg == end) {
        float4 z = make_float4(0.f, 0.f, 0.f, 0.f);
        *(float4*)dstp = z;
        *(float4*)(dstp + 4) = z;
        return;
    }
    const int h8 = lane & 7;
    float erh = er[d * KH + h8];

    float mx = -1e30f;
    {
        int sub = lane >> 3;
        for (int i = beg; i < end; i += 4) {
            int e = i + sub;
            if (e < end) {
                int s = ssort[e];
                mx = fmaxf(mx, leaky(el[s * KH + h8] + erh));
            }
        }
        mx = fmaxf(mx, __shfl_xor_sync(0xffffffffu, mx, 8));
        mx = fmaxf(mx, __shfl_xor_sync(0xffffffffu, mx, 16));
    }

    const int hk = lane >> 2;
    float acc[8] = {0.f, 0.f, 0.f, 0.f, 0.f, 0.f, 0.f, 0.f};
    float se = 0.f;
    int i = beg;
    for (; i + 2 <= end; i += 2) {
        int s0 = ssort[i], s1 = ssort[i + 1];
        float w0 = 0.f, w1 = 0.f;
        if (lane < KH) {
            w0 = __expf(leaky(el[s0 * KH + lane] + erh) - mx);
            w1 = __expf(leaky(el[s1 * KH + lane] + erh) - mx);
            se += w0 + w1;
        }
        float wk0 = __shfl_sync(0xffffffffu, w0, hk);
        float wk1 = __shfl_sync(0xffffffffu, w1, hk);
        const float4* p0 = (const float4*)&Psrc[(size_t)s0 * KD + lane * 8];
        const float4* p1 = (const float4*)&Psrc[(size_t)s1 * KD + lane * 8];
        float4 a0 = p0[0], a1 = p0[1], b0 = p1[0], b1 = p1[1];
        acc[0] = fmaf(wk0, a0.x, acc[0]); acc[0] = fmaf(wk1, b0.x, acc[0]);
        acc[1] = fmaf(wk0, a0.y, acc[1]); acc[1] = fmaf(wk1, b0.y, acc[1]);
        acc[2] = fmaf(wk0, a0.z, acc[2]); acc[2] = fmaf(wk1, b0.z, acc[2]);
        acc[3] = fmaf(wk0, a0.w, acc[3]); acc[3] = fmaf(wk1, b0.w, acc[3]);
        acc[4] = fmaf(wk0, a1.x, acc[4]); acc[4] = fmaf(wk1, b1.x, acc[4]);
        acc[5] = fmaf(wk0, a1.y, acc[5]); acc[5] = fmaf(wk1, b1.y, acc[5]);
        acc[6] = fmaf(wk0, a1.z, acc[6]); acc[6] = fmaf(wk1, b1.z, acc[6]);
        acc[7] = fmaf(wk0, a1.w, acc[7]); acc[7] = fmaf(wk1, b1.w, acc[7]);
    }
    if (i < end) {
        int s0 = ssort[i];
        float w0 = 0.f;
        if (lane < KH) {
            w0 = __expf(leaky(el[s0 * KH + lane] + erh) - mx);
            se += w0;
        }
        float wk0 = __shfl_sync(0xffffffffu, w0, hk);
        const float4* p0 = (const float4*)&Psrc[(size_t)s0 * KD + lane * 8];
        float4 a0 = p0[0], a1 = p0[1];
        acc[0] = fmaf(wk0, a0.x, acc[0]);
        acc[1] = fmaf(wk0, a0.y, acc[1]);
        acc[2] = fmaf(wk0, a0.z, acc[2]);
        acc[3] = fmaf(wk0, a0.w, acc[3]);
        acc[4] = fmaf(wk0, a1.x, acc[4]);
        acc[5] = fmaf(wk0, a1.y, acc[5]);
        acc[6] = fmaf(wk0, a1.z, acc[6]);
        acc[7] = fmaf(wk0, a1.w, acc[7]);
    }
    float inv = 1.f / __shfl_sync(0xffffffffu, se, hk);
    float4 o0, o1;
    o0.x = fmaxf(acc[0] * inv, 0.f);
    o0.y = fmaxf(acc[1] * inv, 0.f);
    o0.z = fmaxf(acc[2] * inv, 0.f);
    o0.w = fmaxf(acc[3] * inv, 0.f);
    o1.x = fmaxf(acc[4] * inv, 0.f);
    o1.y = fmaxf(acc[5] * inv, 0.f);
    o1.z = fmaxf(acc[6] * inv, 0.f);
    o1.w = fmaxf(acc[7] * inv, 0.f);
    *(float4*)dstp = o0;
    *(float4*)(dstp + 4) = o1;
}

// ---------------- launch ----------------
extern "C" void kernel_launch(void* const* d_in, const int* in_sizes, int n_in,
                              void* d_out, int out_size)
{
    const float* feats_author    = (const float*)d_in[0];
    const float* feats_paper     = (const float*)d_in[1];
    const float* W_micro_author  = (const float*)d_in[2];
    const float* W_micro_paper   = (const float*)d_in[3];
    const float* attn_micro_a    = (const float*)d_in[4];
    const float* attn_micro_p    = (const float*)d_in[5];
    const float* W_macro_node_p  = (const float*)d_in[7];
    const float* W_rel_writes    = (const float*)d_in[8];
    const float* W_rel_wb        = (const float*)d_in[9];
    const float* W_rel_cites     = (const float*)d_in[10];
    const float* attn_macro      = (const float*)d_in[11];
    const float* W_res_author    = (const float*)d_in[12];
    const float* b_res_author    = (const float*)d_in[13];
    const float* W_res_paper     = (const float*)d_in[14];
    const float* b_res_paper     = (const float*)d_in[15];
    const float* res_w_author    = (const float*)d_in[16];
    const float* res_w_paper     = (const float*)d_in[17];
    const int*   writes_src      = (const int*)d_in[18];
    const int*   writes_dst      = (const int*)d_in[19];
    const int*   wb_src          = (const int*)d_in[20];
    const int*   wb_dst          = (const int*)d_in[21];
    const int*   cites_src       = (const int*)d_in[22];
    const int*   cites_dst       = (const int*)d_in[23];
    float* out = (float*)d_out;

    float *PA, *PP, *elA_aA, *erP_aA, *elP_aP, *erA_aP, *erP_aP;
    float *ft_w, *ft_wb, *ft_c, *nodeP;
    int *counts, *cursor, *offsets, *partials, *ssort;
    cudaGetSymbolAddress((void**)&PA, g_PA);
    cudaGetSymbolAddress((void**)&PP, g_PP);
    cudaGetSymbolAddress((void**)&elA_aA, g_elA_aA);
    cudaGetSymbolAddress((void**)&erP_aA, g_erP_aA);
    cudaGetSymbolAddress((void**)&elP_aP, g_elP_aP);
    cudaGetSymbolAddress((void**)&erA_aP, g_erA_aP);
    cudaGetSymbolAddress((void**)&erP_aP, g_erP_aP);
    cudaGetSymbolAddress((void**)&ft_w, g_ft_w);
    cudaGetSymbolAddress((void**)&ft_wb, g_ft_wb);
    cudaGetSymbolAddress((void**)&ft_c, g_ft_c);
    cudaGetSymbolAddress((void**)&nodeP, g_nodeP);
    cudaGetSymbolAddress((void**)&counts, g_counts);
    cudaGetSymbolAddress((void**)&cursor, g_cursor);
    cudaGetSymbolAddress((void**)&offsets, g_offsets);
    cudaGetSymbolAddress((void**)&partials, g_partials);
    cudaGetSymbolAddress((void**)&ssort, g_ssort);

    static cudaStream_t s2 = nullptr;
    static cudaEvent_t evFork = nullptr, evA = nullptr, evG0 = nullptr,
                       evG2 = nullptr, evS2 = nullptr, evRes = nullptr;
    if (!s2) {
        cudaStreamCreateWithFlags(&s2, cudaStreamNonBlocking);
        cudaEventCreateWithFlags(&evFork, cudaEventDisableTiming);
        cudaEventCreateWithFlags(&evA, cudaEventDisableTiming);
        cudaEventCreateWithFlags(&evG0, cudaEventDisableTiming);
        cudaEventCreateWithFlags(&evG2, cudaEventDisableTiming);
        cudaEventCreateWithFlags(&evS2, cudaEventDisableTiming);
        cudaEventCreateWithFlags(&evRes, cudaEventDisableTiming);
    }

    cudaFuncSetAttribute(gemm_multi, cudaFuncAttributeMaxDynamicSharedMemorySize, SMEM_BYTES);
    cudaFuncSetAttribute(gemm_rf_fused, cudaFuncAttributeMaxDynamicSharedMemorySize, FUSE_SMEM);

    const int GG = (NA + BM - 1) / BM;          // 391
    const int EB = (EDG + 255) / 256;
    const int GB = (NA * 32 + 255) / 256;

    GemmJob jz = {};

    struct Rel { const int* src; const int* dst; };
    Rel rels[3] = {
        { writes_src, writes_dst },
        { wb_src,     wb_dst     },
        { cites_src,  cites_dst  },
    };

    // ---- fork: s2 runs CSR builds for all 3 relations ----
    cudaEventRecord(evFork, 0);
    cudaStreamWaitEvent(s2, evFork, 0);
    for (int r = 0; r < 3; r++) {
        Rel& R = rels[r];
        int* cnt = counts  + r * 50000;
        int* cur = cursor  + r * 50000;
        int* off = offsets + r * 50001;
        int* par = partials + r * (NBLK + 1);
        int* srt = ssort   + r * EDG;
        cudaMemsetAsync(cnt, 0, 50000 * sizeof(int), s2);
        cudaMemsetAsync(cur, 0, 50000 * sizeof(int), s2);
        csr_hist<<<EB, 256, 0, s2>>>(R.dst, cnt);
        scan_block<<<NBLK, 256, 0, s2>>>(cnt, off, par, 50000);
        scan_top<<<1, 256, 0, s2>>>(par, NBLK);
        scan_add<<<NBLK, 256, 0, s2>>>(off, par, 50000);
        csr_scatter<<<EB, 256, 0, s2>>>(R.src, R.dst, off, cur, srt);
    }

    // ---- main: author micro GEMM (+fused attn dots) ----
    {
        GemmJob ja = { feats_author, W_micro_author, PA, nullptr, nullptr,
                       attn_micro_a + 0,  elA_aA,
                       attn_micro_p + 32, erA_aP,
                       nullptr, nullptr };
        gemm_multi<<<GG, 256, SMEM_BYTES>>>(ja, jz, jz, 1, NA);
    }
    cudaEventRecord(evA, 0);

    // ---- s2: paper micro GEMM (+3 fused attn dots) ----
    {
        GemmJob ja = { feats_paper, W_micro_paper, PP, nullptr, nullptr,
                       attn_micro_a + 32, erP_aA,
                       attn_micro_p + 0,  elP_aP,
                       attn_micro_p + 32, erP_aP };
        gemm_multi<<<GG, 256, SMEM_BYTES, s2>>>(ja, jz, jz, 1, NP);
    }

    // ---- s2: gather cites (paper-only deps) ----
    micro_gather<<<GB, 256, 0, s2>>>(ssort + 2 * EDG, offsets + 2 * 50001,
                                     elP_aP, erP_aP, PP, ft_c, NP);
    cudaEventRecord(evG2, s2);

    // ---- s2: remaining gathers need author micro ----
    cudaStreamWaitEvent(s2, evA, 0);
    micro_gather<<<GB, 256, 0, s2>>>(ssort + 0 * EDG, offsets + 0 * 50001,
                                     elA_aA, erP_aA, PA, ft_w, NP);
    cudaEventRecord(evG0, s2);
    micro_gather<<<GB, 256, 0, s2>>>(ssort + 1 * EDG, offsets + 1 * 50001,
                                     elP_aP, erA_aP, PP, ft_wb, NA);

    // ---- main: 3-job GEMM (res_author, nodeP, res_paper) overlapping gathers ----
    {
        GemmJob ja = { feats_author, W_res_author, out, b_res_author, nullptr,
                       nullptr, nullptr, nullptr, nullptr, nullptr, nullptr };
        GemmJob jb = { feats_paper, W_macro_node_p, nodeP, nullptr, nullptr,
                       nullptr, nullptr, nullptr, nullptr, nullptr, nullptr };
        GemmJob jc = { feats_paper, W_res_paper, out + (size_t)NA * KD, b_res_paper, nullptr,
                       nullptr, nullptr, nullptr, nullptr, nullptr, nullptr };
        gemm_multi<<<GG, 256, SMEM_BYTES>>>(ja, jb, jc, 3, NA);
    }
    cudaEventRecord(evRes, 0);

    // ---- s2: wb gated GEMM (needs ft_wb in-stream + out[:NA] residual) ----
    cudaStreamWaitEvent(s2, evRes, 0);
    {
        GemmJob ja = { ft_wb, W_rel_wb, out, nullptr, res_w_author,
                       nullptr, nullptr, nullptr, nullptr, nullptr, nullptr };
        gemm_multi<<<GG, 256, SMEM_BYTES, s2>>>(ja, jz, jz, 1, NA);
    }
    cudaEventRecord(evS2, s2);

    // ---- main: fused rf_w + rf_c + semantic attention + gated residual -> out[NA:] ----
    cudaStreamWaitEvent(0, evG0, 0);
    cudaStreamWaitEvent(0, evG2, 0);
    gemm_rf_fused<<<GG, 256, FUSE_SMEM>>>(ft_w, W_rel_writes, ft_c, W_rel_cites,
                                          nodeP, attn_macro, res_w_paper,
                                          out + (size_t)NA * KD, NP);

    // ---- join s2 ----
    cudaStreamWaitEvent(0, evS2, 0);
    join_k<<<1, 1>>>();
}

// round 12
// speedup vs baseline: 1.1603x; 1.0368x over previous
#include <cuda_runtime.h>
#include <cstdint>
#include <math.h>

// ---------------- problem constants ----------------
#define NA 50000
#define NP 50000
#define EDG 400000
#define KH 8
#define DH 32
#define KD 256
#define SLOPE 0.2f

// GEMM tiling: block 128(M) x 256(N), 8 warps (2m x 4n), warp tile 64x64, BK=16 (tf32)
#define BM 128
#define BK 16
#define NKT (KD / BK)      // 16
#define LDK 20
#define LDBN 264
#define ASZ (128 * LDK)
#define BSZ (BK * LDBN)
#define SMEM_BYTES ((2 * ASZ + 2 * BSZ) * 4)     // 54272
#define RFLD 260
#define FUSE_SMEM (SMEM_BYTES + 128 * RFLD * 4)  // 187392

#define NTOT 150000                    // 3 * 50000
#define NBLK3 ((NTOT + 255) / 256)     // 586

// ---------------- device scratch ----------------
__device__ float g_PA[NA * KD];
__device__ float g_PP[NP * KD];

__device__ float g_elA_aA[NA * KH];
__device__ float g_erP_aA[NP * KH];
__device__ float g_elP_aP[NP * KH];
__device__ float g_erA_aP[NA * KH];
__device__ float g_erP_aP[NP * KH];

__device__ float g_ft_w[NP * KD];
__device__ float g_ft_wb[NA * KD];
__device__ float g_ft_c[NP * KD];

__device__ float g_npscore[NP * KH];   // <nodeP[n,k,:], attnM[k,:32]>

// CSR scratch (combined across the 3 relations)
__device__ int g_counts[NTOT];
__device__ int g_cursor[NTOT];
__device__ int g_offsets[NTOT + 1];
__device__ int g_partials[NBLK3 + 2];
__device__ int g_ssort[3 * EDG];

// ---------------- helpers ----------------
__device__ __forceinline__ float leaky(float v) {
    return v > 0.f ? v : SLOPE * v;
}
__device__ __forceinline__ uint32_t f2tf32(float f) {
    uint32_t r;
    asm("cvt.rna.tf32.f32 %0, %1;" : "=r"(r) : "f"(f));
    return r;
}
__device__ __forceinline__ void mma_tf32(float c[4], uint32_t a0, uint32_t a1,
                                         uint32_t a2, uint32_t a3,
                                         uint32_t b0, uint32_t b1) {
    asm volatile(
        "mma.sync.aligned.m16n8k8.row.col.f32.tf32.tf32.f32 "
        "{%0,%1,%2,%3}, {%4,%5,%6,%7}, {%8,%9}, {%0,%1,%2,%3};"
        : "+f"(c[0]), "+f"(c[1]), "+f"(c[2]), "+f"(c[3])
        : "r"(a0), "r"(a1), "r"(a2), "r"(a3), "r"(b0), "r"(b1));
}

struct GemmJob {
    const float* A;
    const float* B;
    float*       C;        // nullable: skip C store
    const float* bias;
    const float* gate;
    const float* av0; float* ao0;
    const float* av1; float* ao1;
    const float* av2; float* ao2;
};

// ================= multi-job tf32 GEMM (128x256 block) =================
__global__ void __launch_bounds__(256, 1) gemm_multi(
    GemmJob j0, GemmJob j1, GemmJob j2, int nb, int M)
{
    extern __shared__ uint32_t smem[];
    const int tid = threadIdx.x;
    const int lane = tid & 31;
    const int wid = tid >> 5;
    const int wm = (wid & 1) * 64;
    const int wn = (wid >> 1) * 64;
    const int m0 = blockIdx.x * BM;

    const int qr = lane >> 2;
    const int qc = lane & 3;

    const int am = tid >> 1;
    const int aq = (tid & 1) * 8;
    const int bkr = tid >> 4;
    const int bnc = (tid & 15) * 16;

    float4 rA[2], rB[4];

    auto g_load = [&](int kt, const float* __restrict__ A, const float* __restrict__ B) {
        const int k0 = kt * BK;
        int row = m0 + am;
        if (row < M) {
            rA[0] = *(const float4*)&A[(size_t)row * KD + k0 + aq];
            rA[1] = *(const float4*)&A[(size_t)row * KD + k0 + aq + 4];
        } else {
            rA[0] = make_float4(0.f, 0.f, 0.f, 0.f);
            rA[1] = rA[0];
        }
        const float* bp = &B[(size_t)(k0 + bkr) * KD + bnc];
        rB[0] = *(const float4*)&bp[0];
        rB[1] = *(const float4*)&bp[4];
        rB[2] = *(const float4*)&bp[8];
        rB[3] = *(const float4*)&bp[12];
    };
    auto s_store = [&](int buf) {
        uint32_t* as = &smem[buf * ASZ + am * LDK + aq];
        uint4 v0, v1;
        v0.x = f2tf32(rA[0].x); v0.y = f2tf32(rA[0].y);
        v0.z = f2tf32(rA[0].z); v0.w = f2tf32(rA[0].w);
        v1.x = f2tf32(rA[1].x); v1.y = f2tf32(rA[1].y);
        v1.z = f2tf32(rA[1].z); v1.w = f2tf32(rA[1].w);
        *(uint4*)&as[0] = v0;
        *(uint4*)&as[4] = v1;
        uint32_t* bs = &smem[2 * ASZ + buf * BSZ + bkr * LDBN + bnc];
#pragma unroll
        for (int q = 0; q < 4; q++) {
            uint4 w;
            w.x = f2tf32(((const float*)&rB[q])[0]);
            w.y = f2tf32(((const float*)&rB[q])[1]);
            w.z = f2tf32(((const float*)&rB[q])[2]);
            w.w = f2tf32(((const float*)&rB[q])[3]);
            *(uint4*)&bs[q * 4] = w;
        }
    };

#pragma unroll
    for (int o = 0; o < 3; o++) {
        if (o >= nb) break;
        const GemmJob J = (o == 0) ? j0 : (o == 1) ? j1 : j2;

        float acc[4][8][4];
#pragma unroll
        for (int mi = 0; mi < 4; mi++)
#pragma unroll
            for (int ni = 0; ni < 8; ni++)
#pragma unroll
                for (int r = 0; r < 4; r++) acc[mi][ni][r] = 0.f;

        g_load(0, J.A, J.B);
        s_store(0);
        __syncthreads();

        for (int kt = 0; kt < NKT; kt++) {
            const int cur = kt & 1;
            if (kt + 1 < NKT) g_load(kt + 1, J.A, J.B);

            const uint32_t* asb = &smem[cur * ASZ];
            const uint32_t* bsb = &smem[2 * ASZ + cur * BSZ];
#pragma unroll
            for (int ks = 0; ks < BK; ks += 8) {
                uint32_t a[4][4], b[8][2];
#pragma unroll
                for (int mi = 0; mi < 4; mi++) {
                    int r0 = wm + mi * 16 + qr;
                    a[mi][0] = asb[r0 * LDK + ks + qc];
                    a[mi][1] = asb[(r0 + 8) * LDK + ks + qc];
                    a[mi][2] = asb[r0 * LDK + ks + qc + 4];
                    a[mi][3] = asb[(r0 + 8) * LDK + ks + qc + 4];
                }
#pragma unroll
                for (int ni = 0; ni < 8; ni++) {
                    int c0 = wn + ni * 8 + qr;
                    b[ni][0] = bsb[(ks + qc) * LDBN + c0];
                    b[ni][1] = bsb[(ks + qc + 4) * LDBN + c0];
                }
#pragma unroll
                for (int mi = 0; mi < 4; mi++)
#pragma unroll
                    for (int ni = 0; ni < 8; ni++)
                        mma_tf32(acc[mi][ni], a[mi][0], a[mi][1], a[mi][2], a[mi][3],
                                 b[ni][0], b[ni][1]);
            }

            if (kt + 1 < NKT) {
                s_store(1 - cur);
                __syncthreads();
            }
        }

        if (J.av0) {
            const float* avs[3] = { J.av0, J.av1, J.av2 };
            float*       aos[3] = { J.ao0, J.ao1, J.ao2 };
            const int h0 = wn >> 5;
#pragma unroll
            for (int t = 0; t < 3; t++) {
                const float* av = avs[t];
                if (!av) break;
                float* ao = aos[t];
                float c0[8], c1[8];
#pragma unroll
                for (int ni = 0; ni < 8; ni++) {
                    int col = wn + ni * 8 + qc * 2;
                    int idx = (col >> 5) * 64 + (col & 31);
                    c0[ni] = av[idx];
                    c1[ni] = av[idx + 1];
                }
#pragma unroll
                for (int mi = 0; mi < 4; mi++) {
#pragma unroll
                    for (int half = 0; half < 2; half++) {
                        float pa = 0.f, pb = 0.f;
#pragma unroll
                        for (int ni = 0; ni < 4; ni++)
                            pa += acc[mi][ni][half * 2] * c0[ni]
                                + acc[mi][ni][half * 2 + 1] * c1[ni];
#pragma unroll
                        for (int ni = 4; ni < 8; ni++)
                            pb += acc[mi][ni][half * 2] * c0[ni]
                                + acc[mi][ni][half * 2 + 1] * c1[ni];
                        pa += __shfl_xor_sync(0xffffffffu, pa, 1);
                        pa += __shfl_xor_sync(0xffffffffu, pa, 2);
                        pb += __shfl_xor_sync(0xffffffffu, pb, 1);
                        pb += __shfl_xor_sync(0xffffffffu, pb, 2);
                        int row = m0 + wm + mi * 16 + qr + half * 8;
                        if (qc == 0 && row < M) {
                            ao[row * KH + h0]     = pa;
                            ao[row * KH + h0 + 1] = pb;
                        }
                    }
                }
            }
        }

        if (J.C) {
            float g = 0.f;
            if (J.gate) g = 1.f / (1.f + __expf(-J.gate[0]));
#pragma unroll
            for (int mi = 0; mi < 4; mi++) {
#pragma unroll
                for (int half = 0; half < 2; half++) {
                    int row = m0 + wm + mi * 16 + qr + half * 8;
                    if (row >= M) continue;
                    float* dst = &J.C[(size_t)row * KD + wn];
#pragma unroll
                    for (int ni = 0; ni < 8; ni++) {
                        int col = ni * 8 + qc * 2;
                        float2 v;
                        v.x = acc[mi][ni][half * 2 + 0];
                        v.y = acc[mi][ni][half * 2 + 1];
                        if (J.bias) {
                            v.x += J.bias[wn + col + 0];
                            v.y += J.bias[wn + col + 1];
                        }
                        if (J.gate) {
                            float2 prev = *(const float2*)&dst[col];
                            v.x = g * v.x + (1.f - g) * prev.x;
                            v.y = g * v.y + (1.f - g) * prev.y;
                        }
                        *(float2*)&dst[col] = v;
                    }
                }
            }
        }
        __syncthreads();
    }
}

// ================= fused rf_w + rf_c GEMM + semantic attention + gated residual =================
__global__ void __launch_bounds__(256, 1) gemm_rf_fused(
    const float* __restrict__ Aw, const float* __restrict__ Bw,
    const float* __restrict__ Ac, const float* __restrict__ Bc,
    const float* __restrict__ npscore, const float* __restrict__ attnM,
    const float* __restrict__ resw, float* __restrict__ outP, int M)
{
    extern __shared__ uint32_t smem[];
    float* rfbuf = (float*)(smem + 2 * ASZ + 2 * BSZ);   // [128][RFLD]

    const int tid = threadIdx.x;
    const int lane = tid & 31;
    const int wid = tid >> 5;
    const int wm = (wid & 1) * 64;
    const int wn = (wid >> 1) * 64;
    const int m0 = blockIdx.x * BM;

    const int qr = lane >> 2;
    const int qc = lane & 3;

    const int am = tid >> 1;
    const int aq = (tid & 1) * 8;
    const int bkr = tid >> 4;
    const int bnc = (tid & 15) * 16;

    float4 rA[2], rB[4];

    auto g_load = [&](int kt, const float* __restrict__ A, const float* __restrict__ B) {
        const int k0 = kt * BK;
        int row = m0 + am;
        if (row < M) {
            rA[0] = *(const float4*)&A[(size_t)row * KD + k0 + aq];
            rA[1] = *(const float4*)&A[(size_t)row * KD + k0 + aq + 4];
        } else {
            rA[0] = make_float4(0.f, 0.f, 0.f, 0.f);
            rA[1] = rA[0];
        }
        const float* bp = &B[(size_t)(k0 + bkr) * KD + bnc];
        rB[0] = *(const float4*)&bp[0];
        rB[1] = *(const float4*)&bp[4];
        rB[2] = *(const float4*)&bp[8];
        rB[3] = *(const float4*)&bp[12];
    };
    auto s_store = [&](int buf) {
        uint32_t* as = &smem[buf * ASZ + am * LDK + aq];
        uint4 v0, v1;
        v0.x = f2tf32(rA[0].x); v0.y = f2tf32(rA[0].y);
        v0.z = f2tf32(rA[0].z); v0.w = f2tf32(rA[0].w);
        v1.x = f2tf32(rA[1].x); v1.y = f2tf32(rA[1].y);
        v1.z = f2tf32(rA[1].z); v1.w = f2tf32(rA[1].w);
        *(uint4*)&as[0] = v0;
        *(uint4*)&as[4] = v1;
        uint32_t* bs = &smem[2 * ASZ + buf * BSZ + bkr * LDBN + bnc];
#pragma unroll
        for (int q = 0; q < 4; q++) {
            uint4 w;
            w.x = f2tf32(((const float*)&rB[q])[0]);
            w.y = f2tf32(((const float*)&rB[q])[1]);
            w.z = f2tf32(((const float*)&rB[q])[2]);
            w.w = f2tf32(((const float*)&rB[q])[3]);
            *(uint4*)&bs[q * 4] = w;
        }
    };

#pragma unroll
    for (int o = 0; o < 2; o++) {
        const float* A = (o == 0) ? Aw : Ac;
        const float* B = (o == 0) ? Bw : Bc;

        float acc[4][8][4];
#pragma unroll
        for (int mi = 0; mi < 4; mi++)
#pragma unroll
            for (int ni = 0; ni < 8; ni++)
#pragma unroll
                for (int r = 0; r < 4; r++) acc[mi][ni][r] = 0.f;

        g_load(0, A, B);
        s_store(0);
        __syncthreads();

        for (int kt = 0; kt < NKT; kt++) {
            const int cur = kt & 1;
            if (kt + 1 < NKT) g_load(kt + 1, A, B);

            const uint32_t* asb = &smem[cur * ASZ];
            const uint32_t* bsb = &smem[2 * ASZ + cur * BSZ];
#pragma unroll
            for (int ks = 0; ks < BK; ks += 8) {
                uint32_t a[4][4], b[8][2];
#pragma unroll
                for (int mi = 0; mi < 4; mi++) {
                    int r0 = wm + mi * 16 + qr;
                    a[mi][0] = asb[r0 * LDK + ks + qc];
                    a[mi][1] = asb[(r0 + 8) * LDK + ks + qc];
                    a[mi][2] = asb[r0 * LDK + ks + qc + 4];
                    a[mi][3] = asb[(r0 + 8) * LDK + ks + qc + 4];
                }
#pragma unroll
                for (int ni = 0; ni < 8; ni++) {
                    int c0 = wn + ni * 8 + qr;
                    b[ni][0] = bsb[(ks + qc) * LDBN + c0];
                    b[ni][1] = bsb[(ks + qc + 4) * LDBN + c0];
                }
#pragma unroll
                for (int mi = 0; mi < 4; mi++)
#pragma unroll
                    for (int ni = 0; ni < 8; ni++)
                        mma_tf32(acc[mi][ni], a[mi][0], a[mi][1], a[mi][2], a[mi][3],
                                 b[ni][0], b[ni][1]);
            }

            if (kt + 1 < NKT) {
                s_store(1 - cur);
                __syncthreads();
            }
        }

        if (o == 0) {
#pragma unroll
            for (int mi = 0; mi < 4; mi++)
#pragma unroll
                for (int half = 0; half < 2; half++) {
                    int lr = wm + mi * 16 + qr + half * 8;
                    float* dst = &rfbuf[lr * RFLD + wn];
#pragma unroll
                    for (int ni = 0; ni < 8; ni++) {
                        int col = ni * 8 + qc * 2;
                        dst[col]     = acc[mi][ni][half * 2 + 0];
                        dst[col + 1] = acc[mi][ni][half * 2 + 1];
                    }
                }
            __syncthreads();
            continue;
        }

        // ---- fusion epilogue ----
        const float g = 1.f / (1.f + __expf(-resw[0]));
        const int h0 = wn >> 5;
        float cr0[8], cr1[8];
#pragma unroll
        for (int ni = 0; ni < 8; ni++) {
            int col = wn + ni * 8 + qc * 2;
            int base = (col >> 5) * 64 + (col & 31);
            cr0[ni] = attnM[base + 32];
            cr1[ni] = attnM[base + 33];
        }

#pragma unroll
        for (int mi = 0; mi < 4; mi++) {
#pragma unroll
            for (int half = 0; half < 2; half++) {
                int lr = wm + mi * 16 + qr + half * 8;
                int row = m0 + lr;
                if (row >= M) continue;
                const float* rwrow = &rfbuf[lr * RFLD + wn];
                float* orow = &outP[(size_t)row * KD + wn];
                float npa = npscore[row * KH + h0];
                float npb = npscore[row * KH + h0 + 1];

                float swa = 0.f, sca = 0.f, swb = 0.f, scb = 0.f;
#pragma unroll
                for (int ni = 0; ni < 8; ni++) {
                    int col = ni * 8 + qc * 2;
                    float rw0 = rwrow[col], rw1 = rwrow[col + 1];
                    float rc0 = acc[mi][ni][half * 2], rc1 = acc[mi][ni][half * 2 + 1];
                    float wpart = rw0 * cr0[ni] + rw1 * cr1[ni];
                    float cpart = rc0 * cr0[ni] + rc1 * cr1[ni];
                    if (ni < 4) { swa += wpart; sca += cpart; }
                    else        { swb += wpart; scb += cpart; }
                }
                swa += __shfl_xor_sync(0xffffffffu, swa, 1);
                swa += __shfl_xor_sync(0xffffffffu, swa, 2);
                sca += __shfl_xor_sync(0xffffffffu, sca, 1);
                sca += __shfl_xor_sync(0xffffffffu, sca, 2);
                swb += __shfl_xor_sync(0xffffffffu, swb, 1);
                swb += __shfl_xor_sync(0xffffffffu, swb, 2);
                scb += __shfl_xor_sync(0xffffffffu, scb, 1);
                scb += __shfl_xor_sync(0xffffffffu, scb, 2);

                float swA = leaky(npa + swa), scA = leaky(npa + sca);
                float swB = leaky(npb + swb), scB = leaky(npb + scb);
                float ma = fmaxf(swA, scA);
                float ea = __expf(swA - ma), eca = __expf(scA - ma);
                float awa = ea / (ea + eca);
                float mb = fmaxf(swB, scB);
                float eb = __expf(swB - mb), ecb = __expf(scB - mb);
                float awb = eb / (eb + ecb);

#pragma unroll
                for (int ni = 0; ni < 8; ni++) {
                    int col = ni * 8 + qc * 2;
                    float aw = (ni < 4) ? awa : awb;
                    float rw0 = rwrow[col], rw1 = rwrow[col + 1];
                    float rc0 = acc[mi][ni][half * 2], rc1 = acc[mi][ni][half * 2 + 1];
                    float2 prev = *(const float2*)&orow[col];
                    float2 v;
                    v.x = g * (aw * rw0 + (1.f - aw) * rc0) + (1.f - g) * prev.x;
                    v.y = g * (aw * rw1 + (1.f - aw) * rc1) + (1.f - g) * prev.y;
                    *(float2*)&orow[col] = v;
                }
            }
        }
    }
}

// trailing join node
__global__ void join_k() {}

// ---------------- batched CSR build ----------------
__global__ void csr_hist3(const int* __restrict__ d0, const int* __restrict__ d1,
                          const int* __restrict__ d2, int* __restrict__ counts)
{
    int e = blockIdx.x * blockDim.x + threadIdx.x;
    if (e >= EDG) return;
    atomicAdd(&counts[d0[e]], 1);
    atomicAdd(&counts[50000 + d1[e]], 1);
    atomicAdd(&counts[100000 + d2[e]], 1);
}

__global__ void scan_block(const int* __restrict__ in, int* __restrict__ out,
                           int* __restrict__ partials, int n)
{
    __shared__ int wsum[8];
    int i = blockIdx.x * 256 + threadIdx.x;
    int lane = threadIdx.x & 31, wid = threadIdx.x >> 5;
    int v = (i < n) ? in[i] : 0;
    int x = v;
#pragma unroll
    for (int o = 1; o < 32; o <<= 1) {
        int t = __shfl_up_sync(0xffffffffu, x, o);
        if (lane >= o) x += t;
    }
    if (lane == 31) wsum[wid] = x;
    __syncthreads();
    if (wid == 0) {
        int w = (lane < 8) ? wsum[lane] : 0;
#pragma unroll
        for (int o = 1; o < 8; o <<= 1) {
            int t = __shfl_up_sync(0xffffffffu, w, o);
            if (lane >= o) w += t;
        }
        if (lane < 8) wsum[lane] = w;
    }
    __syncthreads();
    int wpre = (wid > 0) ? wsum[wid - 1] : 0;
    if (i < n) out[i] = wpre + x - v;
    if (threadIdx.x == 0) partials[blockIdx.x] = wsum[7];
}

// top scan over up to 1024 partials (launch 1024 threads)
__global__ void scan_top1k(int* __restrict__ partials, int nb)
{
    __shared__ int wsum[32];
    int i = threadIdx.x;
    int lane = i & 31, wid = i >> 5;
    int v = (i < nb) ? partials[i] : 0;
    int x = v;
#pragma unroll
    for (int o = 1; o < 32; o <<= 1) {
        int t = __shfl_up_sync(0xffffffffu, x, o);
        if (lane >= o) x += t;
    }
    if (lane == 31) wsum[wid] = x;
    __syncthreads();
    if (wid == 0) {
        int w = wsum[lane];
#pragma unroll
        for (int o = 1; o < 32; o <<= 1) {
            int t = __shfl_up_sync(0xffffffffu, w, o);
            if (lane >= o) w += t;
        }
        wsum[lane] = w;
    }
    __syncthreads();
    int wpre = (wid > 0) ? wsum[wid - 1] : 0;
    if (i < nb) partials[i] = wpre + x - v;
    if (i == 0) partials[nb] = wsum[31];
}

__global__ void scan_add(int* __restrict__ offsets, const int* __restrict__ partials, int n)
{
    int i = blockIdx.x * 256 + threadIdx.x;
    if (i < n) offsets[i] += partials[blockIdx.x];
    if (i == 0) offsets[n] = partials[gridDim.x];
}

__global__ void csr_scatter3(
    const int* __restrict__ s0, const int* __restrict__ d0,
    const int* __restrict__ s1, const int* __restrict__ d1,
    const int* __restrict__ s2p, const int* __restrict__ d2,
    const int* __restrict__ offsets, int* __restrict__ cursor,
    int* __restrict__ ssort)
{
    int idx = blockIdx.x * blockDim.x + threadIdx.x;
    if (idx >= 3 * EDG) return;
    int r = (idx >= 2 * EDG) ? 2 : (idx >= EDG) ? 1 : 0;
    int e = idx - r * EDG;
    const int* src = (r == 0) ? s0 : (r == 1) ? s1 : s2p;
    const int* dst = (r == 0) ? d0 : (r == 1) ? d1 : d2;
    int key = r * 50000 + dst[e];
    int pos = offsets[key] + atomicAdd(&cursor[key], 1);
    ssort[pos] = src[e];
}

// ---------------- fused micro gather (no max pass; |scores| << 80 so exp is safe) ----------------
__global__ void micro_gather(const int* __restrict__ ssort, const int* __restrict__ offsets,
                             const float* __restrict__ el, const float* __restrict__ er,
                             const float* __restrict__ Psrc, float* __restrict__ ft, int n_dst)
{
    int d = (blockIdx.x * blockDim.x + threadIdx.x) >> 5;
    int lane = threadIdx.x & 31;
    if (d >= n_dst) return;
    int beg = offsets[d], end = offsets[d + 1];
    float* dstp = &ft[(size_t)d * KD + lane * 8];
    if (beg == end) {
        float4 z = make_float4(0.f, 0.f, 0.f, 0.f);
        *(float4*)dstp = z;
        *(float4*)(dstp + 4) = z;
        return;
    }
    float erh = (lane < KH) ? er[d * KH + lane] : 0.f;

    const int hk = lane >> 2;
    float acc[8] = {0.f, 0.f, 0.f, 0.f, 0.f, 0.f, 0.f, 0.f};
    float se = 0.f;
    int i = beg;
    for (; i + 2 <= end; i += 2) {
        int s0 = ssort[i], s1 = ssort[i + 1];
        float w0 = 0.f, w1 = 0.f;
        if (lane < KH) {
            w0 = __expf(leaky(el[s0 * KH + lane] + erh));
            w1 = __expf(leaky(el[s1 * KH + lane] + erh));
            se += w0 + w1;
        }
        float wk0 = __shfl_sync(0xffffffffu, w0, hk);
        float wk1 = __shfl_sync(0xffffffffu, w1, hk);
        const float4* p0 = (const float4*)&Psrc[(size_t)s0 * KD + lane * 8];
        const float4* p1 = (const float4*)&Psrc[(size_t)s1 * KD + lane * 8];
        float4 a0 = p0[0], a1 = p0[1], b0 = p1[0], b1 = p1[1];
        acc[0] = fmaf(wk0, a0.x, acc[0]); acc[0] = fmaf(wk1, b0.x, acc[0]);
        acc[1] = fmaf(wk0, a0.y, acc[1]); acc[1] = fmaf(wk1, b0.y, acc[1]);
        acc[2] = fmaf(wk0, a0.z, acc[2]); acc[2] = fmaf(wk1, b0.z, acc[2]);
        acc[3] = fmaf(wk0, a0.w, acc[3]); acc[3] = fmaf(wk1, b0.w, acc[3]);
        acc[4] = fmaf(wk0, a1.x, acc[4]); acc[4] = fmaf(wk1, b1.x, acc[4]);
        acc[5] = fmaf(wk0, a1.y, acc[5]); acc[5] = fmaf(wk1, b1.y, acc[5]);
        acc[6] = fmaf(wk0, a1.z, acc[6]); acc[6] = fmaf(wk1, b1.z, acc[6]);
        acc[7] = fmaf(wk0, a1.w, acc[7]); acc[7] = fmaf(wk1, b1.w, acc[7]);
    }
    if (i < end) {
        int s0 = ssort[i];
        float w0 = 0.f;
        if (lane < KH) {
            w0 = __expf(leaky(el[s0 * KH + lane] + erh));
            se += w0;
        }
        float wk0 = __shfl_sync(0xffffffffu, w0, hk);
        const float4* p0 = (const float4*)&Psrc[(size_t)s0 * KD + lane * 8];
        float4 a0 = p0[0], a1 = p0[1];
        acc[0] = fmaf(wk0, a0.x, acc[0]);
        acc[1] = fmaf(wk0, a0.y, acc[1]);
        acc[2] = fmaf(wk0, a0.z, acc[2]);
        acc[3] = fmaf(wk0, a0.w, acc[3]);
        acc[4] = fmaf(wk0, a1.x, acc[4]);
        acc[5] = fmaf(wk0, a1.y, acc[5]);
        acc[6] = fmaf(wk0, a1.z, acc[6]);
        acc[7] = fmaf(wk0, a1.w, acc[7]);
    }
    float inv = 1.f / __shfl_sync(0xffffffffu, se, hk);
    float4 o0, o1;
    o0.x = fmaxf(acc[0] * inv, 0.f);
    o0.y = fmaxf(acc[1] * inv, 0.f);
    o0.z = fmaxf(acc[2] * inv, 0.f);
    o0.w = fmaxf(acc[3] * inv, 0.f);
    o1.x = fmaxf(acc[4] * inv, 0.f);
    o1.y = fmaxf(acc[5] * inv, 0.f);
    o1.z = fmaxf(acc[6] * inv, 0.f);
    o1.w = fmaxf(acc[7] * inv, 0.f);
    *(float4*)dstp = o0;
    *(float4*)(dstp + 4) = o1;
}

// ---------------- launch ----------------
extern "C" void kernel_launch(void* const* d_in, const int* in_sizes, int n_in,
                              void* d_out, int out_size)
{
    const float* feats_author    = (const float*)d_in[0];
    const float* feats_paper     = (const float*)d_in[1];
    const float* W_micro_author  = (const float*)d_in[2];
    const float* W_micro_paper   = (const float*)d_in[3];
    const float* attn_micro_a    = (const float*)d_in[4];
    const float* attn_micro_p    = (const float*)d_in[5];
    const float* W_macro_node_p  = (const float*)d_in[7];
    const float* W_rel_writes    = (const float*)d_in[8];
    const float* W_rel_wb        = (const float*)d_in[9];
    const float* W_rel_cites     = (const float*)d_in[10];
    const float* attn_macro      = (const float*)d_in[11];
    const float* W_res_author    = (const float*)d_in[12];
    const float* b_res_author    = (const float*)d_in[13];
    const float* W_res_paper     = (const float*)d_in[14];
    const float* b_res_paper     = (const float*)d_in[15];
    const float* res_w_author    = (const float*)d_in[16];
    const float* res_w_paper     = (const float*)d_in[17];
    const int*   writes_src      = (const int*)d_in[18];
    const int*   writes_dst      = (const int*)d_in[19];
    const int*   wb_src          = (const int*)d_in[20];
    const int*   wb_dst          = (const int*)d_in[21];
    const int*   cites_src       = (const int*)d_in[22];
    const int*   cites_dst       = (const int*)d_in[23];
    float* out = (float*)d_out;

    float *PA, *PP, *elA_aA, *erP_aA, *elP_aP, *erA_aP, *erP_aP;
    float *ft_w, *ft_wb, *ft_c, *npscore;
    int *counts, *cursor, *offsets, *partials, *ssort;
    cudaGetSymbolAddress((void**)&PA, g_PA);
    cudaGetSymbolAddress((void**)&PP, g_PP);
    cudaGetSymbolAddress((void**)&elA_aA, g_elA_aA);
    cudaGetSymbolAddress((void**)&erP_aA, g_erP_aA);
    cudaGetSymbolAddress((void**)&elP_aP, g_elP_aP);
    cudaGetSymbolAddress((void**)&erA_aP, g_erA_aP);
    cudaGetSymbolAddress((void**)&erP_aP, g_erP_aP);
    cudaGetSymbolAddress((void**)&ft_w, g_ft_w);
    cudaGetSymbolAddress((void**)&ft_wb, g_ft_wb);
    cudaGetSymbolAddress((void**)&ft_c, g_ft_c);
    cudaGetSymbolAddress((void**)&npscore, g_npscore);
    cudaGetSymbolAddress((void**)&counts, g_counts);
    cudaGetSymbolAddress((void**)&cursor, g_cursor);
    cudaGetSymbolAddress((void**)&offsets, g_offsets);
    cudaGetSymbolAddress((void**)&partials, g_partials);
    cudaGetSymbolAddress((void**)&ssort, g_ssort);

    static cudaStream_t s2 = nullptr;
    static cudaEvent_t evFork = nullptr, evA = nullptr, evG0 = nullptr,
                       evG2 = nullptr, evS2 = nullptr, evRes = nullptr;
    if (!s2) {
        cudaStreamCreateWithFlags(&s2, cudaStreamNonBlocking);
        cudaEventCreateWithFlags(&evFork, cudaEventDisableTiming);
        cudaEventCreateWithFlags(&evA, cudaEventDisableTiming);
        cudaEventCreateWithFlags(&evG0, cudaEventDisableTiming);
        cudaEventCreateWithFlags(&evG2, cudaEventDisableTiming);
        cudaEventCreateWithFlags(&evS2, cudaEventDisableTiming);
        cudaEventCreateWithFlags(&evRes, cudaEventDisableTiming);
    }

    cudaFuncSetAttribute(gemm_multi, cudaFuncAttributeMaxDynamicSharedMemorySize, SMEM_BYTES);
    cudaFuncSetAttribute(gemm_rf_fused, cudaFuncAttributeMaxDynamicSharedMemorySize, FUSE_SMEM);

    const int GG = (NA + BM - 1) / BM;          // 391
    const int EB = (EDG + 255) / 256;
    const int EB3 = (3 * EDG + 255) / 256;
    const int GB = (NA * 32 + 255) / 256;

    GemmJob jz = {};

    // ---- fork: s2 runs batched CSR build ----
    cudaEventRecord(evFork, 0);
    cudaStreamWaitEvent(s2, evFork, 0);
    cudaMemsetAsync(counts, 0, NTOT * sizeof(int), s2);
    cudaMemsetAsync(cursor, 0, NTOT * sizeof(int), s2);
    csr_hist3<<<EB, 256, 0, s2>>>(writes_dst, wb_dst, cites_dst, counts);
    scan_block<<<NBLK3, 256, 0, s2>>>(counts, offsets, partials, NTOT);
    scan_top1k<<<1, 1024, 0, s2>>>(partials, NBLK3);
    scan_add<<<NBLK3, 256, 0, s2>>>(offsets, partials, NTOT);
    csr_scatter3<<<EB3, 256, 0, s2>>>(writes_src, writes_dst, wb_src, wb_dst,
                                      cites_src, cites_dst, offsets, cursor, ssort);

    // ---- main: author micro GEMM (+fused attn dots) ----
    {
        GemmJob ja = { feats_author, W_micro_author, PA, nullptr, nullptr,
                       attn_micro_a + 0,  elA_aA,
                       attn_micro_p + 32, erA_aP,
                       nullptr, nullptr };
        gemm_multi<<<GG, 256, SMEM_BYTES>>>(ja, jz, jz, 1, NA);
    }
    cudaEventRecord(evA, 0);

    // ---- s2: paper micro GEMM (+3 fused attn dots) ----
    {
        GemmJob ja = { feats_paper, W_micro_paper, PP, nullptr, nullptr,
                       attn_micro_a + 32, erP_aA,
                       attn_micro_p + 0,  elP_aP,
                       attn_micro_p + 32, erP_aP };
        gemm_multi<<<GG, 256, SMEM_BYTES, s2>>>(ja, jz, jz, 1, NP);
    }

    // ---- s2: gather cites (paper-only deps) ----
    micro_gather<<<GB, 256, 0, s2>>>(ssort, offsets + 2 * 50000,
                                     elP_aP, erP_aP, PP, ft_c, NP);
    cudaEventRecord(evG2, s2);

    // ---- s2: remaining gathers need author micro ----
    cudaStreamWaitEvent(s2, evA, 0);
    micro_gather<<<GB, 256, 0, s2>>>(ssort, offsets + 0 * 50000,
                                     elA_aA, erP_aA, PA, ft_w, NP);
    cudaEventRecord(evG0, s2);
    micro_gather<<<GB, 256, 0, s2>>>(ssort, offsets + 1 * 50000,
                                     elP_aP, erA_aP, PP, ft_wb, NA);

    // ---- main: 3-job GEMM (res_author, npscore via fused dot (no C), res_paper) ----
    {
        GemmJob ja = { feats_author, W_res_author, out, b_res_author, nullptr,
                       nullptr, nullptr, nullptr, nullptr, nullptr, nullptr };
        GemmJob jb = { feats_paper, W_macro_node_p, nullptr, nullptr, nullptr,
                       attn_macro + 0, npscore,
                       nullptr, nullptr, nullptr, nullptr };
        GemmJob jc = { feats_paper, W_res_paper, out + (size_t)NA * KD, b_res_paper, nullptr,
                       nullptr, nullptr, nullptr, nullptr, nullptr, nullptr };
        gemm_multi<<<GG, 256, SMEM_BYTES>>>(ja, jb, jc, 3, NA);
    }
    cudaEventRecord(evRes, 0);

    // ---- s2: wb gated GEMM ----
    cudaStreamWaitEvent(s2, evRes, 0);
    {
        GemmJob ja = { ft_wb, W_rel_wb, out, nullptr, res_w_author,
                       nullptr, nullptr, nullptr, nullptr, nullptr, nullptr };
        gemm_multi<<<GG, 256, SMEM_BYTES, s2>>>(ja, jz, jz, 1, NA);
    }
    cudaEventRecord(evS2, s2);

    // ---- main: fused rf_w + rf_c + semantic attention + gated residual ----
    cudaStreamWaitEvent(0, evG0, 0);
    cudaStreamWaitEvent(0, evG2, 0);
    gemm_rf_fused<<<GG, 256, FUSE_SMEM>>>(ft_w, W_rel_writes, ft_c, W_rel_cites,
                                          npscore, attn_macro, res_w_paper,
                                          out + (size_t)NA * KD, NP);

    // ---- join s2 ----
    cudaStreamWaitEvent(0, evS2, 0);
    join_k<<<1, 1>>>();
}

// round 13
// speedup vs baseline: 1.1789x; 1.0160x over previous
#include <cuda_runtime.h>
#include <cstdint>
#include <math.h>

// ---------------- problem constants ----------------
#define NA 50000
#define NP 50000
#define EDG 400000
#define KH 8
#define DH 32
#define KD 256
#define SLOPE 0.2f

// GEMM tiling: block 128(M) x 256(N), 8 warps (2m x 4n), warp tile 64x64, BK=16 (tf32)
#define BM 128
#define BK 16
#define NKT (KD / BK)      // 16
#define LDK 20
#define LDBN 264
#define ASZ (128 * LDK)
#define BSZ (BK * LDBN)
#define SMEM_BYTES ((2 * ASZ + 2 * BSZ) * 4)     // 54272
#define RFLD 260
#define FUSE_SMEM (SMEM_BYTES + 128 * RFLD * 4)  // 187392

#define NTOT 150000
#define NBLK3 ((NTOT + 255) / 256)     // 586

// ---------------- device scratch ----------------
__device__ float g_PA[NA * KD];
__device__ float g_PP[NP * KD];

__device__ float g_elA_aA[NA * KH];
__device__ float g_erP_aA[NP * KH];
__device__ float g_elP_aP[NP * KH];
__device__ float g_erA_aP[NA * KH];
__device__ float g_erP_aP[NP * KH];

__device__ float g_ft_w[NP * KD];
__device__ float g_ft_wb[NA * KD];
__device__ float g_ft_c[NP * KD];

__device__ float g_npscore[NP * KH];

// CSR scratch (combined)
__device__ int g_counts[NTOT];
__device__ int g_cursor[NTOT];
__device__ int g_offsets[NTOT + 1];
__device__ int g_partials[NBLK3 + 2];
__device__ int g_ssort[3 * EDG];

// ---------------- helpers ----------------
__device__ __forceinline__ float leaky(float v) {
    return v > 0.f ? v : SLOPE * v;
}
__device__ __forceinline__ uint32_t f2tf32(float f) {
    uint32_t r;
    asm("cvt.rna.tf32.f32 %0, %1;" : "=r"(r) : "f"(f));
    return r;
}
__device__ __forceinline__ void mma_tf32(float c[4], uint32_t a0, uint32_t a1,
                                         uint32_t a2, uint32_t a3,
                                         uint32_t b0, uint32_t b1) {
    asm volatile(
        "mma.sync.aligned.m16n8k8.row.col.f32.tf32.tf32.f32 "
        "{%0,%1,%2,%3}, {%4,%5,%6,%7}, {%8,%9}, {%0,%1,%2,%3};"
        : "+f"(c[0]), "+f"(c[1]), "+f"(c[2]), "+f"(c[3])
        : "r"(a0), "r"(a1), "r"(a2), "r"(a3), "r"(b0), "r"(b1));
}

struct GemmJob {
    const float* A;
    const float* B;
    float*       C;        // nullable
    const float* bias;
    const float* gate;
    const float* av0; float* ao0;
    const float* av1; float* ao1;
    const float* av2; float* ao2;
};

// shared mainloop machinery as macros (keeps all kernels consistent)
#define GEMM_PROLOGUE() \
    const int tid = threadIdx.x; \
    const int lane = tid & 31; \
    const int wid = tid >> 5; \
    const int wm = (wid & 1) * 64; \
    const int wn = (wid >> 1) * 64; \
    const int m0 = blockIdx.x * BM; \
    const int qr = lane >> 2; \
    const int qc = lane & 3; \
    const int am = tid >> 1; \
    const int aq = (tid & 1) * 8; \
    const int bkr = tid >> 4; \
    const int bnc = (tid & 15) * 16; \
    float4 rA[2], rB[4]; \
    auto g_load = [&](int kt, const float* __restrict__ A, const float* __restrict__ B) { \
        const int k0 = kt * BK; \
        int row = m0 + am; \
        if (row < M) { \
            rA[0] = *(const float4*)&A[(size_t)row * KD + k0 + aq]; \
            rA[1] = *(const float4*)&A[(size_t)row * KD + k0 + aq + 4]; \
        } else { \
            rA[0] = make_float4(0.f, 0.f, 0.f, 0.f); \
            rA[1] = rA[0]; \
        } \
        const float* bp = &B[(size_t)(k0 + bkr) * KD + bnc]; \
        rB[0] = *(const float4*)&bp[0]; \
        rB[1] = *(const float4*)&bp[4]; \
        rB[2] = *(const float4*)&bp[8]; \
        rB[3] = *(const float4*)&bp[12]; \
    }; \
    auto s_store = [&](int buf) { \
        uint32_t* as = &smem[buf * ASZ + am * LDK + aq]; \
        uint4 v0, v1; \
        v0.x = f2tf32(rA[0].x); v0.y = f2tf32(rA[0].y); \
        v0.z = f2tf32(rA[0].z); v0.w = f2tf32(rA[0].w); \
        v1.x = f2tf32(rA[1].x); v1.y = f2tf32(rA[1].y); \
        v1.z = f2tf32(rA[1].z); v1.w = f2tf32(rA[1].w); \
        *(uint4*)&as[0] = v0; \
        *(uint4*)&as[4] = v1; \
        uint32_t* bs = &smem[2 * ASZ + buf * BSZ + bkr * LDBN + bnc]; \
        _Pragma("unroll") \
        for (int q = 0; q < 4; q++) { \
            uint4 w; \
            w.x = f2tf32(((const float*)&rB[q])[0]); \
            w.y = f2tf32(((const float*)&rB[q])[1]); \
            w.z = f2tf32(((const float*)&rB[q])[2]); \
            w.w = f2tf32(((const float*)&rB[q])[3]); \
            *(uint4*)&bs[q * 4] = w; \
        } \
    };

#define GEMM_MAINLOOP(Aptr, Bptr) \
    { \
        float (*accp)[8][4] = acc; \
        g_load(0, Aptr, Bptr); \
        s_store(0); \
        __syncthreads(); \
        for (int kt = 0; kt < NKT; kt++) { \
            const int cur = kt & 1; \
            if (kt + 1 < NKT) g_load(kt + 1, Aptr, Bptr); \
            const uint32_t* asb = &smem[cur * ASZ]; \
            const uint32_t* bsb = &smem[2 * ASZ + cur * BSZ]; \
            _Pragma("unroll") \
            for (int ks = 0; ks < BK; ks += 8) { \
                uint32_t a[4][4], b[8][2]; \
                _Pragma("unroll") \
                for (int mi = 0; mi < 4; mi++) { \
                    int r0 = wm + mi * 16 + qr; \
                    a[mi][0] = asb[r0 * LDK + ks + qc]; \
                    a[mi][1] = asb[(r0 + 8) * LDK + ks + qc]; \
                    a[mi][2] = asb[r0 * LDK + ks + qc + 4]; \
                    a[mi][3] = asb[(r0 + 8) * LDK + ks + qc + 4]; \
                } \
                _Pragma("unroll") \
                for (int ni = 0; ni < 8; ni++) { \
                    int c0 = wn + ni * 8 + qr; \
                    b[ni][0] = bsb[(ks + qc) * LDBN + c0]; \
                    b[ni][1] = bsb[(ks + qc + 4) * LDBN + c0]; \
                } \
                _Pragma("unroll") \
                for (int mi = 0; mi < 4; mi++) \
                    _Pragma("unroll") \
                    for (int ni = 0; ni < 8; ni++) \
                        mma_tf32(accp[mi][ni], a[mi][0], a[mi][1], a[mi][2], a[mi][3], \
                                 b[ni][0], b[ni][1]); \
            } \
            if (kt + 1 < NKT) { \
                s_store(1 - cur); \
                __syncthreads(); \
            } \
        } \
    }

#define ACC_ZERO() \
    _Pragma("unroll") \
    for (int mi = 0; mi < 4; mi++) \
        _Pragma("unroll") \
        for (int ni = 0; ni < 8; ni++) \
            _Pragma("unroll") \
            for (int r = 0; r < 4; r++) acc[mi][ni][r] = 0.f;

// ================= multi-job tf32 GEMM =================
__global__ void __launch_bounds__(256, 1) gemm_multi(
    GemmJob j0, GemmJob j1, GemmJob j2, int nb, int M)
{
    extern __shared__ uint32_t smem[];
    GEMM_PROLOGUE();

#pragma unroll
    for (int o = 0; o < 3; o++) {
        if (o >= nb) break;
        const GemmJob J = (o == 0) ? j0 : (o == 1) ? j1 : j2;

        float acc[4][8][4];
        ACC_ZERO();
        GEMM_MAINLOOP(J.A, J.B);

        if (J.av0) {
            const float* avs[3] = { J.av0, J.av1, J.av2 };
            float*       aos[3] = { J.ao0, J.ao1, J.ao2 };
            const int h0 = wn >> 5;
#pragma unroll
            for (int t = 0; t < 3; t++) {
                const float* av = avs[t];
                if (!av) break;
                float* ao = aos[t];
                float c0[8], c1[8];
#pragma unroll
                for (int ni = 0; ni < 8; ni++) {
                    int col = wn + ni * 8 + qc * 2;
                    int idx = (col >> 5) * 64 + (col & 31);
                    c0[ni] = av[idx];
                    c1[ni] = av[idx + 1];
                }
#pragma unroll
                for (int mi = 0; mi < 4; mi++) {
#pragma unroll
                    for (int half = 0; half < 2; half++) {
                        float pa = 0.f, pb = 0.f;
#pragma unroll
                        for (int ni = 0; ni < 4; ni++)
                            pa += acc[mi][ni][half * 2] * c0[ni]
                                + acc[mi][ni][half * 2 + 1] * c1[ni];
#pragma unroll
                        for (int ni = 4; ni < 8; ni++)
                            pb += acc[mi][ni][half * 2] * c0[ni]
                                + acc[mi][ni][half * 2 + 1] * c1[ni];
                        pa += __shfl_xor_sync(0xffffffffu, pa, 1);
                        pa += __shfl_xor_sync(0xffffffffu, pa, 2);
                        pb += __shfl_xor_sync(0xffffffffu, pb, 1);
                        pb += __shfl_xor_sync(0xffffffffu, pb, 2);
                        int row = m0 + wm + mi * 16 + qr + half * 8;
                        if (qc == 0 && row < M) {
                            ao[row * KH + h0]     = pa;
                            ao[row * KH + h0 + 1] = pb;
                        }
                    }
                }
            }
        }

        if (J.C) {
            float g = 0.f;
            if (J.gate) g = 1.f / (1.f + __expf(-J.gate[0]));
#pragma unroll
            for (int mi = 0; mi < 4; mi++) {
#pragma unroll
                for (int half = 0; half < 2; half++) {
                    int row = m0 + wm + mi * 16 + qr + half * 8;
                    if (row >= M) continue;
                    float* dst = &J.C[(size_t)row * KD + wn];
#pragma unroll
                    for (int ni = 0; ni < 8; ni++) {
                        int col = ni * 8 + qc * 2;
                        float2 v;
                        v.x = acc[mi][ni][half * 2 + 0];
                        v.y = acc[mi][ni][half * 2 + 1];
                        if (J.bias) {
                            v.x += J.bias[wn + col + 0];
                            v.y += J.bias[wn + col + 1];
                        }
                        if (J.gate) {
                            float2 prev = *(const float2*)&dst[col];
                            v.x = g * v.x + (1.f - g) * prev.x;
                            v.y = g * v.y + (1.f - g) * prev.y;
                        }
                        *(float2*)&dst[col] = v;
                    }
                }
            }
        }
        __syncthreads();
    }
}

// ================= fused rf_w + rf_c + semantic attention + gated residual =================
__global__ void __launch_bounds__(256, 1) gemm_rf_fused(
    const float* __restrict__ Aw, const float* __restrict__ Bw,
    const float* __restrict__ Ac, const float* __restrict__ Bc,
    const float* __restrict__ npscore, const float* __restrict__ attnM,
    const float* __restrict__ resw, float* __restrict__ outP, int M)
{
    extern __shared__ uint32_t smem[];
    float* rfbuf = (float*)(smem + 2 * ASZ + 2 * BSZ);
    GEMM_PROLOGUE();

#pragma unroll
    for (int o = 0; o < 2; o++) {
        const float* A = (o == 0) ? Aw : Ac;
        const float* B = (o == 0) ? Bw : Bc;

        float acc[4][8][4];
        ACC_ZERO();
        GEMM_MAINLOOP(A, B);

        if (o == 0) {
#pragma unroll
            for (int mi = 0; mi < 4; mi++)
#pragma unroll
                for (int half = 0; half < 2; half++) {
                    int lr = wm + mi * 16 + qr + half * 8;
                    float* dst = &rfbuf[lr * RFLD + wn];
#pragma unroll
                    for (int ni = 0; ni < 8; ni++) {
                        int col = ni * 8 + qc * 2;
                        dst[col]     = acc[mi][ni][half * 2 + 0];
                        dst[col + 1] = acc[mi][ni][half * 2 + 1];
                    }
                }
            __syncthreads();
            continue;
        }

        const float g = 1.f / (1.f + __expf(-resw[0]));
        const int h0 = wn >> 5;
        float cr0[8], cr1[8];
#pragma unroll
        for (int ni = 0; ni < 8; ni++) {
            int col = wn + ni * 8 + qc * 2;
            int base = (col >> 5) * 64 + (col & 31);
            cr0[ni] = attnM[base + 32];
            cr1[ni] = attnM[base + 33];
        }

#pragma unroll
        for (int mi = 0; mi < 4; mi++) {
#pragma unroll
            for (int half = 0; half < 2; half++) {
                int lr = wm + mi * 16 + qr + half * 8;
                int row = m0 + lr;
                if (row >= M) continue;
                const float* rwrow = &rfbuf[lr * RFLD + wn];
                float* orow = &outP[(size_t)row * KD + wn];
                float npa = npscore[row * KH + h0];
                float npb = npscore[row * KH + h0 + 1];

                float swa = 0.f, sca = 0.f, swb = 0.f, scb = 0.f;
#pragma unroll
                for (int ni = 0; ni < 8; ni++) {
                    int col = ni * 8 + qc * 2;
                    float rw0 = rwrow[col], rw1 = rwrow[col + 1];
                    float rc0 = acc[mi][ni][half * 2], rc1 = acc[mi][ni][half * 2 + 1];
                    float wpart = rw0 * cr0[ni] + rw1 * cr1[ni];
                    float cpart = rc0 * cr0[ni] + rc1 * cr1[ni];
                    if (ni < 4) { swa += wpart; sca += cpart; }
                    else        { swb += wpart; scb += cpart; }
                }
                swa += __shfl_xor_sync(0xffffffffu, swa, 1);
                swa += __shfl_xor_sync(0xffffffffu, swa, 2);
                sca += __shfl_xor_sync(0xffffffffu, sca, 1);
                sca += __shfl_xor_sync(0xffffffffu, sca, 2);
                swb += __shfl_xor_sync(0xffffffffu, swb, 1);
                swb += __shfl_xor_sync(0xffffffffu, swb, 2);
                scb += __shfl_xor_sync(0xffffffffu, scb, 1);
                scb += __shfl_xor_sync(0xffffffffu, scb, 2);

                float swA = leaky(npa + swa), scA = leaky(npa + sca);
                float swB = leaky(npb + swb), scB = leaky(npb + scb);
                float ma = fmaxf(swA, scA);
                float ea = __expf(swA - ma), eca = __expf(scA - ma);
                float awa = ea / (ea + eca);
                float mb = fmaxf(swB, scB);
                float eb = __expf(swB - mb), ecb = __expf(scB - mb);
                float awb = eb / (eb + ecb);

#pragma unroll
                for (int ni = 0; ni < 8; ni++) {
                    int col = ni * 8 + qc * 2;
                    float aw = (ni < 4) ? awa : awb;
                    float rw0 = rwrow[col], rw1 = rwrow[col + 1];
                    float rc0 = acc[mi][ni][half * 2], rc1 = acc[mi][ni][half * 2 + 1];
                    float2 prev = *(const float2*)&orow[col];
                    float2 v;
                    v.x = g * (aw * rw0 + (1.f - aw) * rc0) + (1.f - g) * prev.x;
                    v.y = g * (aw * rw1 + (1.f - aw) * rc1) + (1.f - g) * prev.y;
                    *(float2*)&orow[col] = v;
                }
            }
        }
    }
}

// ================= fused author: res_author (smem) + wb GEMM + gated blend =================
__global__ void __launch_bounds__(256, 1) gemm_author_fused(
    const float* __restrict__ Ares, const float* __restrict__ Bres,
    const float* __restrict__ bias,
    const float* __restrict__ Awb, const float* __restrict__ Bwb,
    const float* __restrict__ gate, float* __restrict__ outA, int M)
{
    extern __shared__ uint32_t smem[];
    float* rfbuf = (float*)(smem + 2 * ASZ + 2 * BSZ);
    GEMM_PROLOGUE();

#pragma unroll
    for (int o = 0; o < 2; o++) {
        const float* A = (o == 0) ? Ares : Awb;
        const float* B = (o == 0) ? Bres : Bwb;

        float acc[4][8][4];
        ACC_ZERO();
        GEMM_MAINLOOP(A, B);

        if (o == 0) {
            // stash residual (+bias) in smem; no global write
#pragma unroll
            for (int mi = 0; mi < 4; mi++)
#pragma unroll
                for (int half = 0; half < 2; half++) {
                    int lr = wm + mi * 16 + qr + half * 8;
                    float* dst = &rfbuf[lr * RFLD + wn];
#pragma unroll
                    for (int ni = 0; ni < 8; ni++) {
                        int col = ni * 8 + qc * 2;
                        dst[col]     = acc[mi][ni][half * 2 + 0] + bias[wn + col + 0];
                        dst[col + 1] = acc[mi][ni][half * 2 + 1] + bias[wn + col + 1];
                    }
                }
            __syncthreads();
            continue;
        }

        const float g = 1.f / (1.f + __expf(-gate[0]));
#pragma unroll
        for (int mi = 0; mi < 4; mi++) {
#pragma unroll
            for (int half = 0; half < 2; half++) {
                int lr = wm + mi * 16 + qr + half * 8;
                int row = m0 + lr;
                if (row >= M) continue;
                const float* resrow = &rfbuf[lr * RFLD + wn];
                float* orow = &outA[(size_t)row * KD + wn];
#pragma unroll
                for (int ni = 0; ni < 8; ni++) {
                    int col = ni * 8 + qc * 2;
                    float2 v;
                    v.x = g * acc[mi][ni][half * 2 + 0] + (1.f - g) * resrow[col];
                    v.y = g * acc[mi][ni][half * 2 + 1] + (1.f - g) * resrow[col + 1];
                    *(float2*)&orow[col] = v;
                }
            }
        }
    }
}

// trailing join node
__global__ void join_k() {}

// ---------------- batched CSR build ----------------
__global__ void csr_hist3(const int* __restrict__ d0, const int* __restrict__ d1,
                          const int* __restrict__ d2, int* __restrict__ counts)
{
    int e = blockIdx.x * blockDim.x + threadIdx.x;
    if (e >= EDG) return;
    atomicAdd(&counts[d0[e]], 1);
    atomicAdd(&counts[50000 + d1[e]], 1);
    atomicAdd(&counts[100000 + d2[e]], 1);
}

__global__ void scan_block(const int* __restrict__ in, int* __restrict__ out,
                           int* __restrict__ partials, int n)
{
    __shared__ int wsum[8];
    int i = blockIdx.x * 256 + threadIdx.x;
    int lane = threadIdx.x & 31, wid = threadIdx.x >> 5;
    int v = (i < n) ? in[i] : 0;
    int x = v;
#pragma unroll
    for (int o = 1; o < 32; o <<= 1) {
        int t = __shfl_up_sync(0xffffffffu, x, o);
        if (lane >= o) x += t;
    }
    if (lane == 31) wsum[wid] = x;
    __syncthreads();
    if (wid == 0) {
        int w = (lane < 8) ? wsum[lane] : 0;
#pragma unroll
        for (int o = 1; o < 8; o <<= 1) {
            int t = __shfl_up_sync(0xffffffffu, w, o);
            if (lane >= o) w += t;
        }
        if (lane < 8) wsum[lane] = w;
    }
    __syncthreads();
    int wpre = (wid > 0) ? wsum[wid - 1] : 0;
    if (i < n) out[i] = wpre + x - v;
    if (threadIdx.x == 0) partials[blockIdx.x] = wsum[7];
}

__global__ void scan_top1k(int* __restrict__ partials, int nb)
{
    __shared__ int wsum[32];
    int i = threadIdx.x;
    int lane = i & 31, wid = i >> 5;
    int v = (i < nb) ? partials[i] : 0;
    int x = v;
#pragma unroll
    for (int o = 1; o < 32; o <<= 1) {
        int t = __shfl_up_sync(0xffffffffu, x, o);
        if (lane >= o) x += t;
    }
    if (lane == 31) wsum[wid] = x;
    __syncthreads();
    if (wid == 0) {
        int w = wsum[lane];
#pragma unroll
        for (int o = 1; o < 32; o <<= 1) {
            int t = __shfl_up_sync(0xffffffffu, w, o);
            if (lane >= o) w += t;
        }
        wsum[lane] = w;
    }
    __syncthreads();
    int wpre = (wid > 0) ? wsum[wid - 1] : 0;
    if (i < nb) partials[i] = wpre + x - v;
    if (i == 0) partials[nb] = wsum[31];
}

__global__ void scan_add(int* __restrict__ offsets, const int* __restrict__ partials, int n)
{
    int i = blockIdx.x * 256 + threadIdx.x;
    if (i < n) offsets[i] += partials[blockIdx.x];
    if (i == 0) offsets[n] = partials[gridDim.x];
}

__global__ void csr_scatter3(
    const int* __restrict__ s0, const int* __restrict__ d0,
    const int* __restrict__ s1, const int* __restrict__ d1,
    const int* __restrict__ s2p, const int* __restrict__ d2,
    const int* __restrict__ offsets, int* __restrict__ cursor,
    int* __restrict__ ssort)
{
    int idx = blockIdx.x * blockDim.x + threadIdx.x;
    if (idx >= 3 * EDG) return;
    int r = (idx >= 2 * EDG) ? 2 : (idx >= EDG) ? 1 : 0;
    int e = idx - r * EDG;
    const int* src = (r == 0) ? s0 : (r == 1) ? s1 : s2p;
    const int* dst = (r == 0) ? d0 : (r == 1) ? d1 : d2;
    int key = r * 50000 + dst[e];
    int pos = offsets[key] + atomicAdd(&cursor[key], 1);
    ssort[pos] = src[e];
}

// ---------------- fused micro gather (max-free softmax) ----------------
__global__ void micro_gather(const int* __restrict__ ssort, const int* __restrict__ offsets,
                             const float* __restrict__ el, const float* __restrict__ er,
                             const float* __restrict__ Psrc, float* __restrict__ ft, int n_dst)
{
    int d = (blockIdx.x * blockDim.x + threadIdx.x) >> 5;
    int lane = threadIdx.x & 31;
    if (d >= n_dst) return;
    int beg = offsets[d], end = offsets[d + 1];
    float* dstp = &ft[(size_t)d * KD + lane * 8];
    if (beg == end) {
        float4 z = make_float4(0.f, 0.f, 0.f, 0.f);
        *(float4*)dstp = z;
        *(float4*)(dstp + 4) = z;
        return;
    }
    float erh = (lane < KH) ? er[d * KH + lane] : 0.f;

    const int hk = lane >> 2;
    float acc[8] = {0.f, 0.f, 0.f, 0.f, 0.f, 0.f, 0.f, 0.f};
    float se = 0.f;
    int i = beg;
    for (; i + 2 <= end; i += 2) {
        int s0 = ssort[i], s1 = ssort[i + 1];
        float w0 = 0.f, w1 = 0.f;
        if (lane < KH) {
            w0 = __expf(leaky(el[s0 * KH + lane] + erh));
            w1 = __expf(leaky(el[s1 * KH + lane] + erh));
            se += w0 + w1;
        }
        float wk0 = __shfl_sync(0xffffffffu, w0, hk);
        float wk1 = __shfl_sync(0xffffffffu, w1, hk);
        const float4* p0 = (const float4*)&Psrc[(size_t)s0 * KD + lane * 8];
        const float4* p1 = (const float4*)&Psrc[(size_t)s1 * KD + lane * 8];
        float4 a0 = p0[0], a1 = p0[1], b0 = p1[0], b1 = p1[1];
        acc[0] = fmaf(wk0, a0.x, acc[0]); acc[0] = fmaf(wk1, b0.x, acc[0]);
        acc[1] = fmaf(wk0, a0.y, acc[1]); acc[1] = fmaf(wk1, b0.y, acc[1]);
        acc[2] = fmaf(wk0, a0.z, acc[2]); acc[2] = fmaf(wk1, b0.z, acc[2]);
        acc[3] = fmaf(wk0, a0.w, acc[3]); acc[3] = fmaf(wk1, b0.w, acc[3]);
        acc[4] = fmaf(wk0, a1.x, acc[4]); acc[4] = fmaf(wk1, b1.x, acc[4]);
        acc[5] = fmaf(wk0, a1.y, acc[5]); acc[5] = fmaf(wk1, b1.y, acc[5]);
        acc[6] = fmaf(wk0, a1.z, acc[6]); acc[6] = fmaf(wk1, b1.z, acc[6]);
        acc[7] = fmaf(wk0, a1.w, acc[7]); acc[7] = fmaf(wk1, b1.w, acc[7]);
    }
    if (i < end) {
        int s0 = ssort[i];
        float w0 = 0.f;
        if (lane < KH) {
            w0 = __expf(leaky(el[s0 * KH + lane] + erh));
            se += w0;
        }
        float wk0 = __shfl_sync(0xffffffffu, w0, hk);
        const float4* p0 = (const float4*)&Psrc[(size_t)s0 * KD + lane * 8];
        float4 a0 = p0[0], a1 = p0[1];
        acc[0] = fmaf(wk0, a0.x, acc[0]);
        acc[1] = fmaf(wk0, a0.y, acc[1]);
        acc[2] = fmaf(wk0, a0.z, acc[2]);
        acc[3] = fmaf(wk0, a0.w, acc[3]);
        acc[4] = fmaf(wk0, a1.x, acc[4]);
        acc[5] = fmaf(wk0, a1.y, acc[5]);
        acc[6] = fmaf(wk0, a1.z, acc[6]);
        acc[7] = fmaf(wk0, a1.w, acc[7]);
    }
    float inv = 1.f / __shfl_sync(0xffffffffu, se, hk);
    float4 o0, o1;
    o0.x = fmaxf(acc[0] * inv, 0.f);
    o0.y = fmaxf(acc[1] * inv, 0.f);
    o0.z = fmaxf(acc[2] * inv, 0.f);
    o0.w = fmaxf(acc[3] * inv, 0.f);
    o1.x = fmaxf(acc[4] * inv, 0.f);
    o1.y = fmaxf(acc[5] * inv, 0.f);
    o1.z = fmaxf(acc[6] * inv, 0.f);
    o1.w = fmaxf(acc[7] * inv, 0.f);
    *(float4*)dstp = o0;
    *(float4*)(dstp + 4) = o1;
}

// ---------------- launch ----------------
extern "C" void kernel_launch(void* const* d_in, const int* in_sizes, int n_in,
                              void* d_out, int out_size)
{
    const float* feats_author    = (const float*)d_in[0];
    const float* feats_paper     = (const float*)d_in[1];
    const float* W_micro_author  = (const float*)d_in[2];
    const float* W_micro_paper   = (const float*)d_in[3];
    const float* attn_micro_a    = (const float*)d_in[4];
    const float* attn_micro_p    = (const float*)d_in[5];
    const float* W_macro_node_p  = (const float*)d_in[7];
    const float* W_rel_writes    = (const float*)d_in[8];
    const float* W_rel_wb        = (const float*)d_in[9];
    const float* W_rel_cites     = (const float*)d_in[10];
    const float* attn_macro      = (const float*)d_in[11];
    const float* W_res_author    = (const float*)d_in[12];
    const float* b_res_author    = (const float*)d_in[13];
    const float* W_res_paper     = (const float*)d_in[14];
    const float* b_res_paper     = (const float*)d_in[15];
    const float* res_w_author    = (const float*)d_in[16];
    const float* res_w_paper     = (const float*)d_in[17];
    const int*   writes_src      = (const int*)d_in[18];
    const int*   writes_dst      = (const int*)d_in[19];
    const int*   wb_src          = (const int*)d_in[20];
    const int*   wb_dst          = (const int*)d_in[21];
    const int*   cites_src       = (const int*)d_in[22];
    const int*   cites_dst       = (const int*)d_in[23];
    float* out = (float*)d_out;

    float *PA, *PP, *elA_aA, *erP_aA, *elP_aP, *erA_aP, *erP_aP;
    float *ft_w, *ft_wb, *ft_c, *npscore;
    int *counts, *cursor, *offsets, *partials, *ssort;
    cudaGetSymbolAddress((void**)&PA, g_PA);
    cudaGetSymbolAddress((void**)&PP, g_PP);
    cudaGetSymbolAddress((void**)&elA_aA, g_elA_aA);
    cudaGetSymbolAddress((void**)&erP_aA, g_erP_aA);
    cudaGetSymbolAddress((void**)&elP_aP, g_elP_aP);
    cudaGetSymbolAddress((void**)&erA_aP, g_erA_aP);
    cudaGetSymbolAddress((void**)&erP_aP, g_erP_aP);
    cudaGetSymbolAddress((void**)&ft_w, g_ft_w);
    cudaGetSymbolAddress((void**)&ft_wb, g_ft_wb);
    cudaGetSymbolAddress((void**)&ft_c, g_ft_c);
    cudaGetSymbolAddress((void**)&npscore, g_npscore);
    cudaGetSymbolAddress((void**)&counts, g_counts);
    cudaGetSymbolAddress((void**)&cursor, g_cursor);
    cudaGetSymbolAddress((void**)&offsets, g_offsets);
    cudaGetSymbolAddress((void**)&partials, g_partials);
    cudaGetSymbolAddress((void**)&ssort, g_ssort);

    static cudaStream_t s2 = nullptr;
    static cudaEvent_t evFork = nullptr, evA = nullptr, evP = nullptr,
                       ev2 = nullptr, evS2 = nullptr;
    if (!s2) {
        cudaStreamCreateWithFlags(&s2, cudaStreamNonBlocking);
        cudaEventCreateWithFlags(&evFork, cudaEventDisableTiming);
        cudaEventCreateWithFlags(&evA, cudaEventDisableTiming);
        cudaEventCreateWithFlags(&evP, cudaEventDisableTiming);
        cudaEventCreateWithFlags(&ev2, cudaEventDisableTiming);
        cudaEventCreateWithFlags(&evS2, cudaEventDisableTiming);
    }

    cudaFuncSetAttribute(gemm_multi, cudaFuncAttributeMaxDynamicSharedMemorySize, SMEM_BYTES);
    cudaFuncSetAttribute(gemm_rf_fused, cudaFuncAttributeMaxDynamicSharedMemorySize, FUSE_SMEM);
    cudaFuncSetAttribute(gemm_author_fused, cudaFuncAttributeMaxDynamicSharedMemorySize, FUSE_SMEM);

    const int GG = (NA + BM - 1) / BM;          // 391
    const int EB = (EDG + 255) / 256;
    const int EB3 = (3 * EDG + 255) / 256;
    const int GB = (NA * 32 + 255) / 256;

    GemmJob jz = {};

    // ---- fork: s2 runs batched CSR build ----
    cudaEventRecord(evFork, 0);
    cudaStreamWaitEvent(s2, evFork, 0);
    cudaMemsetAsync(counts, 0, NTOT * sizeof(int), s2);
    cudaMemsetAsync(cursor, 0, NTOT * sizeof(int), s2);
    csr_hist3<<<EB, 256, 0, s2>>>(writes_dst, wb_dst, cites_dst, counts);
    scan_block<<<NBLK3, 256, 0, s2>>>(counts, offsets, partials, NTOT);
    scan_top1k<<<1, 1024, 0, s2>>>(partials, NBLK3);
    scan_add<<<NBLK3, 256, 0, s2>>>(offsets, partials, NTOT);
    csr_scatter3<<<EB3, 256, 0, s2>>>(writes_src, writes_dst, wb_src, wb_dst,
                                      cites_src, cites_dst, offsets, cursor, ssort);

    // ---- main: author micro GEMM (+fused attn dots) ----
    {
        GemmJob ja = { feats_author, W_micro_author, PA, nullptr, nullptr,
                       attn_micro_a + 0,  elA_aA,
                       attn_micro_p + 32, erA_aP,
                       nullptr, nullptr };
        gemm_multi<<<GG, 256, SMEM_BYTES>>>(ja, jz, jz, 1, NA);
    }
    cudaEventRecord(evA, 0);

    // ---- s2: paper micro GEMM (+3 fused attn dots) ----
    {
        GemmJob ja = { feats_paper, W_micro_paper, PP, nullptr, nullptr,
                       attn_micro_a + 32, erP_aA,
                       attn_micro_p + 0,  elP_aP,
                       attn_micro_p + 32, erP_aP };
        gemm_multi<<<GG, 256, SMEM_BYTES, s2>>>(ja, jz, jz, 1, NP);
    }
    cudaEventRecord(evP, s2);

    // ---- s2: gather cites, then gather writes (needs author micro) ----
    micro_gather<<<GB, 256, 0, s2>>>(ssort, offsets + 2 * 50000,
                                     elP_aP, erP_aP, PP, ft_c, NP);
    cudaStreamWaitEvent(s2, evA, 0);
    micro_gather<<<GB, 256, 0, s2>>>(ssort, offsets + 0 * 50000,
                                     elA_aA, erP_aA, PA, ft_w, NP);

    // ---- main: 2-job GEMM (npscore via fused dot, res_paper -> out[NA:]) ----
    {
        GemmJob ja = { feats_paper, W_macro_node_p, nullptr, nullptr, nullptr,
                       attn_macro + 0, npscore,
                       nullptr, nullptr, nullptr, nullptr };
        GemmJob jb = { feats_paper, W_res_paper, out + (size_t)NA * KD, b_res_paper, nullptr,
                       nullptr, nullptr, nullptr, nullptr, nullptr, nullptr };
        gemm_multi<<<GG, 256, SMEM_BYTES>>>(ja, jb, jz, 2, NP);
    }
    cudaEventRecord(ev2, 0);

    // ---- main: gather written_by (needs CSR + elP from s2 micro; evP covers both) ----
    cudaStreamWaitEvent(0, evP, 0);
    micro_gather<<<GB, 256, 0, 0>>>(ssort, offsets + 1 * 50000,
                                    elP_aP, erA_aP, PP, ft_wb, NA);

    // ---- main: fused author (res_author in smem + wb GEMM + gated blend) -> out[:NA] ----
    gemm_author_fused<<<GG, 256, FUSE_SMEM>>>(feats_author, W_res_author, b_res_author,
                                              ft_wb, W_rel_wb, res_w_author, out, NA);

    // ---- s2: fused rf_w + rf_c + semantic attention + gated residual -> out[NA:] ----
    cudaStreamWaitEvent(s2, ev2, 0);   // npscore + res_paper ready
    gemm_rf_fused<<<GG, 256, FUSE_SMEM, s2>>>(ft_w, W_rel_writes, ft_c, W_rel_cites,
                                              npscore, attn_macro, res_w_paper,
                                              out + (size_t)NA * KD, NP);
    cudaEventRecord(evS2, s2);

    // ---- join ----
    cudaStreamWaitEvent(0, evS2, 0);
    join_k<<<1, 1>>>();
}

// round 14
// speedup vs baseline: 1.2313x; 1.0445x over previous
#include <cuda_runtime.h>
#include <cuda_fp16.h>
#include <cstdint>
#include <math.h>

// ---------------- problem constants ----------------
#define NA 50000
#define NP 50000
#define EDG 400000
#define KH 8
#define DH 32
#define KD 256
#define SLOPE 0.2f

// GEMM tiling: block 128(M) x 256(N), 8 warps, warp tile 64x64, BK=16 (tf32)
#define BM 128
#define BK 16
#define NKT (KD / BK)
#define LDK 20
#define LDBN 264
#define ASZ (128 * LDK)
#define BSZ (BK * LDBN)
#define SMEM_BYTES ((2 * ASZ + 2 * BSZ) * 4)     // 54272
#define RFLD 260
#define FUSE_SMEM (SMEM_BYTES + 128 * RFLD * 4)  // 187392

#define NTOT 150000
#define NBLK3 ((NTOT + 255) / 256)     // 586

// ---------------- device scratch ----------------
__device__ __half g_PA[NA * KD];       // fp16 projections (gather traffic halved)
__device__ __half g_PP[NP * KD];

__device__ float g_elA_aA[NA * KH];
__device__ float g_erP_aA[NP * KH];
__device__ float g_elP_aP[NP * KH];
__device__ float g_erA_aP[NA * KH];
__device__ float g_erP_aP[NP * KH];

__device__ float g_ft_w[NP * KD];
__device__ float g_ft_wb[NA * KD];
__device__ float g_ft_c[NP * KD];

__device__ float g_npscore[NP * KH];

// CSR scratch (combined)
__device__ int g_counts[NTOT];
__device__ int g_cursor[NTOT];
__device__ int g_offsets[NTOT + 1];
__device__ int g_partials[NBLK3 + 2];
__device__ int g_ssort[3 * EDG];

// ---------------- helpers ----------------
__device__ __forceinline__ float leaky(float v) {
    return v > 0.f ? v : SLOPE * v;
}
__device__ __forceinline__ uint32_t f2tf32(float f) {
    uint32_t r;
    asm("cvt.rna.tf32.f32 %0, %1;" : "=r"(r) : "f"(f));
    return r;
}
__device__ __forceinline__ void mma_tf32(float c[4], uint32_t a0, uint32_t a1,
                                         uint32_t a2, uint32_t a3,
                                         uint32_t b0, uint32_t b1) {
    asm volatile(
        "mma.sync.aligned.m16n8k8.row.col.f32.tf32.tf32.f32 "
        "{%0,%1,%2,%3}, {%4,%5,%6,%7}, {%8,%9}, {%0,%1,%2,%3};"
        : "+f"(c[0]), "+f"(c[1]), "+f"(c[2]), "+f"(c[3])
        : "r"(a0), "r"(a1), "r"(a2), "r"(a3), "r"(b0), "r"(b1));
}

struct GemmJob {
    const float* A;
    const float* B;
    float*       C;        // nullable
    __half*      Ch;       // nullable: fp16 C output (micro projections)
    const float* bias;
    const float* gate;
    const float* av0; float* ao0;
    const float* av1; float* ao1;
    const float* av2; float* ao2;
};

#define GEMM_PROLOGUE() \
    const int tid = threadIdx.x; \
    const int lane = tid & 31; \
    const int wid = tid >> 5; \
    const int wm = (wid & 1) * 64; \
    const int wn = (wid >> 1) * 64; \
    const int m0 = blockIdx.x * BM; \
    const int qr = lane >> 2; \
    const int qc = lane & 3; \
    const int am = tid >> 1; \
    const int aq = (tid & 1) * 8; \
    const int bkr = tid >> 4; \
    const int bnc = (tid & 15) * 16; \
    float4 rA[2], rB[4]; \
    auto g_load = [&](int kt, const float* __restrict__ A, const float* __restrict__ B) { \
        const int k0 = kt * BK; \
        int row = m0 + am; \
        if (row < M) { \
            rA[0] = *(const float4*)&A[(size_t)row * KD + k0 + aq]; \
            rA[1] = *(const float4*)&A[(size_t)row * KD + k0 + aq + 4]; \
        } else { \
            rA[0] = make_float4(0.f, 0.f, 0.f, 0.f); \
            rA[1] = rA[0]; \
        } \
        const float* bp = &B[(size_t)(k0 + bkr) * KD + bnc]; \
        rB[0] = *(const float4*)&bp[0]; \
        rB[1] = *(const float4*)&bp[4]; \
        rB[2] = *(const float4*)&bp[8]; \
        rB[3] = *(const float4*)&bp[12]; \
    }; \
    auto s_store = [&](int buf) { \
        uint32_t* as = &smem[buf * ASZ + am * LDK + aq]; \
        uint4 v0, v1; \
        v0.x = f2tf32(rA[0].x); v0.y = f2tf32(rA[0].y); \
        v0.z = f2tf32(rA[0].z); v0.w = f2tf32(rA[0].w); \
        v1.x = f2tf32(rA[1].x); v1.y = f2tf32(rA[1].y); \
        v1.z = f2tf32(rA[1].z); v1.w = f2tf32(rA[1].w); \
        *(uint4*)&as[0] = v0; \
        *(uint4*)&as[4] = v1; \
        uint32_t* bs = &smem[2 * ASZ + buf * BSZ + bkr * LDBN + bnc]; \
        _Pragma("unroll") \
        for (int q = 0; q < 4; q++) { \
            uint4 w; \
            w.x = f2tf32(((const float*)&rB[q])[0]); \
            w.y = f2tf32(((const float*)&rB[q])[1]); \
            w.z = f2tf32(((const float*)&rB[q])[2]); \
            w.w = f2tf32(((const float*)&rB[q])[3]); \
            *(uint4*)&bs[q * 4] = w; \
        } \
    };

#define GEMM_MAINLOOP(Aptr, Bptr) \
    { \
        float (*accp)[8][4] = acc; \
        g_load(0, Aptr, Bptr); \
        s_store(0); \
        __syncthreads(); \
        for (int kt = 0; kt < NKT; kt++) { \
            const int cur = kt & 1; \
            if (kt + 1 < NKT) g_load(kt + 1, Aptr, Bptr); \
            const uint32_t* asb = &smem[cur * ASZ]; \
            const uint32_t* bsb = &smem[2 * ASZ + cur * BSZ]; \
            _Pragma("unroll") \
            for (int ks = 0; ks < BK; ks += 8) { \
                uint32_t a[4][4], b[8][2]; \
                _Pragma("unroll") \
                for (int mi = 0; mi < 4; mi++) { \
                    int r0 = wm + mi * 16 + qr; \
                    a[mi][0] = asb[r0 * LDK + ks + qc]; \
                    a[mi][1] = asb[(r0 + 8) * LDK + ks + qc]; \
                    a[mi][2] = asb[r0 * LDK + ks + qc + 4]; \
                    a[mi][3] = asb[(r0 + 8) * LDK + ks + qc + 4]; \
                } \
                _Pragma("unroll") \
                for (int ni = 0; ni < 8; ni++) { \
                    int c0 = wn + ni * 8 + qr; \
                    b[ni][0] = bsb[(ks + qc) * LDBN + c0]; \
                    b[ni][1] = bsb[(ks + qc + 4) * LDBN + c0]; \
                } \
                _Pragma("unroll") \
                for (int mi = 0; mi < 4; mi++) \
                    _Pragma("unroll") \
                    for (int ni = 0; ni < 8; ni++) \
                        mma_tf32(accp[mi][ni], a[mi][0], a[mi][1], a[mi][2], a[mi][3], \
                                 b[ni][0], b[ni][1]); \
            } \
            if (kt + 1 < NKT) { \
                s_store(1 - cur); \
                __syncthreads(); \
            } \
        } \
    }

#define ACC_ZERO() \
    _Pragma("unroll") \
    for (int mi = 0; mi < 4; mi++) \
        _Pragma("unroll") \
        for (int ni = 0; ni < 8; ni++) \
            _Pragma("unroll") \
            for (int r = 0; r < 4; r++) acc[mi][ni][r] = 0.f;

// ================= multi-job tf32 GEMM =================
__global__ void __launch_bounds__(256, 1) gemm_multi(
    GemmJob j0, GemmJob j1, GemmJob j2, int nb, int M)
{
    extern __shared__ uint32_t smem[];
    GEMM_PROLOGUE();

#pragma unroll
    for (int o = 0; o < 3; o++) {
        if (o >= nb) break;
        const GemmJob J = (o == 0) ? j0 : (o == 1) ? j1 : j2;

        float acc[4][8][4];
        ACC_ZERO();
        GEMM_MAINLOOP(J.A, J.B);

        if (J.av0) {
            const float* avs[3] = { J.av0, J.av1, J.av2 };
            float*       aos[3] = { J.ao0, J.ao1, J.ao2 };
            const int h0 = wn >> 5;
#pragma unroll
            for (int t = 0; t < 3; t++) {
                const float* av = avs[t];
                if (!av) break;
                float* ao = aos[t];
                float c0[8], c1[8];
#pragma unroll
                for (int ni = 0; ni < 8; ni++) {
                    int col = wn + ni * 8 + qc * 2;
                    int idx = (col >> 5) * 64 + (col & 31);
                    c0[ni] = av[idx];
                    c1[ni] = av[idx + 1];
                }
#pragma unroll
                for (int mi = 0; mi < 4; mi++) {
#pragma unroll
                    for (int half = 0; half < 2; half++) {
                        float pa = 0.f, pb = 0.f;
#pragma unroll
                        for (int ni = 0; ni < 4; ni++)
                            pa += acc[mi][ni][half * 2] * c0[ni]
                                + acc[mi][ni][half * 2 + 1] * c1[ni];
#pragma unroll
                        for (int ni = 4; ni < 8; ni++)
                            pb += acc[mi][ni][half * 2] * c0[ni]
                                + acc[mi][ni][half * 2 + 1] * c1[ni];
                        pa += __shfl_xor_sync(0xffffffffu, pa, 1);
                        pa += __shfl_xor_sync(0xffffffffu, pa, 2);
                        pb += __shfl_xor_sync(0xffffffffu, pb, 1);
                        pb += __shfl_xor_sync(0xffffffffu, pb, 2);
                        int row = m0 + wm + mi * 16 + qr + half * 8;
                        if (qc == 0 && row < M) {
                            ao[row * KH + h0]     = pa;
                            ao[row * KH + h0 + 1] = pb;
                        }
                    }
                }
            }
        }

        if (J.Ch) {
            // fp16 output (micro projections)
#pragma unroll
            for (int mi = 0; mi < 4; mi++) {
#pragma unroll
                for (int half = 0; half < 2; half++) {
                    int row = m0 + wm + mi * 16 + qr + half * 8;
                    if (row >= M) continue;
                    __half* dst = &J.Ch[(size_t)row * KD + wn];
#pragma unroll
                    for (int ni = 0; ni < 8; ni++) {
                        int col = ni * 8 + qc * 2;
                        *(__half2*)&dst[col] = __floats2half2_rn(
                            acc[mi][ni][half * 2 + 0], acc[mi][ni][half * 2 + 1]);
                    }
                }
            }
        } else if (J.C) {
            float g = 0.f;
            if (J.gate) g = 1.f / (1.f + __expf(-J.gate[0]));
#pragma unroll
            for (int mi = 0; mi < 4; mi++) {
#pragma unroll
                for (int half = 0; half < 2; half++) {
                    int row = m0 + wm + mi * 16 + qr + half * 8;
                    if (row >= M) continue;
                    float* dst = &J.C[(size_t)row * KD + wn];
#pragma unroll
                    for (int ni = 0; ni < 8; ni++) {
                        int col = ni * 8 + qc * 2;
                        float2 v;
                        v.x = acc[mi][ni][half * 2 + 0];
                        v.y = acc[mi][ni][half * 2 + 1];
                        if (J.bias) {
                            v.x += J.bias[wn + col + 0];
                            v.y += J.bias[wn + col + 1];
                        }
                        if (J.gate) {
                            float2 prev = *(const float2*)&dst[col];
                            v.x = g * v.x + (1.f - g) * prev.x;
                            v.y = g * v.y + (1.f - g) * prev.y;
                        }
                        *(float2*)&dst[col] = v;
                    }
                }
            }
        }
        __syncthreads();
    }
}

// ================= fused rf_w + rf_c + semantic attention + gated residual =================
__global__ void __launch_bounds__(256, 1) gemm_rf_fused(
    const float* __restrict__ Aw, const float* __restrict__ Bw,
    const float* __restrict__ Ac, const float* __restrict__ Bc,
    const float* __restrict__ npscore, const float* __restrict__ attnM,
    const float* __restrict__ resw, float* __restrict__ outP, int M)
{
    extern __shared__ uint32_t smem[];
    float* rfbuf = (float*)(smem + 2 * ASZ + 2 * BSZ);
    GEMM_PROLOGUE();

#pragma unroll
    for (int o = 0; o < 2; o++) {
        const float* A = (o == 0) ? Aw : Ac;
        const float* B = (o == 0) ? Bw : Bc;

        float acc[4][8][4];
        ACC_ZERO();
        GEMM_MAINLOOP(A, B);

        if (o == 0) {
#pragma unroll
            for (int mi = 0; mi < 4; mi++)
#pragma unroll
                for (int half = 0; half < 2; half++) {
                    int lr = wm + mi * 16 + qr + half * 8;
                    float* dst = &rfbuf[lr * RFLD + wn];
#pragma unroll
                    for (int ni = 0; ni < 8; ni++) {
                        int col = ni * 8 + qc * 2;
                        dst[col]     = acc[mi][ni][half * 2 + 0];
                        dst[col + 1] = acc[mi][ni][half * 2 + 1];
                    }
                }
            __syncthreads();
            continue;
        }

        const float g = 1.f / (1.f + __expf(-resw[0]));
        const int h0 = wn >> 5;
        float cr0[8], cr1[8];
#pragma unroll
        for (int ni = 0; ni < 8; ni++) {
            int col = wn + ni * 8 + qc * 2;
            int base = (col >> 5) * 64 + (col & 31);
            cr0[ni] = attnM[base + 32];
            cr1[ni] = attnM[base + 33];
        }

#pragma unroll
        for (int mi = 0; mi < 4; mi++) {
#pragma unroll
            for (int half = 0; half < 2; half++) {
                int lr = wm + mi * 16 + qr + half * 8;
                int row = m0 + lr;
                if (row >= M) continue;
                const float* rwrow = &rfbuf[lr * RFLD + wn];
                float* orow = &outP[(size_t)row * KD + wn];
                float npa = npscore[row * KH + h0];
                float npb = npscore[row * KH + h0 + 1];

                float swa = 0.f, sca = 0.f, swb = 0.f, scb = 0.f;
#pragma unroll
                for (int ni = 0; ni < 8; ni++) {
                    int col = ni * 8 + qc * 2;
                    float rw0 = rwrow[col], rw1 = rwrow[col + 1];
                    float rc0 = acc[mi][ni][half * 2], rc1 = acc[mi][ni][half * 2 + 1];
                    float wpart = rw0 * cr0[ni] + rw1 * cr1[ni];
                    float cpart = rc0 * cr0[ni] + rc1 * cr1[ni];
                    if (ni < 4) { swa += wpart; sca += cpart; }
                    else        { swb += wpart; scb += cpart; }
                }
                swa += __shfl_xor_sync(0xffffffffu, swa, 1);
                swa += __shfl_xor_sync(0xffffffffu, swa, 2);
                sca += __shfl_xor_sync(0xffffffffu, sca, 1);
                sca += __shfl_xor_sync(0xffffffffu, sca, 2);
                swb += __shfl_xor_sync(0xffffffffu, swb, 1);
                swb += __shfl_xor_sync(0xffffffffu, swb, 2);
                scb += __shfl_xor_sync(0xffffffffu, scb, 1);
                scb += __shfl_xor_sync(0xffffffffu, scb, 2);

                float swA = leaky(npa + swa), scA = leaky(npa + sca);
                float swB = leaky(npb + swb), scB = leaky(npb + scb);
                float ma = fmaxf(swA, scA);
                float ea = __expf(swA - ma), eca = __expf(scA - ma);
                float awa = ea / (ea + eca);
                float mb = fmaxf(swB, scB);
                float eb = __expf(swB - mb), ecb = __expf(scB - mb);
                float awb = eb / (eb + ecb);

#pragma unroll
                for (int ni = 0; ni < 8; ni++) {
                    int col = ni * 8 + qc * 2;
                    float aw = (ni < 4) ? awa : awb;
                    float rw0 = rwrow[col], rw1 = rwrow[col + 1];
                    float rc0 = acc[mi][ni][half * 2], rc1 = acc[mi][ni][half * 2 + 1];
                    float2 prev = *(const float2*)&orow[col];
                    float2 v;
                    v.x = g * (aw * rw0 + (1.f - aw) * rc0) + (1.f - g) * prev.x;
                    v.y = g * (aw * rw1 + (1.f - aw) * rc1) + (1.f - g) * prev.y;
                    *(float2*)&orow[col] = v;
                }
            }
        }
    }
}

// ================= fused author: res_author (smem) + wb GEMM + gated blend =================
__global__ void __launch_bounds__(256, 1) gemm_author_fused(
    const float* __restrict__ Ares, const float* __restrict__ Bres,
    const float* __restrict__ bias,
    const float* __restrict__ Awb, const float* __restrict__ Bwb,
    const float* __restrict__ gate, float* __restrict__ outA, int M)
{
    extern __shared__ uint32_t smem[];
    float* rfbuf = (float*)(smem + 2 * ASZ + 2 * BSZ);
    GEMM_PROLOGUE();

#pragma unroll
    for (int o = 0; o < 2; o++) {
        const float* A = (o == 0) ? Ares : Awb;
        const float* B = (o == 0) ? Bres : Bwb;

        float acc[4][8][4];
        ACC_ZERO();
        GEMM_MAINLOOP(A, B);

        if (o == 0) {
#pragma unroll
            for (int mi = 0; mi < 4; mi++)
#pragma unroll
                for (int half = 0; half < 2; half++) {
                    int lr = wm + mi * 16 + qr + half * 8;
                    float* dst = &rfbuf[lr * RFLD + wn];
#pragma unroll
                    for (int ni = 0; ni < 8; ni++) {
                        int col = ni * 8 + qc * 2;
                        dst[col]     = acc[mi][ni][half * 2 + 0] + bias[wn + col + 0];
                        dst[col + 1] = acc[mi][ni][half * 2 + 1] + bias[wn + col + 1];
                    }
                }
            __syncthreads();
            continue;
        }

        const float g = 1.f / (1.f + __expf(-gate[0]));
#pragma unroll
        for (int mi = 0; mi < 4; mi++) {
#pragma unroll
            for (int half = 0; half < 2; half++) {
                int lr = wm + mi * 16 + qr + half * 8;
                int row = m0 + lr;
                if (row >= M) continue;
                const float* resrow = &rfbuf[lr * RFLD + wn];
                float* orow = &outA[(size_t)row * KD + wn];
#pragma unroll
                for (int ni = 0; ni < 8; ni++) {
                    int col = ni * 8 + qc * 2;
                    float2 v;
                    v.x = g * acc[mi][ni][half * 2 + 0] + (1.f - g) * resrow[col];
                    v.y = g * acc[mi][ni][half * 2 + 1] + (1.f - g) * resrow[col + 1];
                    *(float2*)&orow[col] = v;
                }
            }
        }
    }
}

// trailing join node
__global__ void join_k() {}

// ---------------- batched CSR build ----------------
__global__ void csr_hist3(const int* __restrict__ d0, const int* __restrict__ d1,
                          const int* __restrict__ d2, int* __restrict__ counts)
{
    int e = blockIdx.x * blockDim.x + threadIdx.x;
    if (e >= EDG) return;
    atomicAdd(&counts[d0[e]], 1);
    atomicAdd(&counts[50000 + d1[e]], 1);
    atomicAdd(&counts[100000 + d2[e]], 1);
}

__global__ void scan_block(const int* __restrict__ in, int* __restrict__ out,
                           int* __restrict__ partials, int n)
{
    __shared__ int wsum[8];
    int i = blockIdx.x * 256 + threadIdx.x;
    int lane = threadIdx.x & 31, wid = threadIdx.x >> 5;
    int v = (i < n) ? in[i] : 0;
    int x = v;
#pragma unroll
    for (int o = 1; o < 32; o <<= 1) {
        int t = __shfl_up_sync(0xffffffffu, x, o);
        if (lane >= o) x += t;
    }
    if (lane == 31) wsum[wid] = x;
    __syncthreads();
    if (wid == 0) {
        int w = (lane < 8) ? wsum[lane] : 0;
#pragma unroll
        for (int o = 1; o < 8; o <<= 1) {
            int t = __shfl_up_sync(0xffffffffu, w, o);
            if (lane >= o) w += t;
        }
        if (lane < 8) wsum[lane] = w;
    }
    __syncthreads();
    int wpre = (wid > 0) ? wsum[wid - 1] : 0;
    if (i < n) out[i] = wpre + x - v;
    if (threadIdx.x == 0) partials[blockIdx.x] = wsum[7];
}

__global__ void scan_top1k(int* __restrict__ partials, int nb)
{
    __shared__ int wsum[32];
    int i = threadIdx.x;
    int lane = i & 31, wid = i >> 5;
    int v = (i < nb) ? partials[i] : 0;
    int x = v;
#pragma unroll
    for (int o = 1; o < 32; o <<= 1) {
        int t = __shfl_up_sync(0xffffffffu, x, o);
        if (lane >= o) x += t;
    }
    if (lane == 31) wsum[wid] = x;
    __syncthreads();
    if (wid == 0) {
        int w = wsum[lane];
#pragma unroll
        for (int o = 1; o < 32; o <<= 1) {
            int t = __shfl_up_sync(0xffffffffu, w, o);
            if (lane >= o) w += t;
        }
        wsum[lane] = w;
    }
    __syncthreads();
    int wpre = (wid > 0) ? wsum[wid - 1] : 0;
    if (i < nb) partials[i] = wpre + x - v;
    if (i == 0) partials[nb] = wsum[31];
}

__global__ void scan_add(int* __restrict__ offsets, const int* __restrict__ partials, int n)
{
    int i = blockIdx.x * 256 + threadIdx.x;
    if (i < n) offsets[i] += partials[blockIdx.x];
    if (i == 0) offsets[n] = partials[gridDim.x];
}

__global__ void csr_scatter3(
    const int* __restrict__ s0, const int* __restrict__ d0,
    const int* __restrict__ s1, const int* __restrict__ d1,
    const int* __restrict__ s2p, const int* __restrict__ d2,
    const int* __restrict__ offsets, int* __restrict__ cursor,
    int* __restrict__ ssort)
{
    int idx = blockIdx.x * blockDim.x + threadIdx.x;
    if (idx >= 3 * EDG) return;
    int r = (idx >= 2 * EDG) ? 2 : (idx >= EDG) ? 1 : 0;
    int e = idx - r * EDG;
    const int* src = (r == 0) ? s0 : (r == 1) ? s1 : s2p;
    const int* dst = (r == 0) ? d0 : (r == 1) ? d1 : d2;
    int key = r * 50000 + dst[e];
    int pos = offsets[key] + atomicAdd(&cursor[key], 1);
    ssort[pos] = src[e];
}

// ---------------- fused micro gather (fp16 Psrc, max-free softmax) ----------------
__global__ void micro_gather(const int* __restrict__ ssort, const int* __restrict__ offsets,
                             const float* __restrict__ el, const float* __restrict__ er,
                             const __half* __restrict__ Psrc, float* __restrict__ ft, int n_dst)
{
    int d = (blockIdx.x * blockDim.x + threadIdx.x) >> 5;
    int lane = threadIdx.x & 31;
    if (d >= n_dst) return;
    int beg = offsets[d], end = offsets[d + 1];
    float* dstp = &ft[(size_t)d * KD + lane * 8];
    if (beg == end) {
        float4 z = make_float4(0.f, 0.f, 0.f, 0.f);
        *(float4*)dstp = z;
        *(float4*)(dstp + 4) = z;
        return;
    }
    float erh = (lane < KH) ? er[d * KH + lane] : 0.f;

    const int hk = lane >> 2;
    float acc[8] = {0.f, 0.f, 0.f, 0.f, 0.f, 0.f, 0.f, 0.f};
    float se = 0.f;
    int i = beg;
    for (; i + 2 <= end; i += 2) {
        int s0 = ssort[i], s1 = ssort[i + 1];
        float w0 = 0.f, w1 = 0.f;
        if (lane < KH) {
            w0 = __expf(leaky(el[s0 * KH + lane] + erh));
            w1 = __expf(leaky(el[s1 * KH + lane] + erh));
            se += w0 + w1;
        }
        float wk0 = __shfl_sync(0xffffffffu, w0, hk);
        float wk1 = __shfl_sync(0xffffffffu, w1, hk);
        // 8 halves = 16 bytes per edge row slice
        float4 raw0 = *(const float4*)&Psrc[(size_t)s0 * KD + lane * 8];
        float4 raw1 = *(const float4*)&Psrc[(size_t)s1 * KD + lane * 8];
        const __half2* h0 = (const __half2*)&raw0;
        const __half2* h1 = (const __half2*)&raw1;
#pragma unroll
        for (int q = 0; q < 4; q++) {
            float2 f0 = __half22float2(h0[q]);
            float2 f1 = __half22float2(h1[q]);
            acc[q * 2 + 0] = fmaf(wk0, f0.x, acc[q * 2 + 0]);
            acc[q * 2 + 0] = fmaf(wk1, f1.x, acc[q * 2 + 0]);
            acc[q * 2 + 1] = fmaf(wk0, f0.y, acc[q * 2 + 1]);
            acc[q * 2 + 1] = fmaf(wk1, f1.y, acc[q * 2 + 1]);
        }
    }
    if (i < end) {
        int s0 = ssort[i];
        float w0 = 0.f;
        if (lane < KH) {
            w0 = __expf(leaky(el[s0 * KH + lane] + erh));
            se += w0;
        }
        float wk0 = __shfl_sync(0xffffffffu, w0, hk);
        float4 raw0 = *(const float4*)&Psrc[(size_t)s0 * KD + lane * 8];
        const __half2* h0 = (const __half2*)&raw0;
#pragma unroll
        for (int q = 0; q < 4; q++) {
            float2 f0 = __half22float2(h0[q]);
            acc[q * 2 + 0] = fmaf(wk0, f0.x, acc[q * 2 + 0]);
            acc[q * 2 + 1] = fmaf(wk0, f0.y, acc[q * 2 + 1]);
        }
    }
    float inv = 1.f / __shfl_sync(0xffffffffu, se, hk);
    float4 o0, o1;
    o0.x = fmaxf(acc[0] * inv, 0.f);
    o0.y = fmaxf(acc[1] * inv, 0.f);
    o0.z = fmaxf(acc[2] * inv, 0.f);
    o0.w = fmaxf(acc[3] * inv, 0.f);
    o1.x = fmaxf(acc[4] * inv, 0.f);
    o1.y = fmaxf(acc[5] * inv, 0.f);
    o1.z = fmaxf(acc[6] * inv, 0.f);
    o1.w = fmaxf(acc[7] * inv, 0.f);
    *(float4*)dstp = o0;
    *(float4*)(dstp + 4) = o1;
}

// ---------------- launch ----------------
extern "C" void kernel_launch(void* const* d_in, const int* in_sizes, int n_in,
                              void* d_out, int out_size)
{
    const float* feats_author    = (const float*)d_in[0];
    const float* feats_paper     = (const float*)d_in[1];
    const float* W_micro_author  = (const float*)d_in[2];
    const float* W_micro_paper   = (const float*)d_in[3];
    const float* attn_micro_a    = (const float*)d_in[4];
    const float* attn_micro_p    = (const float*)d_in[5];
    const float* W_macro_node_p  = (const float*)d_in[7];
    const float* W_rel_writes    = (const float*)d_in[8];
    const float* W_rel_wb        = (const float*)d_in[9];
    const float* W_rel_cites     = (const float*)d_in[10];
    const float* attn_macro      = (const float*)d_in[11];
    const float* W_res_author    = (const float*)d_in[12];
    const float* b_res_author    = (const float*)d_in[13];
    const float* W_res_paper     = (const float*)d_in[14];
    const float* b_res_paper     = (const float*)d_in[15];
    const float* res_w_author    = (const float*)d_in[16];
    const float* res_w_paper     = (const float*)d_in[17];
    const int*   writes_src      = (const int*)d_in[18];
    const int*   writes_dst      = (const int*)d_in[19];
    const int*   wb_src          = (const int*)d_in[20];
    const int*   wb_dst          = (const int*)d_in[21];
    const int*   cites_src       = (const int*)d_in[22];
    const int*   cites_dst       = (const int*)d_in[23];
    float* out = (float*)d_out;

    __half *PA, *PP;
    float *elA_aA, *erP_aA, *elP_aP, *erA_aP, *erP_aP;
    float *ft_w, *ft_wb, *ft_c, *npscore;
    int *counts, *cursor, *offsets, *partials, *ssort;
    cudaGetSymbolAddress((void**)&PA, g_PA);
    cudaGetSymbolAddress((void**)&PP, g_PP);
    cudaGetSymbolAddress((void**)&elA_aA, g_elA_aA);
    cudaGetSymbolAddress((void**)&erP_aA, g_erP_aA);
    cudaGetSymbolAddress((void**)&elP_aP, g_elP_aP);
    cudaGetSymbolAddress((void**)&erA_aP, g_erA_aP);
    cudaGetSymbolAddress((void**)&erP_aP, g_erP_aP);
    cudaGetSymbolAddress((void**)&ft_w, g_ft_w);
    cudaGetSymbolAddress((void**)&ft_wb, g_ft_wb);
    cudaGetSymbolAddress((void**)&ft_c, g_ft_c);
    cudaGetSymbolAddress((void**)&npscore, g_npscore);
    cudaGetSymbolAddress((void**)&counts, g_counts);
    cudaGetSymbolAddress((void**)&cursor, g_cursor);
    cudaGetSymbolAddress((void**)&offsets, g_offsets);
    cudaGetSymbolAddress((void**)&partials, g_partials);
    cudaGetSymbolAddress((void**)&ssort, g_ssort);

    static cudaStream_t s2 = nullptr;
    static cudaEvent_t evFork = nullptr, evA = nullptr, evP = nullptr,
                       ev2 = nullptr, evS2 = nullptr;
    if (!s2) {
        cudaStreamCreateWithFlags(&s2, cudaStreamNonBlocking);
        cudaEventCreateWithFlags(&evFork, cudaEventDisableTiming);
        cudaEventCreateWithFlags(&evA, cudaEventDisableTiming);
        cudaEventCreateWithFlags(&evP, cudaEventDisableTiming);
        cudaEventCreateWithFlags(&ev2, cudaEventDisableTiming);
        cudaEventCreateWithFlags(&evS2, cudaEventDisableTiming);
    }

    cudaFuncSetAttribute(gemm_multi, cudaFuncAttributeMaxDynamicSharedMemorySize, SMEM_BYTES);
    cudaFuncSetAttribute(gemm_rf_fused, cudaFuncAttributeMaxDynamicSharedMemorySize, FUSE_SMEM);
    cudaFuncSetAttribute(gemm_author_fused, cudaFuncAttributeMaxDynamicSharedMemorySize, FUSE_SMEM);

    const int GG = (NA + BM - 1) / BM;
    const int EB = (EDG + 255) / 256;
    const int EB3 = (3 * EDG + 255) / 256;
    const int GB = (NA * 32 + 255) / 256;

    GemmJob jz = {};

    // ---- fork: s2 runs batched CSR build ----
    cudaEventRecord(evFork, 0);
    cudaStreamWaitEvent(s2, evFork, 0);
    cudaMemsetAsync(counts, 0, NTOT * sizeof(int), s2);
    cudaMemsetAsync(cursor, 0, NTOT * sizeof(int), s2);
    csr_hist3<<<EB, 256, 0, s2>>>(writes_dst, wb_dst, cites_dst, counts);
    scan_block<<<NBLK3, 256, 0, s2>>>(counts, offsets, partials, NTOT);
    scan_top1k<<<1, 1024, 0, s2>>>(partials, NBLK3);
    scan_add<<<NBLK3, 256, 0, s2>>>(offsets, partials, NTOT);
    csr_scatter3<<<EB3, 256, 0, s2>>>(writes_src, writes_dst, wb_src, wb_dst,
                                      cites_src, cites_dst, offsets, cursor, ssort);

    // ---- main: author micro GEMM -> fp16 PA (+fused attn dots) ----
    {
        GemmJob ja = { feats_author, W_micro_author, nullptr, PA, nullptr, nullptr,
                       attn_micro_a + 0,  elA_aA,
                       attn_micro_p + 32, erA_aP,
                       nullptr, nullptr };
        gemm_multi<<<GG, 256, SMEM_BYTES>>>(ja, jz, jz, 1, NA);
    }
    cudaEventRecord(evA, 0);

    // ---- s2: paper micro GEMM -> fp16 PP (+3 fused attn dots) ----
    {
        GemmJob ja = { feats_paper, W_micro_paper, nullptr, PP, nullptr, nullptr,
                       attn_micro_a + 32, erP_aA,
                       attn_micro_p + 0,  elP_aP,
                       attn_micro_p + 32, erP_aP };
        gemm_multi<<<GG, 256, SMEM_BYTES, s2>>>(ja, jz, jz, 1, NP);
    }
    cudaEventRecord(evP, s2);

    // ---- s2: gather cites, then gather writes ----
    micro_gather<<<GB, 256, 0, s2>>>(ssort, offsets + 2 * 50000,
                                     elP_aP, erP_aP, PP, ft_c, NP);
    cudaStreamWaitEvent(s2, evA, 0);
    micro_gather<<<GB, 256, 0, s2>>>(ssort, offsets + 0 * 50000,
                                     elA_aA, erP_aA, PA, ft_w, NP);

    // ---- main: 2-job GEMM (npscore fused dot, res_paper -> out[NA:]) ----
    {
        GemmJob ja = { feats_paper, W_macro_node_p, nullptr, nullptr, nullptr, nullptr,
                       attn_macro + 0, npscore,
                       nullptr, nullptr, nullptr, nullptr };
        GemmJob jb = { feats_paper, W_res_paper, out + (size_t)NA * KD, nullptr,
                       b_res_paper, nullptr,
                       nullptr, nullptr, nullptr, nullptr, nullptr, nullptr };
        gemm_multi<<<GG, 256, SMEM_BYTES>>>(ja, jb, jz, 2, NP);
    }
    cudaEventRecord(ev2, 0);

    // ---- main: gather written_by ----
    cudaStreamWaitEvent(0, evP, 0);
    micro_gather<<<GB, 256, 0, 0>>>(ssort, offsets + 1 * 50000,
                                    elP_aP, erA_aP, PP, ft_wb, NA);

    // ---- main: fused author -> out[:NA] ----
    gemm_author_fused<<<GG, 256, FUSE_SMEM>>>(feats_author, W_res_author, b_res_author,
                                              ft_wb, W_rel_wb, res_w_author, out, NA);

    // ---- s2: fused rf + semantic attention + gated residual -> out[NA:] ----
    cudaStreamWaitEvent(s2, ev2, 0);
    gemm_rf_fused<<<GG, 256, FUSE_SMEM, s2>>>(ft_w, W_rel_writes, ft_c, W_rel_cites,
                                              npscore, attn_macro, res_w_paper,
                                              out + (size_t)NA * KD, NP);
    cudaEventRecord(evS2, s2);

    // ---- join ----
    cudaStreamWaitEvent(0, evS2, 0);
    join_k<<<1, 1>>>();
}

// round 15
// speedup vs baseline: 1.2321x; 1.0007x over previous
#include <cuda_runtime.h>
#include <cuda_fp16.h>
#include <cstdint>
#include <math.h>

// ---------------- problem constants ----------------
#define NA 50000
#define NP 50000
#define EDG 400000
#define KH 8
#define DH 32
#define KD 256
#define SLOPE 0.2f

// GEMM tiling: block 128(M) x 256(N), 8 warps, warp tile 64x64, BK=16 (tf32)
#define BM 128
#define BK 16
#define NKT (KD / BK)
#define LDK 20
#define LDBN 264
#define ASZ (128 * LDK)
#define BSZ (BK * LDBN)
#define SMEM_BYTES ((2 * ASZ + 2 * BSZ) * 4)     // 54272
#define RFLD 260
#define FUSE_SMEM (SMEM_BYTES + 128 * RFLD * 4)  // 187392

#define NTOT 150000
#define NBLK3 ((NTOT + 255) / 256)     // 586

// ---------------- device scratch ----------------
__device__ __half g_PA[NA * KD];
__device__ __half g_PP[NP * KD];

__device__ float g_elA_aA[NA * KH];
__device__ float g_erP_aA[NP * KH];
__device__ float g_elP_aP[NP * KH];
__device__ float g_erA_aP[NA * KH];
__device__ float g_erP_aP[NP * KH];

__device__ __half g_ft_w[NP * KD];
__device__ __half g_ft_wb[NA * KD];
__device__ __half g_ft_c[NP * KD];

__device__ float g_npscore[NP * KH];

// CSR scratch (combined)
__device__ int g_counts[NTOT];
__device__ int g_cursor[NTOT];
__device__ int g_offsets[NTOT + 1];
__device__ int g_partials[NBLK3 + 2];
__device__ int g_ssort[3 * EDG];

// ---------------- helpers ----------------
__device__ __forceinline__ float leaky(float v) {
    return v > 0.f ? v : SLOPE * v;
}
__device__ __forceinline__ uint32_t f2tf32(float f) {
    uint32_t r;
    asm("cvt.rna.tf32.f32 %0, %1;" : "=r"(r) : "f"(f));
    return r;
}
__device__ __forceinline__ void mma_tf32(float c[4], uint32_t a0, uint32_t a1,
                                         uint32_t a2, uint32_t a3,
                                         uint32_t b0, uint32_t b1) {
    asm volatile(
        "mma.sync.aligned.m16n8k8.row.col.f32.tf32.tf32.f32 "
        "{%0,%1,%2,%3}, {%4,%5,%6,%7}, {%8,%9}, {%0,%1,%2,%3};"
        : "+f"(c[0]), "+f"(c[1]), "+f"(c[2]), "+f"(c[3])
        : "r"(a0), "r"(a1), "r"(a2), "r"(a3), "r"(b0), "r"(b1));
}

struct GemmJob {
    const float* A;
    const float* B;
    float*       C;        // nullable
    __half*      Ch;       // nullable: fp16 C output
    const float* bias;
    const float* gate;
    const float* av0; float* ao0;
    const float* av1; float* ao1;
    const float* av2; float* ao2;
};

#define GEMM_PROLOGUE() \
    const int tid = threadIdx.x; \
    const int lane = tid & 31; \
    const int wid = tid >> 5; \
    const int wm = (wid & 1) * 64; \
    const int wn = (wid >> 1) * 64; \
    const int m0 = blockIdx.x * BM; \
    const int qr = lane >> 2; \
    const int qc = lane & 3; \
    const int am = tid >> 1; \
    const int aq = (tid & 1) * 8; \
    const int bkr = tid >> 4; \
    const int bnc = (tid & 15) * 16; \
    float4 rA[2], rB[4]; \
    auto g_load = [&](int kt, const float* __restrict__ A, const float* __restrict__ B) { \
        const int k0 = kt * BK; \
        int row = m0 + am; \
        if (row < M) { \
            rA[0] = *(const float4*)&A[(size_t)row * KD + k0 + aq]; \
            rA[1] = *(const float4*)&A[(size_t)row * KD + k0 + aq + 4]; \
        } else { \
            rA[0] = make_float4(0.f, 0.f, 0.f, 0.f); \
            rA[1] = rA[0]; \
        } \
        const float* bp = &B[(size_t)(k0 + bkr) * KD + bnc]; \
        rB[0] = *(const float4*)&bp[0]; \
        rB[1] = *(const float4*)&bp[4]; \
        rB[2] = *(const float4*)&bp[8]; \
        rB[3] = *(const float4*)&bp[12]; \
    }; \
    auto g_load_h = [&](int kt, const __half* __restrict__ Ah, const float* __restrict__ B) { \
        const int k0 = kt * BK; \
        int row = m0 + am; \
        if (row < M) { \
            float4 raw = *(const float4*)&Ah[(size_t)row * KD + k0 + aq]; \
            const __half2* hp = (const __half2*)&raw; \
            float2 f0 = __half22float2(hp[0]); \
            float2 f1 = __half22float2(hp[1]); \
            float2 f2 = __half22float2(hp[2]); \
            float2 f3 = __half22float2(hp[3]); \
            rA[0] = make_float4(f0.x, f0.y, f1.x, f1.y); \
            rA[1] = make_float4(f2.x, f2.y, f3.x, f3.y); \
        } else { \
            rA[0] = make_float4(0.f, 0.f, 0.f, 0.f); \
            rA[1] = rA[0]; \
        } \
        const float* bp = &B[(size_t)(k0 + bkr) * KD + bnc]; \
        rB[0] = *(const float4*)&bp[0]; \
        rB[1] = *(const float4*)&bp[4]; \
        rB[2] = *(const float4*)&bp[8]; \
        rB[3] = *(const float4*)&bp[12]; \
    }; \
    auto s_store = [&](int buf) { \
        uint32_t* as = &smem[buf * ASZ + am * LDK + aq]; \
        uint4 v0, v1; \
        v0.x = f2tf32(rA[0].x); v0.y = f2tf32(rA[0].y); \
        v0.z = f2tf32(rA[0].z); v0.w = f2tf32(rA[0].w); \
        v1.x = f2tf32(rA[1].x); v1.y = f2tf32(rA[1].y); \
        v1.z = f2tf32(rA[1].z); v1.w = f2tf32(rA[1].w); \
        *(uint4*)&as[0] = v0; \
        *(uint4*)&as[4] = v1; \
        uint32_t* bs = &smem[2 * ASZ + buf * BSZ + bkr * LDBN + bnc]; \
        _Pragma("unroll") \
        for (int q = 0; q < 4; q++) { \
            uint4 w; \
            w.x = f2tf32(((const float*)&rB[q])[0]); \
            w.y = f2tf32(((const float*)&rB[q])[1]); \
            w.z = f2tf32(((const float*)&rB[q])[2]); \
            w.w = f2tf32(((const float*)&rB[q])[3]); \
            *(uint4*)&bs[q * 4] = w; \
        } \
    };

#define GEMM_MAINLOOP_GEN(loader, Aptr, Bptr) \
    { \
        float (*accp)[8][4] = acc; \
        loader(0, Aptr, Bptr); \
        s_store(0); \
        __syncthreads(); \
        for (int kt = 0; kt < NKT; kt++) { \
            const int cur = kt & 1; \
            if (kt + 1 < NKT) loader(kt + 1, Aptr, Bptr); \
            const uint32_t* asb = &smem[cur * ASZ]; \
            const uint32_t* bsb = &smem[2 * ASZ + cur * BSZ]; \
            _Pragma("unroll") \
            for (int ks = 0; ks < BK; ks += 8) { \
                uint32_t a[4][4], b[8][2]; \
                _Pragma("unroll") \
                for (int mi = 0; mi < 4; mi++) { \
                    int r0 = wm + mi * 16 + qr; \
                    a[mi][0] = asb[r0 * LDK + ks + qc]; \
                    a[mi][1] = asb[(r0 + 8) * LDK + ks + qc]; \
                    a[mi][2] = asb[r0 * LDK + ks + qc + 4]; \
                    a[mi][3] = asb[(r0 + 8) * LDK + ks + qc + 4]; \
                } \
                _Pragma("unroll") \
                for (int ni = 0; ni < 8; ni++) { \
                    int c0 = wn + ni * 8 + qr; \
                    b[ni][0] = bsb[(ks + qc) * LDBN + c0]; \
                    b[ni][1] = bsb[(ks + qc + 4) * LDBN + c0]; \
                } \
                _Pragma("unroll") \
                for (int mi = 0; mi < 4; mi++) \
                    _Pragma("unroll") \
                    for (int ni = 0; ni < 8; ni++) \
                        mma_tf32(accp[mi][ni], a[mi][0], a[mi][1], a[mi][2], a[mi][3], \
                                 b[ni][0], b[ni][1]); \
            } \
            if (kt + 1 < NKT) { \
                s_store(1 - cur); \
                __syncthreads(); \
            } \
        } \
    }

#define ACC_ZERO() \
    _Pragma("unroll") \
    for (int mi = 0; mi < 4; mi++) \
        _Pragma("unroll") \
        for (int ni = 0; ni < 8; ni++) \
            _Pragma("unroll") \
            for (int r = 0; r < 4; r++) acc[mi][ni][r] = 0.f;

// ================= multi-job tf32 GEMM (fp32 A) =================
__global__ void __launch_bounds__(256, 1) gemm_multi(
    GemmJob j0, GemmJob j1, GemmJob j2, int nb, int M)
{
    extern __shared__ uint32_t smem[];
    GEMM_PROLOGUE();

#pragma unroll
    for (int o = 0; o < 3; o++) {
        if (o >= nb) break;
        const GemmJob J = (o == 0) ? j0 : (o == 1) ? j1 : j2;

        float acc[4][8][4];
        ACC_ZERO();
        GEMM_MAINLOOP_GEN(g_load, J.A, J.B);

        if (J.av0) {
            const float* avs[3] = { J.av0, J.av1, J.av2 };
            float*       aos[3] = { J.ao0, J.ao1, J.ao2 };
            const int h0 = wn >> 5;
#pragma unroll
            for (int t = 0; t < 3; t++) {
                const float* av = avs[t];
                if (!av) break;
                float* ao = aos[t];
                float c0[8], c1[8];
#pragma unroll
                for (int ni = 0; ni < 8; ni++) {
                    int col = wn + ni * 8 + qc * 2;
                    int idx = (col >> 5) * 64 + (col & 31);
                    c0[ni] = av[idx];
                    c1[ni] = av[idx + 1];
                }
#pragma unroll
                for (int mi = 0; mi < 4; mi++) {
#pragma unroll
                    for (int half = 0; half < 2; half++) {
                        float pa = 0.f, pb = 0.f;
#pragma unroll
                        for (int ni = 0; ni < 4; ni++)
                            pa += acc[mi][ni][half * 2] * c0[ni]
                                + acc[mi][ni][half * 2 + 1] * c1[ni];
#pragma unroll
                        for (int ni = 4; ni < 8; ni++)
                            pb += acc[mi][ni][half * 2] * c0[ni]
                                + acc[mi][ni][half * 2 + 1] * c1[ni];
                        pa += __shfl_xor_sync(0xffffffffu, pa, 1);
                        pa += __shfl_xor_sync(0xffffffffu, pa, 2);
                        pb += __shfl_xor_sync(0xffffffffu, pb, 1);
                        pb += __shfl_xor_sync(0xffffffffu, pb, 2);
                        int row = m0 + wm + mi * 16 + qr + half * 8;
                        if (qc == 0 && row < M) {
                            ao[row * KH + h0]     = pa;
                            ao[row * KH + h0 + 1] = pb;
                        }
                    }
                }
            }
        }

        if (J.Ch) {
#pragma unroll
            for (int mi = 0; mi < 4; mi++) {
#pragma unroll
                for (int half = 0; half < 2; half++) {
                    int row = m0 + wm + mi * 16 + qr + half * 8;
                    if (row >= M) continue;
                    __half* dst = &J.Ch[(size_t)row * KD + wn];
#pragma unroll
                    for (int ni = 0; ni < 8; ni++) {
                        int col = ni * 8 + qc * 2;
                        *(__half2*)&dst[col] = __floats2half2_rn(
                            acc[mi][ni][half * 2 + 0], acc[mi][ni][half * 2 + 1]);
                    }
                }
            }
        } else if (J.C) {
            float g = 0.f;
            if (J.gate) g = 1.f / (1.f + __expf(-J.gate[0]));
#pragma unroll
            for (int mi = 0; mi < 4; mi++) {
#pragma unroll
                for (int half = 0; half < 2; half++) {
                    int row = m0 + wm + mi * 16 + qr + half * 8;
                    if (row >= M) continue;
                    float* dst = &J.C[(size_t)row * KD + wn];
#pragma unroll
                    for (int ni = 0; ni < 8; ni++) {
                        int col = ni * 8 + qc * 2;
                        float2 v;
                        v.x = acc[mi][ni][half * 2 + 0];
                        v.y = acc[mi][ni][half * 2 + 1];
                        if (J.bias) {
                            v.x += J.bias[wn + col + 0];
                            v.y += J.bias[wn + col + 1];
                        }
                        if (J.gate) {
                            float2 prev = *(const float2*)&dst[col];
                            v.x = g * v.x + (1.f - g) * prev.x;
                            v.y = g * v.y + (1.f - g) * prev.y;
                        }
                        *(float2*)&dst[col] = v;
                    }
                }
            }
        }
        __syncthreads();
    }
}

// ================= fused rf_w + rf_c (fp16 A) + semantic attention + gated residual =================
__global__ void __launch_bounds__(256, 1) gemm_rf_fused(
    const __half* __restrict__ Aw, const float* __restrict__ Bw,
    const __half* __restrict__ Ac, const float* __restrict__ Bc,
    const float* __restrict__ npscore, const float* __restrict__ attnM,
    const float* __restrict__ resw, float* __restrict__ outP, int M)
{
    extern __shared__ uint32_t smem[];
    float* rfbuf = (float*)(smem + 2 * ASZ + 2 * BSZ);
    GEMM_PROLOGUE();

#pragma unroll
    for (int o = 0; o < 2; o++) {
        const __half* A = (o == 0) ? Aw : Ac;
        const float* B = (o == 0) ? Bw : Bc;

        float acc[4][8][4];
        ACC_ZERO();
        GEMM_MAINLOOP_GEN(g_load_h, A, B);

        if (o == 0) {
#pragma unroll
            for (int mi = 0; mi < 4; mi++)
#pragma unroll
                for (int half = 0; half < 2; half++) {
                    int lr = wm + mi * 16 + qr + half * 8;
                    float* dst = &rfbuf[lr * RFLD + wn];
#pragma unroll
                    for (int ni = 0; ni < 8; ni++) {
                        int col = ni * 8 + qc * 2;
                        dst[col]     = acc[mi][ni][half * 2 + 0];
                        dst[col + 1] = acc[mi][ni][half * 2 + 1];
                    }
                }
            __syncthreads();
            continue;
        }

        const float g = 1.f / (1.f + __expf(-resw[0]));
        const int h0 = wn >> 5;
        float cr0[8], cr1[8];
#pragma unroll
        for (int ni = 0; ni < 8; ni++) {
            int col = wn + ni * 8 + qc * 2;
            int base = (col >> 5) * 64 + (col & 31);
            cr0[ni] = attnM[base + 32];
            cr1[ni] = attnM[base + 33];
        }

#pragma unroll
        for (int mi = 0; mi < 4; mi++) {
#pragma unroll
            for (int half = 0; half < 2; half++) {
                int lr = wm + mi * 16 + qr + half * 8;
                int row = m0 + lr;
                if (row >= M) continue;
                const float* rwrow = &rfbuf[lr * RFLD + wn];
                float* orow = &outP[(size_t)row * KD + wn];
                float npa = npscore[row * KH + h0];
                float npb = npscore[row * KH + h0 + 1];

                float swa = 0.f, sca = 0.f, swb = 0.f, scb = 0.f;
#pragma unroll
                for (int ni = 0; ni < 8; ni++) {
                    int col = ni * 8 + qc * 2;
                    float rw0 = rwrow[col], rw1 = rwrow[col + 1];
                    float rc0 = acc[mi][ni][half * 2], rc1 = acc[mi][ni][half * 2 + 1];
                    float wpart = rw0 * cr0[ni] + rw1 * cr1[ni];
                    float cpart = rc0 * cr0[ni] + rc1 * cr1[ni];
                    if (ni < 4) { swa += wpart; sca += cpart; }
                    else        { swb += wpart; scb += cpart; }
                }
                swa += __shfl_xor_sync(0xffffffffu, swa, 1);
                swa += __shfl_xor_sync(0xffffffffu, swa, 2);
                sca += __shfl_xor_sync(0xffffffffu, sca, 1);
                sca += __shfl_xor_sync(0xffffffffu, sca, 2);
                swb += __shfl_xor_sync(0xffffffffu, swb, 1);
                swb += __shfl_xor_sync(0xffffffffu, swb, 2);
                scb += __shfl_xor_sync(0xffffffffu, scb, 1);
                scb += __shfl_xor_sync(0xffffffffu, scb, 2);

                float swA = leaky(npa + swa), scA = leaky(npa + sca);
                float swB = leaky(npb + swb), scB = leaky(npb + scb);
                float ma = fmaxf(swA, scA);
                float ea = __expf(swA - ma), eca = __expf(scA - ma);
                float awa = ea / (ea + eca);
                float mb = fmaxf(swB, scB);
                float eb = __expf(swB - mb), ecb = __expf(scB - mb);
                float awb = eb / (eb + ecb);

#pragma unroll
                for (int ni = 0; ni < 8; ni++) {
                    int col = ni * 8 + qc * 2;
                    float aw = (ni < 4) ? awa : awb;
                    float rw0 = rwrow[col], rw1 = rwrow[col + 1];
                    float rc0 = acc[mi][ni][half * 2], rc1 = acc[mi][ni][half * 2 + 1];
                    float2 prev = *(const float2*)&orow[col];
                    float2 v;
                    v.x = g * (aw * rw0 + (1.f - aw) * rc0) + (1.f - g) * prev.x;
                    v.y = g * (aw * rw1 + (1.f - aw) * rc1) + (1.f - g) * prev.y;
                    *(float2*)&orow[col] = v;
                }
            }
        }
    }
}

// ================= fused author: res_author fp32 A (smem) + wb GEMM fp16 A + gated blend =================
__global__ void __launch_bounds__(256, 1) gemm_author_fused(
    const float* __restrict__ Ares, const float* __restrict__ Bres,
    const float* __restrict__ bias,
    const __half* __restrict__ Awb, const float* __restrict__ Bwb,
    const float* __restrict__ gate, float* __restrict__ outA, int M)
{
    extern __shared__ uint32_t smem[];
    float* rfbuf = (float*)(smem + 2 * ASZ + 2 * BSZ);
    GEMM_PROLOGUE();

    // job 0: residual (fp32 A)
    {
        float acc[4][8][4];
        ACC_ZERO();
        GEMM_MAINLOOP_GEN(g_load, Ares, Bres);
#pragma unroll
        for (int mi = 0; mi < 4; mi++)
#pragma unroll
            for (int half = 0; half < 2; half++) {
                int lr = wm + mi * 16 + qr + half * 8;
                float* dst = &rfbuf[lr * RFLD + wn];
#pragma unroll
                for (int ni = 0; ni < 8; ni++) {
                    int col = ni * 8 + qc * 2;
                    dst[col]     = acc[mi][ni][half * 2 + 0] + bias[wn + col + 0];
                    dst[col + 1] = acc[mi][ni][half * 2 + 1] + bias[wn + col + 1];
                }
            }
        __syncthreads();
    }

    // job 1: wb GEMM (fp16 A) + gated blend
    {
        float acc[4][8][4];
        ACC_ZERO();
        GEMM_MAINLOOP_GEN(g_load_h, Awb, Bwb);

        const float g = 1.f / (1.f + __expf(-gate[0]));
#pragma unroll
        for (int mi = 0; mi < 4; mi++) {
#pragma unroll
            for (int half = 0; half < 2; half++) {
                int lr = wm + mi * 16 + qr + half * 8;
                int row = m0 + lr;
                if (row >= M) continue;
                const float* resrow = &rfbuf[lr * RFLD + wn];
                float* orow = &outA[(size_t)row * KD + wn];
#pragma unroll
                for (int ni = 0; ni < 8; ni++) {
                    int col = ni * 8 + qc * 2;
                    float2 v;
                    v.x = g * acc[mi][ni][half * 2 + 0] + (1.f - g) * resrow[col];
                    v.y = g * acc[mi][ni][half * 2 + 1] + (1.f - g) * resrow[col + 1];
                    *(float2*)&orow[col] = v;
                }
            }
        }
    }
}

// trailing join node
__global__ void join_k() {}

// ---------------- batched CSR build ----------------
__global__ void csr_hist3(const int* __restrict__ d0, const int* __restrict__ d1,
                          const int* __restrict__ d2, int* __restrict__ counts)
{
    int e = blockIdx.x * blockDim.x + threadIdx.x;
    if (e >= EDG) return;
    atomicAdd(&counts[d0[e]], 1);
    atomicAdd(&counts[50000 + d1[e]], 1);
    atomicAdd(&counts[100000 + d2[e]], 1);
}

__global__ void scan_block(const int* __restrict__ in, int* __restrict__ out,
                           int* __restrict__ partials, int n)
{
    __shared__ int wsum[8];
    int i = blockIdx.x * 256 + threadIdx.x;
    int lane = threadIdx.x & 31, wid = threadIdx.x >> 5;
    int v = (i < n) ? in[i] : 0;
    int x = v;
#pragma unroll
    for (int o = 1; o < 32; o <<= 1) {
        int t = __shfl_up_sync(0xffffffffu, x, o);
        if (lane >= o) x += t;
    }
    if (lane == 31) wsum[wid] = x;
    __syncthreads();
    if (wid == 0) {
        int w = (lane < 8) ? wsum[lane] : 0;
#pragma unroll
        for (int o = 1; o < 8; o <<= 1) {
            int t = __shfl_up_sync(0xffffffffu, w, o);
            if (lane >= o) w += t;
        }
        if (lane < 8) wsum[lane] = w;
    }
    __syncthreads();
    int wpre = (wid > 0) ? wsum[wid - 1] : 0;
    if (i < n) out[i] = wpre + x - v;
    if (threadIdx.x == 0) partials[blockIdx.x] = wsum[7];
}

__global__ void scan_top1k(int* __restrict__ partials, int nb)
{
    __shared__ int wsum[32];
    int i = threadIdx.x;
    int lane = i & 31, wid = i >> 5;
    int v = (i < nb) ? partials[i] : 0;
    int x = v;
#pragma unroll
    for (int o = 1; o < 32; o <<= 1) {
        int t = __shfl_up_sync(0xffffffffu, x, o);
        if (lane >= o) x += t;
    }
    if (lane == 31) wsum[wid] = x;
    __syncthreads();
    if (wid == 0) {
        int w = wsum[lane];
#pragma unroll
        for (int o = 1; o < 32; o <<= 1) {
            int t = __shfl_up_sync(0xffffffffu, w, o);
            if (lane >= o) w += t;
        }
        wsum[lane] = w;
    }
    __syncthreads();
    int wpre = (wid > 0) ? wsum[wid - 1] : 0;
    if (i < nb) partials[i] = wpre + x - v;
    if (i == 0) partials[nb] = wsum[31];
}

// writes offsets AND initializes cursor = offsets (scatter uses cursor directly)
__global__ void scan_add(int* __restrict__ offsets, int* __restrict__ cursor,
                         const int* __restrict__ partials, int n)
{
    int i = blockIdx.x * 256 + threadIdx.x;
    if (i < n) {
        int v = offsets[i] + partials[blockIdx.x];
        offsets[i] = v;
        cursor[i] = v;
    }
    if (i == 0) offsets[n] = partials[gridDim.x];
}

__global__ void csr_scatter3(
    const int* __restrict__ s0, const int* __restrict__ d0,
    const int* __restrict__ s1, const int* __restrict__ d1,
    const int* __restrict__ s2p, const int* __restrict__ d2,
    int* __restrict__ cursor, int* __restrict__ ssort)
{
    int idx = blockIdx.x * blockDim.x + threadIdx.x;
    if (idx >= 3 * EDG) return;
    int r = (idx >= 2 * EDG) ? 2 : (idx >= EDG) ? 1 : 0;
    int e = idx - r * EDG;
    const int* src = (r == 0) ? s0 : (r == 1) ? s1 : s2p;
    const int* dst = (r == 0) ? d0 : (r == 1) ? d1 : d2;
    int key = r * 50000 + dst[e];
    int pos = atomicAdd(&cursor[key], 1);
    ssort[pos] = src[e];
}

// ---------------- fused micro gather (fp16 in + out, max-free softmax) ----------------
__global__ void micro_gather(const int* __restrict__ ssort, const int* __restrict__ offsets,
                             const float* __restrict__ el, const float* __restrict__ er,
                             const __half* __restrict__ Psrc, __half* __restrict__ ft, int n_dst)
{
    int d = (blockIdx.x * blockDim.x + threadIdx.x) >> 5;
    int lane = threadIdx.x & 31;
    if (d >= n_dst) return;
    int beg = offsets[d], end = offsets[d + 1];
    __half* dstp = &ft[(size_t)d * KD + lane * 8];
    if (beg == end) {
        float4 z = make_float4(0.f, 0.f, 0.f, 0.f);
        *(float4*)dstp = z;   // 8 zero halves
        return;
    }
    float erh = (lane < KH) ? er[d * KH + lane] : 0.f;

    const int hk = lane >> 2;
    float acc[8] = {0.f, 0.f, 0.f, 0.f, 0.f, 0.f, 0.f, 0.f};
    float se = 0.f;
    int i = beg;
    for (; i + 2 <= end; i += 2) {
        int s0 = ssort[i], s1 = ssort[i + 1];
        float w0 = 0.f, w1 = 0.f;
        if (lane < KH) {
            w0 = __expf(leaky(el[s0 * KH + lane] + erh));
            w1 = __expf(leaky(el[s1 * KH + lane] + erh));
            se += w0 + w1;
        }
        float wk0 = __shfl_sync(0xffffffffu, w0, hk);
        float wk1 = __shfl_sync(0xffffffffu, w1, hk);
        float4 raw0 = *(const float4*)&Psrc[(size_t)s0 * KD + lane * 8];
        float4 raw1 = *(const float4*)&Psrc[(size_t)s1 * KD + lane * 8];
        const __half2* h0 = (const __half2*)&raw0;
        const __half2* h1 = (const __half2*)&raw1;
#pragma unroll
        for (int q = 0; q < 4; q++) {
            float2 f0 = __half22float2(h0[q]);
            float2 f1 = __half22float2(h1[q]);
            acc[q * 2 + 0] = fmaf(wk0, f0.x, acc[q * 2 + 0]);
            acc[q * 2 + 0] = fmaf(wk1, f1.x, acc[q * 2 + 0]);
            acc[q * 2 + 1] = fmaf(wk0, f0.y, acc[q * 2 + 1]);
            acc[q * 2 + 1] = fmaf(wk1, f1.y, acc[q * 2 + 1]);
        }
    }
    if (i < end) {
        int s0 = ssort[i];
        float w0 = 0.f;
        if (lane < KH) {
            w0 = __expf(leaky(el[s0 * KH + lane] + erh));
            se += w0;
        }
        float wk0 = __shfl_sync(0xffffffffu, w0, hk);
        float4 raw0 = *(const float4*)&Psrc[(size_t)s0 * KD + lane * 8];
        const __half2* h0 = (const __half2*)&raw0;
#pragma unroll
        for (int q = 0; q < 4; q++) {
            float2 f0 = __half22float2(h0[q]);
            acc[q * 2 + 0] = fmaf(wk0, f0.x, acc[q * 2 + 0]);
            acc[q * 2 + 1] = fmaf(wk0, f0.y, acc[q * 2 + 1]);
        }
    }
    float inv = 1.f / __shfl_sync(0xffffffffu, se, hk);
    float4 outv;
    __half2* op = (__half2*)&outv;
#pragma unroll
    for (int q = 0; q < 4; q++) {
        float vx = fmaxf(acc[q * 2 + 0] * inv, 0.f);
        float vy = fmaxf(acc[q * 2 + 1] * inv, 0.f);
        op[q] = __floats2half2_rn(vx, vy);
    }
    *(float4*)dstp = outv;
}

// ---------------- launch ----------------
extern "C" void kernel_launch(void* const* d_in, const int* in_sizes, int n_in,
                              void* d_out, int out_size)
{
    const float* feats_author    = (const float*)d_in[0];
    const float* feats_paper     = (const float*)d_in[1];
    const float* W_micro_author  = (const float*)d_in[2];
    const float* W_micro_paper   = (const float*)d_in[3];
    const float* attn_micro_a    = (const float*)d_in[4];
    const float* attn_micro_p    = (const float*)d_in[5];
    const float* W_macro_node_p  = (const float*)d_in[7];
    const float* W_rel_writes    = (const float*)d_in[8];
    const float* W_rel_wb        = (const float*)d_in[9];
    const float* W_rel_cites     = (const float*)d_in[10];
    const float* attn_macro      = (const float*)d_in[11];
    const float* W_res_author    = (const float*)d_in[12];
    const float* b_res_author    = (const float*)d_in[13];
    const float* W_res_paper     = (const float*)d_in[14];
    const float* b_res_paper     = (const float*)d_in[15];
    const float* res_w_author    = (const float*)d_in[16];
    const float* res_w_paper     = (const float*)d_in[17];
    const int*   writes_src      = (const int*)d_in[18];
    const int*   writes_dst      = (const int*)d_in[19];
    const int*   wb_src          = (const int*)d_in[20];
    const int*   wb_dst          = (const int*)d_in[21];
    const int*   cites_src       = (const int*)d_in[22];
    const int*   cites_dst       = (const int*)d_in[23];
    float* out = (float*)d_out;

    __half *PA, *PP, *ft_w, *ft_wb, *ft_c;
    float *elA_aA, *erP_aA, *elP_aP, *erA_aP, *erP_aP, *npscore;
    int *counts, *cursor, *offsets, *partials, *ssort;
    cudaGetSymbolAddress((void**)&PA, g_PA);
    cudaGetSymbolAddress((void**)&PP, g_PP);
    cudaGetSymbolAddress((void**)&elA_aA, g_elA_aA);
    cudaGetSymbolAddress((void**)&erP_aA, g_erP_aA);
    cudaGetSymbolAddress((void**)&elP_aP, g_elP_aP);
    cudaGetSymbolAddress((void**)&erA_aP, g_erA_aP);
    cudaGetSymbolAddress((void**)&erP_aP, g_erP_aP);
    cudaGetSymbolAddress((void**)&ft_w, g_ft_w);
    cudaGetSymbolAddress((void**)&ft_wb, g_ft_wb);
    cudaGetSymbolAddress((void**)&ft_c, g_ft_c);
    cudaGetSymbolAddress((void**)&npscore, g_npscore);
    cudaGetSymbolAddress((void**)&counts, g_counts);
    cudaGetSymbolAddress((void**)&cursor, g_cursor);
    cudaGetSymbolAddress((void**)&offsets, g_offsets);
    cudaGetSymbolAddress((void**)&partials, g_partials);
    cudaGetSymbolAddress((void**)&ssort, g_ssort);

    static cudaStream_t s2 = nullptr;
    static cudaEvent_t evFork = nullptr, evA = nullptr, evP = nullptr,
                       ev2 = nullptr, evS2 = nullptr;
    if (!s2) {
        cudaStreamCreateWithFlags(&s2, cudaStreamNonBlocking);
        cudaEventCreateWithFlags(&evFork, cudaEventDisableTiming);
        cudaEventCreateWithFlags(&evA, cudaEventDisableTiming);
        cudaEventCreateWithFlags(&evP, cudaEventDisableTiming);
        cudaEventCreateWithFlags(&ev2, cudaEventDisableTiming);
        cudaEventCreateWithFlags(&evS2, cudaEventDisableTiming);
    }

    cudaFuncSetAttribute(gemm_multi, cudaFuncAttributeMaxDynamicSharedMemorySize, SMEM_BYTES);
    cudaFuncSetAttribute(gemm_rf_fused, cudaFuncAttributeMaxDynamicSharedMemorySize, FUSE_SMEM);
    cudaFuncSetAttribute(gemm_author_fused, cudaFuncAttributeMaxDynamicSharedMemorySize, FUSE_SMEM);

    const int GG = (NA + BM - 1) / BM;
    const int EB = (EDG + 255) / 256;
    const int EB3 = (3 * EDG + 255) / 256;
    const int GB = (NA * 32 + 255) / 256;

    GemmJob jz = {};

    // ---- fork: s2 runs batched CSR build ----
    cudaEventRecord(evFork, 0);
    cudaStreamWaitEvent(s2, evFork, 0);
    cudaMemsetAsync(counts, 0, NTOT * sizeof(int), s2);
    csr_hist3<<<EB, 256, 0, s2>>>(writes_dst, wb_dst, cites_dst, counts);
    scan_block<<<NBLK3, 256, 0, s2>>>(counts, offsets, partials, NTOT);
    scan_top1k<<<1, 1024, 0, s2>>>(partials, NBLK3);
    scan_add<<<NBLK3, 256, 0, s2>>>(offsets, cursor, partials, NTOT);
    csr_scatter3<<<EB3, 256, 0, s2>>>(writes_src, writes_dst, wb_src, wb_dst,
                                      cites_src, cites_dst, cursor, ssort);

    // ---- main: author micro GEMM -> fp16 PA (+fused attn dots) ----
    {
        GemmJob ja = { feats_author, W_micro_author, nullptr, PA, nullptr, nullptr,
                       attn_micro_a + 0,  elA_aA,
                       attn_micro_p + 32, erA_aP,
                       nullptr, nullptr };
        gemm_multi<<<GG, 256, SMEM_BYTES>>>(ja, jz, jz, 1, NA);
    }
    cudaEventRecord(evA, 0);

    // ---- s2: paper micro GEMM -> fp16 PP (+3 fused attn dots) ----
    {
        GemmJob ja = { feats_paper, W_micro_paper, nullptr, PP, nullptr, nullptr,
                       attn_micro_a + 32, erP_aA,
                       attn_micro_p + 0,  elP_aP,
                       attn_micro_p + 32, erP_aP };
        gemm_multi<<<GG, 256, SMEM_BYTES, s2>>>(ja, jz, jz, 1, NP);
    }
    cudaEventRecord(evP, s2);

    // ---- s2: gather cites, then gather writes ----
    micro_gather<<<GB, 256, 0, s2>>>(ssort, offsets + 2 * 50000,
                                     elP_aP, erP_aP, PP, ft_c, NP);
    cudaStreamWaitEvent(s2, evA, 0);
    micro_gather<<<GB, 256, 0, s2>>>(ssort, offsets + 0 * 50000,
                                     elA_aA, erP_aA, PA, ft_w, NP);

    // ---- main: 2-job GEMM (npscore fused dot, res_paper -> out[NA:]) ----
    {
        GemmJob ja = { feats_paper, W_macro_node_p, nullptr, nullptr, nullptr, nullptr,
                       attn_macro + 0, npscore,
                       nullptr, nullptr, nullptr, nullptr };
        GemmJob jb = { feats_paper, W_res_paper, out + (size_t)NA * KD, nullptr,
                       b_res_paper, nullptr,
                       nullptr, nullptr, nullptr, nullptr, nullptr, nullptr };
        gemm_multi<<<GG, 256, SMEM_BYTES>>>(ja, jb, jz, 2, NP);
    }
    cudaEventRecord(ev2, 0);

    // ---- main: gather written_by ----
    cudaStreamWaitEvent(0, evP, 0);
    micro_gather<<<GB, 256, 0, 0>>>(ssort, offsets + 1 * 50000,
                                    elP_aP, erA_aP, PP, ft_wb, NA);

    // ---- main: fused author -> out[:NA] ----
    gemm_author_fused<<<GG, 256, FUSE_SMEM>>>(feats_author, W_res_author, b_res_author,
                                              ft_wb, W_rel_wb, res_w_author, out, NA);

    // ---- s2: fused rf + semantic attention + gated residual -> out[NA:] ----
    cudaStreamWaitEvent(s2, ev2, 0);
    gemm_rf_fused<<<GG, 256, FUSE_SMEM, s2>>>(ft_w, W_rel_writes, ft_c, W_rel_cites,
                                              npscore, attn_macro, res_w_paper,
                                              out + (size_t)NA * KD, NP);
    cudaEventRecord(evS2, s2);

    // ---- join ----
    cudaStreamWaitEvent(0, evS2, 0);
    join_k<<<1, 1>>>();
}

// round 16
// speedup vs baseline: 1.2523x; 1.0164x over previous
#include <cuda_runtime.h>
#include <cuda_fp16.h>
#include <cstdint>
#include <math.h>

// ---------------- problem constants ----------------
#define NA 50000
#define NP 50000
#define EDG 400000
#define KH 8
#define DH 32
#define KD 256
#define SLOPE 0.2f

// GEMM tiling
#define BM 128
#define BK 16
#define NKT (KD / BK)
#define LDK 20
#define LDBN 264
#define ASZ (128 * LDK)
#define BSZ (BK * LDBN)
#define SMEM_BYTES ((2 * ASZ + 2 * BSZ) * 4)     // 54272
#define RFLD 260
#define FUSE_SMEM (SMEM_BYTES + 128 * RFLD * 4)  // 187392

#define NTOT 150000
#define NBLK3 ((NTOT + 255) / 256)     // 586

// ---------------- device scratch ----------------
__device__ __half g_PA[NA * KD];
__device__ __half g_PP[NP * KD];

__device__ float g_elA_aA[NA * KH];
__device__ float g_erP_aA[NP * KH];
__device__ float g_elP_aP[NP * KH];
__device__ float g_erA_aP[NA * KH];
__device__ float g_erP_aP[NP * KH];

__device__ __half g_ft_w[NP * KD];
__device__ __half g_ft_wb[NA * KD];
__device__ __half g_ft_c[NP * KD];

__device__ float g_npscore[NP * KH];
__device__ float g_Wnp[KH * 256];      // transposed effective weight [k][i]

// CSR scratch (combined)
__device__ int g_counts[NTOT];
__device__ int g_cursor[NTOT];
__device__ int g_offsets[NTOT + 1];
__device__ int g_partials[NBLK3 + 2];
__device__ int g_ssort[3 * EDG];

// ---------------- helpers ----------------
__device__ __forceinline__ float leaky(float v) {
    return v > 0.f ? v : SLOPE * v;
}
__device__ __forceinline__ uint32_t f2tf32(float f) {
    uint32_t r;
    asm("cvt.rna.tf32.f32 %0, %1;" : "=r"(r) : "f"(f));
    return r;
}
__device__ __forceinline__ void mma_tf32(float c[4], uint32_t a0, uint32_t a1,
                                         uint32_t a2, uint32_t a3,
                                         uint32_t b0, uint32_t b1) {
    asm volatile(
        "mma.sync.aligned.m16n8k8.row.col.f32.tf32.tf32.f32 "
        "{%0,%1,%2,%3}, {%4,%5,%6,%7}, {%8,%9}, {%0,%1,%2,%3};"
        : "+f"(c[0]), "+f"(c[1]), "+f"(c[2]), "+f"(c[3])
        : "r"(a0), "r"(a1), "r"(a2), "r"(a3), "r"(b0), "r"(b1));
}

struct GemmJob {
    const float* A;
    const float* B;
    float*       C;
    __half*      Ch;
    const float* bias;
    const float* gate;
    const float* av0; float* ao0;
    const float* av1; float* ao1;
    const float* av2; float* ao2;
};

#define GEMM_PROLOGUE() \
    const int tid = threadIdx.x; \
    const int lane = tid & 31; \
    const int wid = tid >> 5; \
    const int wm = (wid & 1) * 64; \
    const int wn = (wid >> 1) * 64; \
    const int m0 = blockIdx.x * BM; \
    const int qr = lane >> 2; \
    const int qc = lane & 3; \
    const int am = tid >> 1; \
    const int aq = (tid & 1) * 8; \
    const int bkr = tid >> 4; \
    const int bnc = (tid & 15) * 16; \
    float4 rA[2], rB[4]; \
    auto g_load = [&](int kt, const float* __restrict__ A, const float* __restrict__ B) { \
        const int k0 = kt * BK; \
        int row = m0 + am; \
        if (row < M) { \
            rA[0] = *(const float4*)&A[(size_t)row * KD + k0 + aq]; \
            rA[1] = *(const float4*)&A[(size_t)row * KD + k0 + aq + 4]; \
        } else { \
            rA[0] = make_float4(0.f, 0.f, 0.f, 0.f); \
            rA[1] = rA[0]; \
        } \
        const float* bp = &B[(size_t)(k0 + bkr) * KD + bnc]; \
        rB[0] = *(const float4*)&bp[0]; \
        rB[1] = *(const float4*)&bp[4]; \
        rB[2] = *(const float4*)&bp[8]; \
        rB[3] = *(const float4*)&bp[12]; \
    }; \
    auto g_load_h = [&](int kt, const __half* __restrict__ Ah, const float* __restrict__ B) { \
        const int k0 = kt * BK; \
        int row = m0 + am; \
        if (row < M) { \
            float4 raw = *(const float4*)&Ah[(size_t)row * KD + k0 + aq]; \
            const __half2* hp = (const __half2*)&raw; \
            float2 f0 = __half22float2(hp[0]); \
            float2 f1 = __half22float2(hp[1]); \
            float2 f2 = __half22float2(hp[2]); \
            float2 f3 = __half22float2(hp[3]); \
            rA[0] = make_float4(f0.x, f0.y, f1.x, f1.y); \
            rA[1] = make_float4(f2.x, f2.y, f3.x, f3.y); \
        } else { \
            rA[0] = make_float4(0.f, 0.f, 0.f, 0.f); \
            rA[1] = rA[0]; \
        } \
        const float* bp = &B[(size_t)(k0 + bkr) * KD + bnc]; \
        rB[0] = *(const float4*)&bp[0]; \
        rB[1] = *(const float4*)&bp[4]; \
        rB[2] = *(const float4*)&bp[8]; \
        rB[3] = *(const float4*)&bp[12]; \
    }; \
    auto s_store = [&](int buf) { \
        uint32_t* as = &smem[buf * ASZ + am * LDK + aq]; \
        uint4 v0, v1; \
        v0.x = f2tf32(rA[0].x); v0.y = f2tf32(rA[0].y); \
        v0.z = f2tf32(rA[0].z); v0.w = f2tf32(rA[0].w); \
        v1.x = f2tf32(rA[1].x); v1.y = f2tf32(rA[1].y); \
        v1.z = f2tf32(rA[1].z); v1.w = f2tf32(rA[1].w); \
        *(uint4*)&as[0] = v0; \
        *(uint4*)&as[4] = v1; \
        uint32_t* bs = &smem[2 * ASZ + buf * BSZ + bkr * LDBN + bnc]; \
        _Pragma("unroll") \
        for (int q = 0; q < 4; q++) { \
            uint4 w; \
            w.x = f2tf32(((const float*)&rB[q])[0]); \
            w.y = f2tf32(((const float*)&rB[q])[1]); \
            w.z = f2tf32(((const float*)&rB[q])[2]); \
            w.w = f2tf32(((const float*)&rB[q])[3]); \
            *(uint4*)&bs[q * 4] = w; \
        } \
    };

#define GEMM_MAINLOOP_GEN(loader, Aptr, Bptr) \
    { \
        float (*accp)[8][4] = acc; \
        loader(0, Aptr, Bptr); \
        s_store(0); \
        __syncthreads(); \
        for (int kt = 0; kt < NKT; kt++) { \
            const int cur = kt & 1; \
            if (kt + 1 < NKT) loader(kt + 1, Aptr, Bptr); \
            const uint32_t* asb = &smem[cur * ASZ]; \
            const uint32_t* bsb = &smem[2 * ASZ + cur * BSZ]; \
            _Pragma("unroll") \
            for (int ks = 0; ks < BK; ks += 8) { \
                uint32_t a[4][4], b[8][2]; \
                _Pragma("unroll") \
                for (int mi = 0; mi < 4; mi++) { \
                    int r0 = wm + mi * 16 + qr; \
                    a[mi][0] = asb[r0 * LDK + ks + qc]; \
                    a[mi][1] = asb[(r0 + 8) * LDK + ks + qc]; \
                    a[mi][2] = asb[r0 * LDK + ks + qc + 4]; \
                    a[mi][3] = asb[(r0 + 8) * LDK + ks + qc + 4]; \
                } \
                _Pragma("unroll") \
                for (int ni = 0; ni < 8; ni++) { \
                    int c0 = wn + ni * 8 + qr; \
                    b[ni][0] = bsb[(ks + qc) * LDBN + c0]; \
                    b[ni][1] = bsb[(ks + qc + 4) * LDBN + c0]; \
                } \
                _Pragma("unroll") \
                for (int mi = 0; mi < 4; mi++) \
                    _Pragma("unroll") \
                    for (int ni = 0; ni < 8; ni++) \
                        mma_tf32(accp[mi][ni], a[mi][0], a[mi][1], a[mi][2], a[mi][3], \
                                 b[ni][0], b[ni][1]); \
            } \
            if (kt + 1 < NKT) { \
                s_store(1 - cur); \
                __syncthreads(); \
            } \
        } \
    }

#define ACC_ZERO() \
    _Pragma("unroll") \
    for (int mi = 0; mi < 4; mi++) \
        _Pragma("unroll") \
        for (int ni = 0; ni < 8; ni++) \
            _Pragma("unroll") \
            for (int r = 0; r < 4; r++) acc[mi][ni][r] = 0.f;

// ================= multi-job tf32 GEMM (fp32 A) =================
__global__ void __launch_bounds__(256, 1) gemm_multi(
    GemmJob j0, GemmJob j1, GemmJob j2, int nb, int M)
{
    extern __shared__ uint32_t smem[];
    GEMM_PROLOGUE();

#pragma unroll
    for (int o = 0; o < 3; o++) {
        if (o >= nb) break;
        const GemmJob J = (o == 0) ? j0 : (o == 1) ? j1 : j2;

        float acc[4][8][4];
        ACC_ZERO();
        GEMM_MAINLOOP_GEN(g_load, J.A, J.B);

        if (J.av0) {
            const float* avs[3] = { J.av0, J.av1, J.av2 };
            float*       aos[3] = { J.ao0, J.ao1, J.ao2 };
            const int h0 = wn >> 5;
#pragma unroll
            for (int t = 0; t < 3; t++) {
                const float* av = avs[t];
                if (!av) break;
                float* ao = aos[t];
                float c0[8], c1[8];
#pragma unroll
                for (int ni = 0; ni < 8; ni++) {
                    int col = wn + ni * 8 + qc * 2;
                    int idx = (col >> 5) * 64 + (col & 31);
                    c0[ni] = av[idx];
                    c1[ni] = av[idx + 1];
                }
#pragma unroll
                for (int mi = 0; mi < 4; mi++) {
#pragma unroll
                    for (int half = 0; half < 2; half++) {
                        float pa = 0.f, pb = 0.f;
#pragma unroll
                        for (int ni = 0; ni < 4; ni++)
                            pa += acc[mi][ni][half * 2] * c0[ni]
                                + acc[mi][ni][half * 2 + 1] * c1[ni];
#pragma unroll
                        for (int ni = 4; ni < 8; ni++)
                            pb += acc[mi][ni][half * 2] * c0[ni]
                                + acc[mi][ni][half * 2 + 1] * c1[ni];
                        pa += __shfl_xor_sync(0xffffffffu, pa, 1);
                        pa += __shfl_xor_sync(0xffffffffu, pa, 2);
                        pb += __shfl_xor_sync(0xffffffffu, pb, 1);
                        pb += __shfl_xor_sync(0xffffffffu, pb, 2);
                        int row = m0 + wm + mi * 16 + qr + half * 8;
                        if (qc == 0 && row < M) {
                            ao[row * KH + h0]     = pa;
                            ao[row * KH + h0 + 1] = pb;
                        }
                    }
                }
            }
        }

        if (J.Ch) {
#pragma unroll
            for (int mi = 0; mi < 4; mi++) {
#pragma unroll
                for (int half = 0; half < 2; half++) {
                    int row = m0 + wm + mi * 16 + qr + half * 8;
                    if (row >= M) continue;
                    __half* dst = &J.Ch[(size_t)row * KD + wn];
#pragma unroll
                    for (int ni = 0; ni < 8; ni++) {
                        int col = ni * 8 + qc * 2;
                        *(__half2*)&dst[col] = __floats2half2_rn(
                            acc[mi][ni][half * 2 + 0], acc[mi][ni][half * 2 + 1]);
                    }
                }
            }
        } else if (J.C) {
            float g = 0.f;
            if (J.gate) g = 1.f / (1.f + __expf(-J.gate[0]));
#pragma unroll
            for (int mi = 0; mi < 4; mi++) {
#pragma unroll
                for (int half = 0; half < 2; half++) {
                    int row = m0 + wm + mi * 16 + qr + half * 8;
                    if (row >= M) continue;
                    float* dst = &J.C[(size_t)row * KD + wn];
#pragma unroll
                    for (int ni = 0; ni < 8; ni++) {
                        int col = ni * 8 + qc * 2;
                        float2 v;
                        v.x = acc[mi][ni][half * 2 + 0];
                        v.y = acc[mi][ni][half * 2 + 1];
                        if (J.bias) {
                            v.x += J.bias[wn + col + 0];
                            v.y += J.bias[wn + col + 1];
                        }
                        if (J.gate) {
                            float2 prev = *(const float2*)&dst[col];
                            v.x = g * v.x + (1.f - g) * prev.x;
                            v.y = g * v.y + (1.f - g) * prev.y;
                        }
                        *(float2*)&dst[col] = v;
                    }
                }
            }
        }
        __syncthreads();
    }
}

// ================= fused rf_w + rf_c (fp16 A) + semantic attention + gated residual =================
__global__ void __launch_bounds__(256, 1) gemm_rf_fused(
    const __half* __restrict__ Aw, const float* __restrict__ Bw,
    const __half* __restrict__ Ac, const float* __restrict__ Bc,
    const float* __restrict__ npscore, const float* __restrict__ attnM,
    const float* __restrict__ resw, float* __restrict__ outP, int M)
{
    extern __shared__ uint32_t smem[];
    float* rfbuf = (float*)(smem + 2 * ASZ + 2 * BSZ);
    GEMM_PROLOGUE();

#pragma unroll
    for (int o = 0; o < 2; o++) {
        const __half* A = (o == 0) ? Aw : Ac;
        const float* B = (o == 0) ? Bw : Bc;

        float acc[4][8][4];
        ACC_ZERO();
        GEMM_MAINLOOP_GEN(g_load_h, A, B);

        if (o == 0) {
#pragma unroll
            for (int mi = 0; mi < 4; mi++)
#pragma unroll
                for (int half = 0; half < 2; half++) {
                    int lr = wm + mi * 16 + qr + half * 8;
                    float* dst = &rfbuf[lr * RFLD + wn];
#pragma unroll
                    for (int ni = 0; ni < 8; ni++) {
                        int col = ni * 8 + qc * 2;
                        dst[col]     = acc[mi][ni][half * 2 + 0];
                        dst[col + 1] = acc[mi][ni][half * 2 + 1];
                    }
                }
            __syncthreads();
            continue;
        }

        const float g = 1.f / (1.f + __expf(-resw[0]));
        const int h0 = wn >> 5;
        float cr0[8], cr1[8];
#pragma unroll
        for (int ni = 0; ni < 8; ni++) {
            int col = wn + ni * 8 + qc * 2;
            int base = (col >> 5) * 64 + (col & 31);
            cr0[ni] = attnM[base + 32];
            cr1[ni] = attnM[base + 33];
        }

#pragma unroll
        for (int mi = 0; mi < 4; mi++) {
#pragma unroll
            for (int half = 0; half < 2; half++) {
                int lr = wm + mi * 16 + qr + half * 8;
                int row = m0 + lr;
                if (row >= M) continue;
                const float* rwrow = &rfbuf[lr * RFLD + wn];
                float* orow = &outP[(size_t)row * KD + wn];
                float npa = npscore[row * KH + h0];
                float npb = npscore[row * KH + h0 + 1];

                float swa = 0.f, sca = 0.f, swb = 0.f, scb = 0.f;
#pragma unroll
                for (int ni = 0; ni < 8; ni++) {
                    int col = ni * 8 + qc * 2;
                    float rw0 = rwrow[col], rw1 = rwrow[col + 1];
                    float rc0 = acc[mi][ni][half * 2], rc1 = acc[mi][ni][half * 2 + 1];
                    float wpart = rw0 * cr0[ni] + rw1 * cr1[ni];
                    float cpart = rc0 * cr0[ni] + rc1 * cr1[ni];
                    if (ni < 4) { swa += wpart; sca += cpart; }
                    else        { swb += wpart; scb += cpart; }
                }
                swa += __shfl_xor_sync(0xffffffffu, swa, 1);
                swa += __shfl_xor_sync(0xffffffffu, swa, 2);
                sca += __shfl_xor_sync(0xffffffffu, sca, 1);
                sca += __shfl_xor_sync(0xffffffffu, sca, 2);
                swb += __shfl_xor_sync(0xffffffffu, swb, 1);
                swb += __shfl_xor_sync(0xffffffffu, swb, 2);
                scb += __shfl_xor_sync(0xffffffffu, scb, 1);
                scb += __shfl_xor_sync(0xffffffffu, scb, 2);

                float swA = leaky(npa + swa), scA = leaky(npa + sca);
                float swB = leaky(npb + swb), scB = leaky(npb + scb);
                float ma = fmaxf(swA, scA);
                float ea = __expf(swA - ma), eca = __expf(scA - ma);
                float awa = ea / (ea + eca);
                float mb = fmaxf(swB, scB);
                float eb = __expf(swB - mb), ecb = __expf(scB - mb);
                float awb = eb / (eb + ecb);

#pragma unroll
                for (int ni = 0; ni < 8; ni++) {
                    int col = ni * 8 + qc * 2;
                    float aw = (ni < 4) ? awa : awb;
                    float rw0 = rwrow[col], rw1 = rwrow[col + 1];
                    float rc0 = acc[mi][ni][half * 2], rc1 = acc[mi][ni][half * 2 + 1];
                    float2 prev = *(const float2*)&orow[col];
                    float2 v;
                    v.x = g * (aw * rw0 + (1.f - aw) * rc0) + (1.f - g) * prev.x;
                    v.y = g * (aw * rw1 + (1.f - aw) * rc1) + (1.f - g) * prev.y;
                    *(float2*)&orow[col] = v;
                }
            }
        }
    }
}

// ================= fused author =================
__global__ void __launch_bounds__(256, 1) gemm_author_fused(
    const float* __restrict__ Ares, const float* __restrict__ Bres,
    const float* __restrict__ bias,
    const __half* __restrict__ Awb, const float* __restrict__ Bwb,
    const float* __restrict__ gate, float* __restrict__ outA, int M)
{
    extern __shared__ uint32_t smem[];
    float* rfbuf = (float*)(smem + 2 * ASZ + 2 * BSZ);
    GEMM_PROLOGUE();

    {
        float acc[4][8][4];
        ACC_ZERO();
        GEMM_MAINLOOP_GEN(g_load, Ares, Bres);
#pragma unroll
        for (int mi = 0; mi < 4; mi++)
#pragma unroll
            for (int half = 0; half < 2; half++) {
                int lr = wm + mi * 16 + qr + half * 8;
                float* dst = &rfbuf[lr * RFLD + wn];
#pragma unroll
                for (int ni = 0; ni < 8; ni++) {
                    int col = ni * 8 + qc * 2;
                    dst[col]     = acc[mi][ni][half * 2 + 0] + bias[wn + col + 0];
                    dst[col + 1] = acc[mi][ni][half * 2 + 1] + bias[wn + col + 1];
                }
            }
        __syncthreads();
    }

    {
        float acc[4][8][4];
        ACC_ZERO();
        GEMM_MAINLOOP_GEN(g_load_h, Awb, Bwb);

        const float g = 1.f / (1.f + __expf(-gate[0]));
#pragma unroll
        for (int mi = 0; mi < 4; mi++) {
#pragma unroll
            for (int half = 0; half < 2; half++) {
                int lr = wm + mi * 16 + qr + half * 8;
                int row = m0 + lr;
                if (row >= M) continue;
                const float* resrow = &rfbuf[lr * RFLD + wn];
                float* orow = &outA[(size_t)row * KD + wn];
#pragma unroll
                for (int ni = 0; ni < 8; ni++) {
                    int col = ni * 8 + qc * 2;
                    float2 v;
                    v.x = g * acc[mi][ni][half * 2 + 0] + (1.f - g) * resrow[col];
                    v.y = g * acc[mi][ni][half * 2 + 1] + (1.f - g) * resrow[col + 1];
                    *(float2*)&orow[col] = v;
                }
            }
        }
    }
}

// trailing join node
__global__ void join_k() {}

// ---------------- Wnp precompute: Wnp_T[k][i] = sum_d W[i, k*32+d] * attnM[k*64+d] ----------------
__global__ void wnp_k(const float* __restrict__ W, const float* __restrict__ attnM,
                      float* __restrict__ WnpT)
{
    int i = threadIdx.x;       // 0..255
    int k = blockIdx.x;        // 0..7
    float s = 0.f;
#pragma unroll
    for (int d = 0; d < DH; d++)
        s = fmaf(W[i * KD + k * DH + d], attnM[k * 64 + d], s);
    WnpT[k * 256 + i] = s;
}

// ---------------- npscore: warp per node, np[n,k] = <feats[n,:], WnpT[k,:]> ----------------
__global__ void __launch_bounds__(256) npscore_k(
    const float* __restrict__ feats, const float* __restrict__ WnpT,
    float* __restrict__ np, int N)
{
    __shared__ float w[KH * 256];
    for (int i = threadIdx.x; i < KH * 256; i += 256) w[i] = WnpT[i];
    __syncthreads();
    int warp = threadIdx.x >> 5, lane = threadIdx.x & 31;
    int n = blockIdx.x * 8 + warp;
    if (n >= N) return;
    const float4* f = (const float4*)&feats[(size_t)n * KD + lane * 8];
    float4 f0 = f[0], f1 = f[1];
    float fv[8] = { f0.x, f0.y, f0.z, f0.w, f1.x, f1.y, f1.z, f1.w };
    float pk[KH] = {0.f, 0.f, 0.f, 0.f, 0.f, 0.f, 0.f, 0.f};
#pragma unroll
    for (int k = 0; k < KH; k++) {
        const float* wr = &w[k * 256 + lane * 8];
#pragma unroll
        for (int j = 0; j < 8; j++) pk[k] = fmaf(fv[j], wr[j], pk[k]);
    }
#pragma unroll
    for (int s = 16; s > 0; s >>= 1)
#pragma unroll
        for (int k = 0; k < KH; k++) pk[k] += __shfl_xor_sync(0xffffffffu, pk[k], s);
    if (lane == 0) {
#pragma unroll
        for (int k = 0; k < KH; k++) np[n * KH + k] = pk[k];
    }
}

// ---------------- batched CSR build ----------------
__global__ void csr_hist3(const int* __restrict__ d0, const int* __restrict__ d1,
                          const int* __restrict__ d2, int* __restrict__ counts)
{
    int e = blockIdx.x * blockDim.x + threadIdx.x;
    if (e >= EDG) return;
    atomicAdd(&counts[d0[e]], 1);
    atomicAdd(&counts[50000 + d1[e]], 1);
    atomicAdd(&counts[100000 + d2[e]], 1);
}

__global__ void scan_block(const int* __restrict__ in, int* __restrict__ out,
                           int* __restrict__ partials, int n)
{
    __shared__ int wsum[8];
    int i = blockIdx.x * 256 + threadIdx.x;
    int lane = threadIdx.x & 31, wid = threadIdx.x >> 5;
    int v = (i < n) ? in[i] : 0;
    int x = v;
#pragma unroll
    for (int o = 1; o < 32; o <<= 1) {
        int t = __shfl_up_sync(0xffffffffu, x, o);
        if (lane >= o) x += t;
    }
    if (lane == 31) wsum[wid] = x;
    __syncthreads();
    if (wid == 0) {
        int w = (lane < 8) ? wsum[lane] : 0;
#pragma unroll
        for (int o = 1; o < 8; o <<= 1) {
            int t = __shfl_up_sync(0xffffffffu, w, o);
            if (lane >= o) w += t;
        }
        if (lane < 8) wsum[lane] = w;
    }
    __syncthreads();
    int wpre = (wid > 0) ? wsum[wid - 1] : 0;
    if (i < n) out[i] = wpre + x - v;
    if (threadIdx.x == 0) partials[blockIdx.x] = wsum[7];
}

__global__ void scan_top1k(int* __restrict__ partials, int nb)
{
    __shared__ int wsum[32];
    int i = threadIdx.x;
    int lane = i & 31, wid = i >> 5;
    int v = (i < nb) ? partials[i] : 0;
    int x = v;
#pragma unroll
    for (int o = 1; o < 32; o <<= 1) {
        int t = __shfl_up_sync(0xffffffffu, x, o);
        if (lane >= o) x += t;
    }
    if (lane == 31) wsum[wid] = x;
    __syncthreads();
    if (wid == 0) {
        int w = wsum[lane];
#pragma unroll
        for (int o = 1; o < 32; o <<= 1) {
            int t = __shfl_up_sync(0xffffffffu, w, o);
            if (lane >= o) w += t;
        }
        wsum[lane] = w;
    }
    __syncthreads();
    int wpre = (wid > 0) ? wsum[wid - 1] : 0;
    if (i < nb) partials[i] = wpre + x - v;
    if (i == 0) partials[nb] = wsum[31];
}

__global__ void scan_add(int* __restrict__ offsets, int* __restrict__ cursor,
                         const int* __restrict__ partials, int n)
{
    int i = blockIdx.x * 256 + threadIdx.x;
    if (i < n) {
        int v = offsets[i] + partials[blockIdx.x];
        offsets[i] = v;
        cursor[i] = v;
    }
    if (i == 0) offsets[n] = partials[gridDim.x];
}

__global__ void csr_scatter3(
    const int* __restrict__ s0, const int* __restrict__ d0,
    const int* __restrict__ s1, const int* __restrict__ d1,
    const int* __restrict__ s2p, const int* __restrict__ d2,
    int* __restrict__ cursor, int* __restrict__ ssort)
{
    int idx = blockIdx.x * blockDim.x + threadIdx.x;
    if (idx >= 3 * EDG) return;
    int r = (idx >= 2 * EDG) ? 2 : (idx >= EDG) ? 1 : 0;
    int e = idx - r * EDG;
    const int* src = (r == 0) ? s0 : (r == 1) ? s1 : s2p;
    const int* dst = (r == 0) ? d0 : (r == 1) ? d1 : d2;
    int key = r * 50000 + dst[e];
    int pos = atomicAdd(&cursor[key], 1);
    ssort[pos] = src[e];
}

// ---------------- fused micro gather (fp16 in/out, 4-edge ILP, max-free softmax) ----------------
__global__ void micro_gather(const int* __restrict__ ssort, const int* __restrict__ offsets,
                             const float* __restrict__ el, const float* __restrict__ er,
                             const __half* __restrict__ Psrc, __half* __restrict__ ft, int n_dst)
{
    int d = (blockIdx.x * blockDim.x + threadIdx.x) >> 5;
    int lane = threadIdx.x & 31;
    if (d >= n_dst) return;
    int beg = offsets[d], end = offsets[d + 1];
    __half* dstp = &ft[(size_t)d * KD + lane * 8];
    if (beg == end) {
        float4 z = make_float4(0.f, 0.f, 0.f, 0.f);
        *(float4*)dstp = z;
        return;
    }
    float erh = (lane < KH) ? er[d * KH + lane] : 0.f;

    const int hk = lane >> 2;
    float acc[8] = {0.f, 0.f, 0.f, 0.f, 0.f, 0.f, 0.f, 0.f};
    float se = 0.f;
    int i = beg;
    for (; i + 4 <= end; i += 4) {
        int s0 = ssort[i], s1 = ssort[i + 1], s2e = ssort[i + 2], s3 = ssort[i + 3];
        float w0 = 0.f, w1 = 0.f, w2 = 0.f, w3 = 0.f;
        if (lane < KH) {
            w0 = __expf(leaky(el[s0 * KH + lane] + erh));
            w1 = __expf(leaky(el[s1 * KH + lane] + erh));
            w2 = __expf(leaky(el[s2e * KH + lane] + erh));
            w3 = __expf(leaky(el[s3 * KH + lane] + erh));
            se += (w0 + w1) + (w2 + w3);
        }
        float wk0 = __shfl_sync(0xffffffffu, w0, hk);
        float wk1 = __shfl_sync(0xffffffffu, w1, hk);
        float wk2 = __shfl_sync(0xffffffffu, w2, hk);
        float wk3 = __shfl_sync(0xffffffffu, w3, hk);
        float4 r0 = *(const float4*)&Psrc[(size_t)s0 * KD + lane * 8];
        float4 r1 = *(const float4*)&Psrc[(size_t)s1 * KD + lane * 8];
        float4 r2 = *(const float4*)&Psrc[(size_t)s2e * KD + lane * 8];
        float4 r3 = *(const float4*)&Psrc[(size_t)s3 * KD + lane * 8];
        const __half2* h0 = (const __half2*)&r0;
        const __half2* h1 = (const __half2*)&r1;
        const __half2* h2 = (const __half2*)&r2;
        const __half2* h3 = (const __half2*)&r3;
#pragma unroll
        for (int q = 0; q < 4; q++) {
            float2 f0 = __half22float2(h0[q]);
            float2 f1 = __half22float2(h1[q]);
            float2 f2 = __half22float2(h2[q]);
            float2 f3 = __half22float2(h3[q]);
            acc[q * 2 + 0] = fmaf(wk0, f0.x, acc[q * 2 + 0]);
            acc[q * 2 + 0] = fmaf(wk1, f1.x, acc[q * 2 + 0]);
            acc[q * 2 + 0] = fmaf(wk2, f2.x, acc[q * 2 + 0]);
            acc[q * 2 + 0] = fmaf(wk3, f3.x, acc[q * 2 + 0]);
            acc[q * 2 + 1] = fmaf(wk0, f0.y, acc[q * 2 + 1]);
            acc[q * 2 + 1] = fmaf(wk1, f1.y, acc[q * 2 + 1]);
            acc[q * 2 + 1] = fmaf(wk2, f2.y, acc[q * 2 + 1]);
            acc[q * 2 + 1] = fmaf(wk3, f3.y, acc[q * 2 + 1]);
        }
    }
    for (; i < end; i++) {
        int s0 = ssort[i];
        float w0 = 0.f;
        if (lane < KH) {
            w0 = __expf(leaky(el[s0 * KH + lane] + erh));
            se += w0;
        }
        float wk0 = __shfl_sync(0xffffffffu, w0, hk);
        float4 r0 = *(const float4*)&Psrc[(size_t)s0 * KD + lane * 8];
        const __half2* h0 = (const __half2*)&r0;
#pragma unroll
        for (int q = 0; q < 4; q++) {
            float2 f0 = __half22float2(h0[q]);
            acc[q * 2 + 0] = fmaf(wk0, f0.x, acc[q * 2 + 0]);
            acc[q * 2 + 1] = fmaf(wk0, f0.y, acc[q * 2 + 1]);
        }
    }
    float inv = 1.f / __shfl_sync(0xffffffffu, se, hk);
    float4 outv;
    __half2* op = (__half2*)&outv;
#pragma unroll
    for (int q = 0; q < 4; q++) {
        float vx = fmaxf(acc[q * 2 + 0] * inv, 0.f);
        float vy = fmaxf(acc[q * 2 + 1] * inv, 0.f);
        op[q] = __floats2half2_rn(vx, vy);
    }
    *(float4*)dstp = outv;
}

// ---------------- launch ----------------
extern "C" void kernel_launch(void* const* d_in, const int* in_sizes, int n_in,
                              void* d_out, int out_size)
{
    const float* feats_author    = (const float*)d_in[0];
    const float* feats_paper     = (const float*)d_in[1];
    const float* W_micro_author  = (const float*)d_in[2];
    const float* W_micro_paper   = (const float*)d_in[3];
    const float* attn_micro_a    = (const float*)d_in[4];
    const float* attn_micro_p    = (const float*)d_in[5];
    const float* W_macro_node_p  = (const float*)d_in[7];
    const float* W_rel_writes    = (const float*)d_in[8];
    const float* W_rel_wb        = (const float*)d_in[9];
    const float* W_rel_cites     = (const float*)d_in[10];
    const float* attn_macro      = (const float*)d_in[11];
    const float* W_res_author    = (const float*)d_in[12];
    const float* b_res_author    = (const float*)d_in[13];
    const float* W_res_paper     = (const float*)d_in[14];
    const float* b_res_paper     = (const float*)d_in[15];
    const float* res_w_author    = (const float*)d_in[16];
    const float* res_w_paper     = (const float*)d_in[17];
    const int*   writes_src      = (const int*)d_in[18];
    const int*   writes_dst      = (const int*)d_in[19];
    const int*   wb_src          = (const int*)d_in[20];
    const int*   wb_dst          = (const int*)d_in[21];
    const int*   cites_src       = (const int*)d_in[22];
    const int*   cites_dst       = (const int*)d_in[23];
    float* out = (float*)d_out;

    __half *PA, *PP, *ft_w, *ft_wb, *ft_c;
    float *elA_aA, *erP_aA, *elP_aP, *erA_aP, *erP_aP, *npscore, *Wnp;
    int *counts, *cursor, *offsets, *partials, *ssort;
    cudaGetSymbolAddress((void**)&PA, g_PA);
    cudaGetSymbolAddress((void**)&PP, g_PP);
    cudaGetSymbolAddress((void**)&elA_aA, g_elA_aA);
    cudaGetSymbolAddress((void**)&erP_aA, g_erP_aA);
    cudaGetSymbolAddress((void**)&elP_aP, g_elP_aP);
    cudaGetSymbolAddress((void**)&erA_aP, g_erA_aP);
    cudaGetSymbolAddress((void**)&erP_aP, g_erP_aP);
    cudaGetSymbolAddress((void**)&ft_w, g_ft_w);
    cudaGetSymbolAddress((void**)&ft_wb, g_ft_wb);
    cudaGetSymbolAddress((void**)&ft_c, g_ft_c);
    cudaGetSymbolAddress((void**)&npscore, g_npscore);
    cudaGetSymbolAddress((void**)&Wnp, g_Wnp);
    cudaGetSymbolAddress((void**)&counts, g_counts);
    cudaGetSymbolAddress((void**)&cursor, g_cursor);
    cudaGetSymbolAddress((void**)&offsets, g_offsets);
    cudaGetSymbolAddress((void**)&partials, g_partials);
    cudaGetSymbolAddress((void**)&ssort, g_ssort);

    static cudaStream_t s2 = nullptr;
    static cudaEvent_t evFork = nullptr, evA = nullptr, evP = nullptr,
                       ev2 = nullptr, evGW = nullptr, evS2 = nullptr;
    if (!s2) {
        cudaStreamCreateWithFlags(&s2, cudaStreamNonBlocking);
        cudaEventCreateWithFlags(&evFork, cudaEventDisableTiming);
        cudaEventCreateWithFlags(&evA, cudaEventDisableTiming);
        cudaEventCreateWithFlags(&evP, cudaEventDisableTiming);
        cudaEventCreateWithFlags(&ev2, cudaEventDisableTiming);
        cudaEventCreateWithFlags(&evGW, cudaEventDisableTiming);
        cudaEventCreateWithFlags(&evS2, cudaEventDisableTiming);
    }

    cudaFuncSetAttribute(gemm_multi, cudaFuncAttributeMaxDynamicSharedMemorySize, SMEM_BYTES);
    cudaFuncSetAttribute(gemm_rf_fused, cudaFuncAttributeMaxDynamicSharedMemorySize, FUSE_SMEM);
    cudaFuncSetAttribute(gemm_author_fused, cudaFuncAttributeMaxDynamicSharedMemorySize, FUSE_SMEM);

    const int GG = (NA + BM - 1) / BM;
    const int EB = (EDG + 255) / 256;
    const int EB3 = (3 * EDG + 255) / 256;
    const int GB = (NA * 32 + 255) / 256;
    const int NPB = (NP + 7) / 8;

    GemmJob jz = {};

    // ---- fork: s2 runs batched CSR build ----
    cudaEventRecord(evFork, 0);
    cudaStreamWaitEvent(s2, evFork, 0);
    cudaMemsetAsync(counts, 0, NTOT * sizeof(int), s2);
    csr_hist3<<<EB, 256, 0, s2>>>(writes_dst, wb_dst, cites_dst, counts);
    scan_block<<<NBLK3, 256, 0, s2>>>(counts, offsets, partials, NTOT);
    scan_top1k<<<1, 1024, 0, s2>>>(partials, NBLK3);
    scan_add<<<NBLK3, 256, 0, s2>>>(offsets, cursor, partials, NTOT);
    csr_scatter3<<<EB3, 256, 0, s2>>>(writes_src, writes_dst, wb_src, wb_dst,
                                      cites_src, cites_dst, cursor, ssort);

    // ---- main: Wnp precompute + author micro GEMM ----
    wnp_k<<<KH, 256>>>(W_macro_node_p, attn_macro, Wnp);
    {
        GemmJob ja = { feats_author, W_micro_author, nullptr, PA, nullptr, nullptr,
                       attn_micro_a + 0,  elA_aA,
                       attn_micro_p + 32, erA_aP,
                       nullptr, nullptr };
        gemm_multi<<<GG, 256, SMEM_BYTES>>>(ja, jz, jz, 1, NA);
    }
    cudaEventRecord(evA, 0);

    // ---- s2: paper micro GEMM ----
    {
        GemmJob ja = { feats_paper, W_micro_paper, nullptr, PP, nullptr, nullptr,
                       attn_micro_a + 32, erP_aA,
                       attn_micro_p + 0,  elP_aP,
                       attn_micro_p + 32, erP_aP };
        gemm_multi<<<GG, 256, SMEM_BYTES, s2>>>(ja, jz, jz, 1, NP);
    }
    cudaEventRecord(evP, s2);

    // ---- s2: gather cites ----
    micro_gather<<<GB, 256, 0, s2>>>(ssort, offsets + 2 * 50000,
                                     elP_aP, erP_aP, PP, ft_c, NP);

    // ---- main: npscore (skinny) + res_paper GEMM ----
    npscore_k<<<NPB, 256>>>(feats_paper, Wnp, npscore, NP);
    {
        GemmJob jb = { feats_paper, W_res_paper, out + (size_t)NA * KD, nullptr,
                       b_res_paper, nullptr,
                       nullptr, nullptr, nullptr, nullptr, nullptr, nullptr };
        gemm_multi<<<GG, 256, SMEM_BYTES>>>(jb, jz, jz, 1, NP);
    }
    cudaEventRecord(ev2, 0);

    // ---- main: gathers writes + written_by (need CSR + micro_P via evP) ----
    cudaStreamWaitEvent(0, evP, 0);
    micro_gather<<<GB, 256, 0, 0>>>(ssort, offsets + 0 * 50000,
                                    elA_aA, erP_aA, PA, ft_w, NP);
    cudaEventRecord(evGW, 0);
    micro_gather<<<GB, 256, 0, 0>>>(ssort, offsets + 1 * 50000,
                                    elP_aP, erA_aP, PP, ft_wb, NA);

    // ---- main: fused author -> out[:NA] ----
    gemm_author_fused<<<GG, 256, FUSE_SMEM>>>(feats_author, W_res_author, b_res_author,
                                              ft_wb, W_rel_wb, res_w_author, out, NA);

    // ---- s2: fused rf + semantic attention + gated residual -> out[NA:] ----
    cudaStreamWaitEvent(s2, ev2, 0);    // npscore + res_paper
    cudaStreamWaitEvent(s2, evGW, 0);   // ft_w
    gemm_rf_fused<<<GG, 256, FUSE_SMEM, s2>>>(ft_w, W_rel_writes, ft_c, W_rel_cites,
                                              npscore, attn_macro, res_w_paper,
                                              out + (size_t)NA * KD, NP);
    cudaEventRecord(evS2, s2);

    // ---- join ----
    cudaStreamWaitEvent(0, evS2, 0);
    join_k<<<1, 1>>>();
}

// round 17
// speedup vs baseline: 1.3477x; 1.0762x over previous
#include <cuda_runtime.h>
#include <cuda_fp16.h>
#include <cstdint>
#include <math.h>

// ---------------- problem constants ----------------
#define NA 50000
#define NP 50000
#define EDG 400000
#define KH 8
#define DH 32
#define KD 256
#define SLOPE 0.2f

// GEMM tiling
#define BM 128
#define BK 16
#define NKT (KD / BK)
#define LDK 20
#define LDBN 264
#define ASZ (128 * LDK)
#define BSZ (BK * LDBN)
#define SMEM_BYTES ((2 * ASZ + 2 * BSZ) * 4)     // 54272
#define RFLD 260
#define FUSE_SMEM (SMEM_BYTES + 128 * RFLD * 4)  // 187392 (author_fused, fp32 buf)
#define RFLD2 264
#define FUSE3_SMEM (SMEM_BYTES + 2 * 128 * RFLD2 * 2)  // 189440 (rf_fused3, 2 fp16 bufs)

#define NTOT 150000
#define NBLK3 ((NTOT + 255) / 256)     // 586

// ---------------- device scratch ----------------
__device__ __half g_PA[NA * KD];
__device__ __half g_PP[NP * KD];

__device__ float g_elA_aA[NA * KH];
__device__ float g_erP_aA[NP * KH];
__device__ float g_elP_aP[NP * KH];
__device__ float g_erA_aP[NA * KH];
__device__ float g_erP_aP[NP * KH];

__device__ __half g_ft_w[NP * KD];
__device__ __half g_ft_wb[NA * KD];
__device__ __half g_ft_c[NP * KD];

__device__ float g_npscore[NP * KH];
__device__ float g_Wnp[KH * 256];

// CSR scratch (combined)
__device__ int g_counts[NTOT];
__device__ int g_cursor[NTOT];
__device__ int g_offsets[NTOT + 1];
__device__ int g_partials[NBLK3 + 2];
__device__ int g_ssort[3 * EDG];

// ---------------- helpers ----------------
__device__ __forceinline__ float leaky(float v) {
    return v > 0.f ? v : SLOPE * v;
}
__device__ __forceinline__ uint32_t f2tf32(float f) {
    uint32_t r;
    asm("cvt.rna.tf32.f32 %0, %1;" : "=r"(r) : "f"(f));
    return r;
}
__device__ __forceinline__ void mma_tf32(float c[4], uint32_t a0, uint32_t a1,
                                         uint32_t a2, uint32_t a3,
                                         uint32_t b0, uint32_t b1) {
    asm volatile(
        "mma.sync.aligned.m16n8k8.row.col.f32.tf32.tf32.f32 "
        "{%0,%1,%2,%3}, {%4,%5,%6,%7}, {%8,%9}, {%0,%1,%2,%3};"
        : "+f"(c[0]), "+f"(c[1]), "+f"(c[2]), "+f"(c[3])
        : "r"(a0), "r"(a1), "r"(a2), "r"(a3), "r"(b0), "r"(b1));
}

struct GemmJob {
    const float* A;
    const float* B;
    float*       C;
    __half*      Ch;
    const float* bias;
    const float* gate;
    const float* av0; float* ao0;
    const float* av1; float* ao1;
    const float* av2; float* ao2;
};

#define GEMM_PROLOGUE() \
    const int tid = threadIdx.x; \
    const int lane = tid & 31; \
    const int wid = tid >> 5; \
    const int wm = (wid & 1) * 64; \
    const int wn = (wid >> 1) * 64; \
    const int m0 = blockIdx.x * BM; \
    const int qr = lane >> 2; \
    const int qc = lane & 3; \
    const int am = tid >> 1; \
    const int aq = (tid & 1) * 8; \
    const int bkr = tid >> 4; \
    const int bnc = (tid & 15) * 16; \
    float4 rA[2], rB[4]; \
    auto g_load = [&](int kt, const float* __restrict__ A, const float* __restrict__ B) { \
        const int k0 = kt * BK; \
        int row = m0 + am; \
        if (row < M) { \
            rA[0] = *(const float4*)&A[(size_t)row * KD + k0 + aq]; \
            rA[1] = *(const float4*)&A[(size_t)row * KD + k0 + aq + 4]; \
        } else { \
            rA[0] = make_float4(0.f, 0.f, 0.f, 0.f); \
            rA[1] = rA[0]; \
        } \
        const float* bp = &B[(size_t)(k0 + bkr) * KD + bnc]; \
        rB[0] = *(const float4*)&bp[0]; \
        rB[1] = *(const float4*)&bp[4]; \
        rB[2] = *(const float4*)&bp[8]; \
        rB[3] = *(const float4*)&bp[12]; \
    }; \
    auto g_load_h = [&](int kt, const __half* __restrict__ Ah, const float* __restrict__ B) { \
        const int k0 = kt * BK; \
        int row = m0 + am; \
        if (row < M) { \
            float4 raw = *(const float4*)&Ah[(size_t)row * KD + k0 + aq]; \
            const __half2* hp = (const __half2*)&raw; \
            float2 f0 = __half22float2(hp[0]); \
            float2 f1 = __half22float2(hp[1]); \
            float2 f2 = __half22float2(hp[2]); \
            float2 f3 = __half22float2(hp[3]); \
            rA[0] = make_float4(f0.x, f0.y, f1.x, f1.y); \
            rA[1] = make_float4(f2.x, f2.y, f3.x, f3.y); \
        } else { \
            rA[0] = make_float4(0.f, 0.f, 0.f, 0.f); \
            rA[1] = rA[0]; \
        } \
        const float* bp = &B[(size_t)(k0 + bkr) * KD + bnc]; \
        rB[0] = *(const float4*)&bp[0]; \
        rB[1] = *(const float4*)&bp[4]; \
        rB[2] = *(const float4*)&bp[8]; \
        rB[3] = *(const float4*)&bp[12]; \
    }; \
    auto s_store = [&](int buf) { \
        uint32_t* as = &smem[buf * ASZ + am * LDK + aq]; \
        uint4 v0, v1; \
        v0.x = f2tf32(rA[0].x); v0.y = f2tf32(rA[0].y); \
        v0.z = f2tf32(rA[0].z); v0.w = f2tf32(rA[0].w); \
        v1.x = f2tf32(rA[1].x); v1.y = f2tf32(rA[1].y); \
        v1.z = f2tf32(rA[1].z); v1.w = f2tf32(rA[1].w); \
        *(uint4*)&as[0] = v0; \
        *(uint4*)&as[4] = v1; \
        uint32_t* bs = &smem[2 * ASZ + buf * BSZ + bkr * LDBN + bnc]; \
        _Pragma("unroll") \
        for (int q = 0; q < 4; q++) { \
            uint4 w; \
            w.x = f2tf32(((const float*)&rB[q])[0]); \
            w.y = f2tf32(((const float*)&rB[q])[1]); \
            w.z = f2tf32(((const float*)&rB[q])[2]); \
            w.w = f2tf32(((const float*)&rB[q])[3]); \
            *(uint4*)&bs[q * 4] = w; \
        } \
    };

#define GEMM_MAINLOOP_GEN(loader, Aptr, Bptr) \
    { \
        float (*accp)[8][4] = acc; \
        loader(0, Aptr, Bptr); \
        s_store(0); \
        __syncthreads(); \
        for (int kt = 0; kt < NKT; kt++) { \
            const int cur = kt & 1; \
            if (kt + 1 < NKT) loader(kt + 1, Aptr, Bptr); \
            const uint32_t* asb = &smem[cur * ASZ]; \
            const uint32_t* bsb = &smem[2 * ASZ + cur * BSZ]; \
            _Pragma("unroll") \
            for (int ks = 0; ks < BK; ks += 8) { \
                uint32_t a[4][4], b[8][2]; \
                _Pragma("unroll") \
                for (int mi = 0; mi < 4; mi++) { \
                    int r0 = wm + mi * 16 + qr; \
                    a[mi][0] = asb[r0 * LDK + ks + qc]; \
                    a[mi][1] = asb[(r0 + 8) * LDK + ks + qc]; \
                    a[mi][2] = asb[r0 * LDK + ks + qc + 4]; \
                    a[mi][3] = asb[(r0 + 8) * LDK + ks + qc + 4]; \
                } \
                _Pragma("unroll") \
                for (int ni = 0; ni < 8; ni++) { \
                    int c0 = wn + ni * 8 + qr; \
                    b[ni][0] = bsb[(ks + qc) * LDBN + c0]; \
                    b[ni][1] = bsb[(ks + qc + 4) * LDBN + c0]; \
                } \
                _Pragma("unroll") \
                for (int mi = 0; mi < 4; mi++) \
                    _Pragma("unroll") \
                    for (int ni = 0; ni < 8; ni++) \
                        mma_tf32(accp[mi][ni], a[mi][0], a[mi][1], a[mi][2], a[mi][3], \
                                 b[ni][0], b[ni][1]); \
            } \
            if (kt + 1 < NKT) { \
                s_store(1 - cur); \
                __syncthreads(); \
            } \
        } \
    }

#define ACC_ZERO() \
    _Pragma("unroll") \
    for (int mi = 0; mi < 4; mi++) \
        _Pragma("unroll") \
        for (int ni = 0; ni < 8; ni++) \
            _Pragma("unroll") \
            for (int r = 0; r < 4; r++) acc[mi][ni][r] = 0.f;

// ================= multi-job tf32 GEMM (fp32 A) =================
__global__ void __launch_bounds__(256, 1) gemm_multi(
    GemmJob j0, GemmJob j1, GemmJob j2, int nb, int M)
{
    extern __shared__ uint32_t smem[];
    GEMM_PROLOGUE();

#pragma unroll
    for (int o = 0; o < 3; o++) {
        if (o >= nb) break;
        const GemmJob J = (o == 0) ? j0 : (o == 1) ? j1 : j2;

        float acc[4][8][4];
        ACC_ZERO();
        GEMM_MAINLOOP_GEN(g_load, J.A, J.B);

        if (J.av0) {
            const float* avs[3] = { J.av0, J.av1, J.av2 };
            float*       aos[3] = { J.ao0, J.ao1, J.ao2 };
            const int h0 = wn >> 5;
#pragma unroll
            for (int t = 0; t < 3; t++) {
                const float* av = avs[t];
                if (!av) break;
                float* ao = aos[t];
                float c0[8], c1[8];
#pragma unroll
                for (int ni = 0; ni < 8; ni++) {
                    int col = wn + ni * 8 + qc * 2;
                    int idx = (col >> 5) * 64 + (col & 31);
                    c0[ni] = av[idx];
                    c1[ni] = av[idx + 1];
                }
#pragma unroll
                for (int mi = 0; mi < 4; mi++) {
#pragma unroll
                    for (int half = 0; half < 2; half++) {
                        float pa = 0.f, pb = 0.f;
#pragma unroll
                        for (int ni = 0; ni < 4; ni++)
                            pa += acc[mi][ni][half * 2] * c0[ni]
                                + acc[mi][ni][half * 2 + 1] * c1[ni];
#pragma unroll
                        for (int ni = 4; ni < 8; ni++)
                            pb += acc[mi][ni][half * 2] * c0[ni]
                                + acc[mi][ni][half * 2 + 1] * c1[ni];
                        pa += __shfl_xor_sync(0xffffffffu, pa, 1);
                        pa += __shfl_xor_sync(0xffffffffu, pa, 2);
                        pb += __shfl_xor_sync(0xffffffffu, pb, 1);
                        pb += __shfl_xor_sync(0xffffffffu, pb, 2);
                        int row = m0 + wm + mi * 16 + qr + half * 8;
                        if (qc == 0 && row < M) {
                            ao[row * KH + h0]     = pa;
                            ao[row * KH + h0 + 1] = pb;
                        }
                    }
                }
            }
        }

        if (J.Ch) {
#pragma unroll
            for (int mi = 0; mi < 4; mi++) {
#pragma unroll
                for (int half = 0; half < 2; half++) {
                    int row = m0 + wm + mi * 16 + qr + half * 8;
                    if (row >= M) continue;
                    __half* dst = &J.Ch[(size_t)row * KD + wn];
#pragma unroll
                    for (int ni = 0; ni < 8; ni++) {
                        int col = ni * 8 + qc * 2;
                        *(__half2*)&dst[col] = __floats2half2_rn(
                            acc[mi][ni][half * 2 + 0], acc[mi][ni][half * 2 + 1]);
                    }
                }
            }
        } else if (J.C) {
            float g = 0.f;
            if (J.gate) g = 1.f / (1.f + __expf(-J.gate[0]));
#pragma unroll
            for (int mi = 0; mi < 4; mi++) {
#pragma unroll
                for (int half = 0; half < 2; half++) {
                    int row = m0 + wm + mi * 16 + qr + half * 8;
                    if (row >= M) continue;
                    float* dst = &J.C[(size_t)row * KD + wn];
#pragma unroll
                    for (int ni = 0; ni < 8; ni++) {
                        int col = ni * 8 + qc * 2;
                        float2 v;
                        v.x = acc[mi][ni][half * 2 + 0];
                        v.y = acc[mi][ni][half * 2 + 1];
                        if (J.bias) {
                            v.x += J.bias[wn + col + 0];
                            v.y += J.bias[wn + col + 1];
                        }
                        if (J.gate) {
                            float2 prev = *(const float2*)&dst[col];
                            v.x = g * v.x + (1.f - g) * prev.x;
                            v.y = g * v.y + (1.f - g) * prev.y;
                        }
                        *(float2*)&dst[col] = v;
                    }
                }
            }
        }
        __syncthreads();
    }
}

// ===== fused paper epilogue: res_paper + rf_w + rf_c + semantic attention + gated residual =====
__global__ void __launch_bounds__(256, 1) gemm_rf_fused3(
    const float* __restrict__ Ares, const float* __restrict__ Bres,
    const float* __restrict__ bias,
    const __half* __restrict__ Aw, const float* __restrict__ Bw,
    const __half* __restrict__ Ac, const float* __restrict__ Bc,
    const float* __restrict__ npscore, const float* __restrict__ attnM,
    const float* __restrict__ resw, float* __restrict__ outP, int M)
{
    extern __shared__ uint32_t smem[];
    __half* resbuf = (__half*)(smem + 2 * ASZ + 2 * BSZ);
    __half* rwbuf  = resbuf + 128 * RFLD2;
    GEMM_PROLOGUE();

    // job 0: res_paper (+bias) -> fp16 smem
    {
        float acc[4][8][4];
        ACC_ZERO();
        GEMM_MAINLOOP_GEN(g_load, Ares, Bres);
#pragma unroll
        for (int mi = 0; mi < 4; mi++)
#pragma unroll
            for (int half = 0; half < 2; half++) {
                int lr = wm + mi * 16 + qr + half * 8;
                __half* dst = &resbuf[lr * RFLD2 + wn];
#pragma unroll
                for (int ni = 0; ni < 8; ni++) {
                    int col = ni * 8 + qc * 2;
                    *(__half2*)&dst[col] = __floats2half2_rn(
                        acc[mi][ni][half * 2 + 0] + bias[wn + col + 0],
                        acc[mi][ni][half * 2 + 1] + bias[wn + col + 1]);
                }
            }
        __syncthreads();
    }

    // job 1: rf_w -> fp16 smem
    {
        float acc[4][8][4];
        ACC_ZERO();
        GEMM_MAINLOOP_GEN(g_load_h, Aw, Bw);
#pragma unroll
        for (int mi = 0; mi < 4; mi++)
#pragma unroll
            for (int half = 0; half < 2; half++) {
                int lr = wm + mi * 16 + qr + half * 8;
                __half* dst = &rwbuf[lr * RFLD2 + wn];
#pragma unroll
                for (int ni = 0; ni < 8; ni++) {
                    int col = ni * 8 + qc * 2;
                    *(__half2*)&dst[col] = __floats2half2_rn(
                        acc[mi][ni][half * 2 + 0], acc[mi][ni][half * 2 + 1]);
                }
            }
        __syncthreads();
    }

    // job 2: rf_c in registers + fusion epilogue
    {
        float acc[4][8][4];
        ACC_ZERO();
        GEMM_MAINLOOP_GEN(g_load_h, Ac, Bc);

        const float g = 1.f / (1.f + __expf(-resw[0]));
        const int h0 = wn >> 5;
        float cr0[8], cr1[8];
#pragma unroll
        for (int ni = 0; ni < 8; ni++) {
            int col = wn + ni * 8 + qc * 2;
            int base = (col >> 5) * 64 + (col & 31);
            cr0[ni] = attnM[base + 32];
            cr1[ni] = attnM[base + 33];
        }

#pragma unroll
        for (int mi = 0; mi < 4; mi++) {
#pragma unroll
            for (int half = 0; half < 2; half++) {
                int lr = wm + mi * 16 + qr + half * 8;
                int row = m0 + lr;
                if (row >= M) continue;
                const __half* rwrow = &rwbuf[lr * RFLD2 + wn];
                const __half* resrow = &resbuf[lr * RFLD2 + wn];
                float* orow = &outP[(size_t)row * KD + wn];
                float npa = npscore[row * KH + h0];
                float npb = npscore[row * KH + h0 + 1];

                float rw[16];
#pragma unroll
                for (int ni = 0; ni < 8; ni++) {
                    float2 f = __half22float2(*(const __half2*)&rwrow[ni * 8 + qc * 2]);
                    rw[ni * 2] = f.x; rw[ni * 2 + 1] = f.y;
                }

                float swa = 0.f, sca = 0.f, swb = 0.f, scb = 0.f;
#pragma unroll
                for (int ni = 0; ni < 8; ni++) {
                    float rw0 = rw[ni * 2], rw1 = rw[ni * 2 + 1];
                    float rc0 = acc[mi][ni][half * 2], rc1 = acc[mi][ni][half * 2 + 1];
                    float wpart = rw0 * cr0[ni] + rw1 * cr1[ni];
                    float cpart = rc0 * cr0[ni] + rc1 * cr1[ni];
                    if (ni < 4) { swa += wpart; sca += cpart; }
                    else        { swb += wpart; scb += cpart; }
                }
                swa += __shfl_xor_sync(0xffffffffu, swa, 1);
                swa += __shfl_xor_sync(0xffffffffu, swa, 2);
                sca += __shfl_xor_sync(0xffffffffu, sca, 1);
                sca += __shfl_xor_sync(0xffffffffu, sca, 2);
                swb += __shfl_xor_sync(0xffffffffu, swb, 1);
                swb += __shfl_xor_sync(0xffffffffu, swb, 2);
                scb += __shfl_xor_sync(0xffffffffu, scb, 1);
                scb += __shfl_xor_sync(0xffffffffu, scb, 2);

                float swA = leaky(npa + swa), scA = leaky(npa + sca);
                float swB = leaky(npb + swb), scB = leaky(npb + scb);
                float ma = fmaxf(swA, scA);
                float ea = __expf(swA - ma), eca = __expf(scA - ma);
                float awa = ea / (ea + eca);
                float mb = fmaxf(swB, scB);
                float eb = __expf(swB - mb), ecb = __expf(scB - mb);
                float awb = eb / (eb + ecb);

#pragma unroll
                for (int ni = 0; ni < 8; ni++) {
                    int col = ni * 8 + qc * 2;
                    float aw = (ni < 4) ? awa : awb;
                    float rw0 = rw[ni * 2], rw1 = rw[ni * 2 + 1];
                    float rc0 = acc[mi][ni][half * 2], rc1 = acc[mi][ni][half * 2 + 1];
                    float2 res = __half22float2(*(const __half2*)&resrow[col]);
                    float2 v;
                    v.x = g * (aw * rw0 + (1.f - aw) * rc0) + (1.f - g) * res.x;
                    v.y = g * (aw * rw1 + (1.f - aw) * rc1) + (1.f - g) * res.y;
                    *(float2*)&orow[col] = v;
                }
            }
        }
    }
}

// ================= fused author =================
__global__ void __launch_bounds__(256, 1) gemm_author_fused(
    const float* __restrict__ Ares, const float* __restrict__ Bres,
    const float* __restrict__ bias,
    const __half* __restrict__ Awb, const float* __restrict__ Bwb,
    const float* __restrict__ gate, float* __restrict__ outA, int M)
{
    extern __shared__ uint32_t smem[];
    float* rfbuf = (float*)(smem + 2 * ASZ + 2 * BSZ);
    GEMM_PROLOGUE();

    {
        float acc[4][8][4];
        ACC_ZERO();
        GEMM_MAINLOOP_GEN(g_load, Ares, Bres);
#pragma unroll
        for (int mi = 0; mi < 4; mi++)
#pragma unroll
            for (int half = 0; half < 2; half++) {
                int lr = wm + mi * 16 + qr + half * 8;
                float* dst = &rfbuf[lr * RFLD + wn];
#pragma unroll
                for (int ni = 0; ni < 8; ni++) {
                    int col = ni * 8 + qc * 2;
                    dst[col]     = acc[mi][ni][half * 2 + 0] + bias[wn + col + 0];
                    dst[col + 1] = acc[mi][ni][half * 2 + 1] + bias[wn + col + 1];
                }
            }
        __syncthreads();
    }

    {
        float acc[4][8][4];
        ACC_ZERO();
        GEMM_MAINLOOP_GEN(g_load_h, Awb, Bwb);

        const float g = 1.f / (1.f + __expf(-gate[0]));
#pragma unroll
        for (int mi = 0; mi < 4; mi++) {
#pragma unroll
            for (int half = 0; half < 2; half++) {
                int lr = wm + mi * 16 + qr + half * 8;
                int row = m0 + lr;
                if (row >= M) continue;
                const float* resrow = &rfbuf[lr * RFLD + wn];
                float* orow = &outA[(size_t)row * KD + wn];
#pragma unroll
                for (int ni = 0; ni < 8; ni++) {
                    int col = ni * 8 + qc * 2;
                    float2 v;
                    v.x = g * acc[mi][ni][half * 2 + 0] + (1.f - g) * resrow[col];
                    v.y = g * acc[mi][ni][half * 2 + 1] + (1.f - g) * resrow[col + 1];
                    *(float2*)&orow[col] = v;
                }
            }
        }
    }
}

// trailing join node
__global__ void join_k() {}

// ---------------- Wnp precompute ----------------
__global__ void wnp_k(const float* __restrict__ W, const float* __restrict__ attnM,
                      float* __restrict__ WnpT)
{
    int i = threadIdx.x;
    int k = blockIdx.x;
    float s = 0.f;
#pragma unroll
    for (int d = 0; d < DH; d++)
        s = fmaf(W[i * KD + k * DH + d], attnM[k * 64 + d], s);
    WnpT[k * 256 + i] = s;
}

// ---------------- npscore ----------------
__global__ void __launch_bounds__(256) npscore_k(
    const float* __restrict__ feats, const float* __restrict__ WnpT,
    float* __restrict__ np, int N)
{
    __shared__ float w[KH * 256];
    for (int i = threadIdx.x; i < KH * 256; i += 256) w[i] = WnpT[i];
    __syncthreads();
    int warp = threadIdx.x >> 5, lane = threadIdx.x & 31;
    int n = blockIdx.x * 8 + warp;
    if (n >= N) return;
    const float4* f = (const float4*)&feats[(size_t)n * KD + lane * 8];
    float4 f0 = f[0], f1 = f[1];
    float fv[8] = { f0.x, f0.y, f0.z, f0.w, f1.x, f1.y, f1.z, f1.w };
    float pk[KH] = {0.f, 0.f, 0.f, 0.f, 0.f, 0.f, 0.f, 0.f};
#pragma unroll
    for (int k = 0; k < KH; k++) {
        const float* wr = &w[k * 256 + lane * 8];
#pragma unroll
        for (int j = 0; j < 8; j++) pk[k] = fmaf(fv[j], wr[j], pk[k]);
    }
#pragma unroll
    for (int s = 16; s > 0; s >>= 1)
#pragma unroll
        for (int k = 0; k < KH; k++) pk[k] += __shfl_xor_sync(0xffffffffu, pk[k], s);
    if (lane == 0) {
#pragma unroll
        for (int k = 0; k < KH; k++) np[n * KH + k] = pk[k];
    }
}

// ---------------- batched CSR build ----------------
__global__ void csr_hist3(const int* __restrict__ d0, const int* __restrict__ d1,
                          const int* __restrict__ d2, int* __restrict__ counts)
{
    int e = blockIdx.x * blockDim.x + threadIdx.x;
    if (e >= EDG) return;
    atomicAdd(&counts[d0[e]], 1);
    atomicAdd(&counts[50000 + d1[e]], 1);
    atomicAdd(&counts[100000 + d2[e]], 1);
}

__global__ void scan_block(const int* __restrict__ in, int* __restrict__ out,
                           int* __restrict__ partials, int n)
{
    __shared__ int wsum[8];
    int i = blockIdx.x * 256 + threadIdx.x;
    int lane = threadIdx.x & 31, wid = threadIdx.x >> 5;
    int v = (i < n) ? in[i] : 0;
    int x = v;
#pragma unroll
    for (int o = 1; o < 32; o <<= 1) {
        int t = __shfl_up_sync(0xffffffffu, x, o);
        if (lane >= o) x += t;
    }
    if (lane == 31) wsum[wid] = x;
    __syncthreads();
    if (wid == 0) {
        int w = (lane < 8) ? wsum[lane] : 0;
#pragma unroll
        for (int o = 1; o < 8; o <<= 1) {
            int t = __shfl_up_sync(0xffffffffu, w, o);
            if (lane >= o) w += t;
        }
        if (lane < 8) wsum[lane] = w;
    }
    __syncthreads();
    int wpre = (wid > 0) ? wsum[wid - 1] : 0;
    if (i < n) out[i] = wpre + x - v;
    if (threadIdx.x == 0) partials[blockIdx.x] = wsum[7];
}

__global__ void scan_top1k(int* __restrict__ partials, int nb)
{
    __shared__ int wsum[32];
    int i = threadIdx.x;
    int lane = i & 31, wid = i >> 5;
    int v = (i < nb) ? partials[i] : 0;
    int x = v;
#pragma unroll
    for (int o = 1; o < 32; o <<= 1) {
        int t = __shfl_up_sync(0xffffffffu, x, o);
        if (lane >= o) x += t;
    }
    if (lane == 31) wsum[wid] = x;
    __syncthreads();
    if (wid == 0) {
        int w = wsum[lane];
#pragma unroll
        for (int o = 1; o < 32; o <<= 1) {
            int t = __shfl_up_sync(0xffffffffu, w, o);
            if (lane >= o) w += t;
        }
        wsum[lane] = w;
    }
    __syncthreads();
    int wpre = (wid > 0) ? wsum[wid - 1] : 0;
    if (i < nb) partials[i] = wpre + x - v;
    if (i == 0) partials[nb] = wsum[31];
}

__global__ void scan_add(int* __restrict__ offsets, int* __restrict__ cursor,
                         const int* __restrict__ partials, int n)
{
    int i = blockIdx.x * 256 + threadIdx.x;
    if (i < n) {
        int v = offsets[i] + partials[blockIdx.x];
        offsets[i] = v;
        cursor[i] = v;
    }
    if (i == 0) offsets[n] = partials[gridDim.x];
}

__global__ void csr_scatter3(
    const int* __restrict__ s0, const int* __restrict__ d0,
    const int* __restrict__ s1, const int* __restrict__ d1,
    const int* __restrict__ s2p, const int* __restrict__ d2,
    int* __restrict__ cursor, int* __restrict__ ssort)
{
    int idx = blockIdx.x * blockDim.x + threadIdx.x;
    if (idx >= 3 * EDG) return;
    int r = (idx >= 2 * EDG) ? 2 : (idx >= EDG) ? 1 : 0;
    int e = idx - r * EDG;
    const int* src = (r == 0) ? s0 : (r == 1) ? s1 : s2p;
    const int* dst = (r == 0) ? d0 : (r == 1) ? d1 : d2;
    int key = r * 50000 + dst[e];
    int pos = atomicAdd(&cursor[key], 1);
    ssort[pos] = src[e];
}

// ---------------- fused micro gather (fp16 in/out, 4-edge ILP) ----------------
__global__ void micro_gather(const int* __restrict__ ssort, const int* __restrict__ offsets,
                             const float* __restrict__ el, const float* __restrict__ er,
                             const __half* __restrict__ Psrc, __half* __restrict__ ft, int n_dst)
{
    int d = (blockIdx.x * blockDim.x + threadIdx.x) >> 5;
    int lane = threadIdx.x & 31;
    if (d >= n_dst) return;
    int beg = offsets[d], end = offsets[d + 1];
    __half* dstp = &ft[(size_t)d * KD + lane * 8];
    if (beg == end) {
        float4 z = make_float4(0.f, 0.f, 0.f, 0.f);
        *(float4*)dstp = z;
        return;
    }
    float erh = (lane < KH) ? er[d * KH + lane] : 0.f;

    const int hk = lane >> 2;
    float acc[8] = {0.f, 0.f, 0.f, 0.f, 0.f, 0.f, 0.f, 0.f};
    float se = 0.f;
    int i = beg;
    for (; i + 4 <= end; i += 4) {
        int s0 = ssort[i], s1 = ssort[i + 1], s2e = ssort[i + 2], s3 = ssort[i + 3];
        float w0 = 0.f, w1 = 0.f, w2 = 0.f, w3 = 0.f;
        if (lane < KH) {
            w0 = __expf(leaky(el[s0 * KH + lane] + erh));
            w1 = __expf(leaky(el[s1 * KH + lane] + erh));
            w2 = __expf(leaky(el[s2e * KH + lane] + erh));
            w3 = __expf(leaky(el[s3 * KH + lane] + erh));
            se += (w0 + w1) + (w2 + w3);
        }
        float wk0 = __shfl_sync(0xffffffffu, w0, hk);
        float wk1 = __shfl_sync(0xffffffffu, w1, hk);
        float wk2 = __shfl_sync(0xffffffffu, w2, hk);
        float wk3 = __shfl_sync(0xffffffffu, w3, hk);
        float4 r0 = *(const float4*)&Psrc[(size_t)s0 * KD + lane * 8];
        float4 r1 = *(const float4*)&Psrc[(size_t)s1 * KD + lane * 8];
        float4 r2 = *(const float4*)&Psrc[(size_t)s2e * KD + lane * 8];
        float4 r3 = *(const float4*)&Psrc[(size_t)s3 * KD + lane * 8];
        const __half2* h0 = (const __half2*)&r0;
        const __half2* h1 = (const __half2*)&r1;
        const __half2* h2 = (const __half2*)&r2;
        const __half2* h3 = (const __half2*)&r3;
#pragma unroll
        for (int q = 0; q < 4; q++) {
            float2 f0 = __half22float2(h0[q]);
            float2 f1 = __half22float2(h1[q]);
            float2 f2 = __half22float2(h2[q]);
            float2 f3 = __half22float2(h3[q]);
            acc[q * 2 + 0] = fmaf(wk0, f0.x, acc[q * 2 + 0]);
            acc[q * 2 + 0] = fmaf(wk1, f1.x, acc[q * 2 + 0]);
            acc[q * 2 + 0] = fmaf(wk2, f2.x, acc[q * 2 + 0]);
            acc[q * 2 + 0] = fmaf(wk3, f3.x, acc[q * 2 + 0]);
            acc[q * 2 + 1] = fmaf(wk0, f0.y, acc[q * 2 + 1]);
            acc[q * 2 + 1] = fmaf(wk1, f1.y, acc[q * 2 + 1]);
            acc[q * 2 + 1] = fmaf(wk2, f2.y, acc[q * 2 + 1]);
            acc[q * 2 + 1] = fmaf(wk3, f3.y, acc[q * 2 + 1]);
        }
    }
    for (; i < end; i++) {
        int s0 = ssort[i];
        float w0 = 0.f;
        if (lane < KH) {
            w0 = __expf(leaky(el[s0 * KH + lane] + erh));
            se += w0;
        }
        float wk0 = __shfl_sync(0xffffffffu, w0, hk);
        float4 r0 = *(const float4*)&Psrc[(size_t)s0 * KD + lane * 8];
        const __half2* h0 = (const __half2*)&r0;
#pragma unroll
        for (int q = 0; q < 4; q++) {
            float2 f0 = __half22float2(h0[q]);
            acc[q * 2 + 0] = fmaf(wk0, f0.x, acc[q * 2 + 0]);
            acc[q * 2 + 1] = fmaf(wk0, f0.y, acc[q * 2 + 1]);
        }
    }
    float inv = 1.f / __shfl_sync(0xffffffffu, se, hk);
    float4 outv;
    __half2* op = (__half2*)&outv;
#pragma unroll
    for (int q = 0; q < 4; q++) {
        float vx = fmaxf(acc[q * 2 + 0] * inv, 0.f);
        float vy = fmaxf(acc[q * 2 + 1] * inv, 0.f);
        op[q] = __floats2half2_rn(vx, vy);
    }
    *(float4*)dstp = outv;
}

// ---------------- launch ----------------
extern "C" void kernel_launch(void* const* d_in, const int* in_sizes, int n_in,
                              void* d_out, int out_size)
{
    const float* feats_author    = (const float*)d_in[0];
    const float* feats_paper     = (const float*)d_in[1];
    const float* W_micro_author  = (const float*)d_in[2];
    const float* W_micro_paper   = (const float*)d_in[3];
    const float* attn_micro_a    = (const float*)d_in[4];
    const float* attn_micro_p    = (const float*)d_in[5];
    const float* W_macro_node_p  = (const float*)d_in[7];
    const float* W_rel_writes    = (const float*)d_in[8];
    const float* W_rel_wb        = (const float*)d_in[9];
    const float* W_rel_cites     = (const float*)d_in[10];
    const float* attn_macro      = (const float*)d_in[11];
    const float* W_res_author    = (const float*)d_in[12];
    const float* b_res_author    = (const float*)d_in[13];
    const float* W_res_paper     = (const float*)d_in[14];
    const float* b_res_paper     = (const float*)d_in[15];
    const float* res_w_author    = (const float*)d_in[16];
    const float* res_w_paper     = (const float*)d_in[17];
    const int*   writes_src      = (const int*)d_in[18];
    const int*   writes_dst      = (const int*)d_in[19];
    const int*   wb_src          = (const int*)d_in[20];
    const int*   wb_dst          = (const int*)d_in[21];
    const int*   cites_src       = (const int*)d_in[22];
    const int*   cites_dst       = (const int*)d_in[23];
    float* out = (float*)d_out;

    __half *PA, *PP, *ft_w, *ft_wb, *ft_c;
    float *elA_aA, *erP_aA, *elP_aP, *erA_aP, *erP_aP, *npscore, *Wnp;
    int *counts, *cursor, *offsets, *partials, *ssort;
    cudaGetSymbolAddress((void**)&PA, g_PA);
    cudaGetSymbolAddress((void**)&PP, g_PP);
    cudaGetSymbolAddress((void**)&elA_aA, g_elA_aA);
    cudaGetSymbolAddress((void**)&erP_aA, g_erP_aA);
    cudaGetSymbolAddress((void**)&elP_aP, g_elP_aP);
    cudaGetSymbolAddress((void**)&erA_aP, g_erA_aP);
    cudaGetSymbolAddress((void**)&erP_aP, g_erP_aP);
    cudaGetSymbolAddress((void**)&ft_w, g_ft_w);
    cudaGetSymbolAddress((void**)&ft_wb, g_ft_wb);
    cudaGetSymbolAddress((void**)&ft_c, g_ft_c);
    cudaGetSymbolAddress((void**)&npscore, g_npscore);
    cudaGetSymbolAddress((void**)&Wnp, g_Wnp);
    cudaGetSymbolAddress((void**)&counts, g_counts);
    cudaGetSymbolAddress((void**)&cursor, g_cursor);
    cudaGetSymbolAddress((void**)&offsets, g_offsets);
    cudaGetSymbolAddress((void**)&partials, g_partials);
    cudaGetSymbolAddress((void**)&ssort, g_ssort);

    static cudaStream_t s2 = nullptr;
    static cudaEvent_t evFork = nullptr, evA = nullptr, evP = nullptr,
                       evGC = nullptr, evS2 = nullptr;
    if (!s2) {
        cudaStreamCreateWithFlags(&s2, cudaStreamNonBlocking);
        cudaEventCreateWithFlags(&evFork, cudaEventDisableTiming);
        cudaEventCreateWithFlags(&evA, cudaEventDisableTiming);
        cudaEventCreateWithFlags(&evP, cudaEventDisableTiming);
        cudaEventCreateWithFlags(&evGC, cudaEventDisableTiming);
        cudaEventCreateWithFlags(&evS2, cudaEventDisableTiming);
    }

    cudaFuncSetAttribute(gemm_multi, cudaFuncAttributeMaxDynamicSharedMemorySize, SMEM_BYTES);
    cudaFuncSetAttribute(gemm_rf_fused3, cudaFuncAttributeMaxDynamicSharedMemorySize, FUSE3_SMEM);
    cudaFuncSetAttribute(gemm_author_fused, cudaFuncAttributeMaxDynamicSharedMemorySize, FUSE_SMEM);

    const int GG = (NA + BM - 1) / BM;
    const int EB = (EDG + 255) / 256;
    const int EB3 = (3 * EDG + 255) / 256;
    const int GB = (NA * 32 + 255) / 256;
    const int NPB = (NP + 7) / 8;

    GemmJob jz = {};

    // ---- fork: s2 runs batched CSR build ----
    cudaEventRecord(evFork, 0);
    cudaStreamWaitEvent(s2, evFork, 0);
    cudaMemsetAsync(counts, 0, NTOT * sizeof(int), s2);
    csr_hist3<<<EB, 256, 0, s2>>>(writes_dst, wb_dst, cites_dst, counts);
    scan_block<<<NBLK3, 256, 0, s2>>>(counts, offsets, partials, NTOT);
    scan_top1k<<<1, 1024, 0, s2>>>(partials, NBLK3);
    scan_add<<<NBLK3, 256, 0, s2>>>(offsets, cursor, partials, NTOT);
    csr_scatter3<<<EB3, 256, 0, s2>>>(writes_src, writes_dst, wb_src, wb_dst,
                                      cites_src, cites_dst, cursor, ssort);

    // ---- main: Wnp + author micro GEMM ----
    wnp_k<<<KH, 256>>>(W_macro_node_p, attn_macro, Wnp);
    {
        GemmJob ja = { feats_author, W_micro_author, nullptr, PA, nullptr, nullptr,
                       attn_micro_a + 0,  elA_aA,
                       attn_micro_p + 32, erA_aP,
                       nullptr, nullptr };
        gemm_multi<<<GG, 256, SMEM_BYTES>>>(ja, jz, jz, 1, NA);
    }
    cudaEventRecord(evA, 0);

    // ---- s2: paper micro GEMM, gather cites, gather written_by, author_fused ----
    {
        GemmJob ja = { feats_paper, W_micro_paper, nullptr, PP, nullptr, nullptr,
                       attn_micro_a + 32, erP_aA,
                       attn_micro_p + 0,  elP_aP,
                       attn_micro_p + 32, erP_aP };
        gemm_multi<<<GG, 256, SMEM_BYTES, s2>>>(ja, jz, jz, 1, NP);
    }
    cudaEventRecord(evP, s2);
    micro_gather<<<GB, 256, 0, s2>>>(ssort, offsets + 2 * 50000,
                                     elP_aP, erP_aP, PP, ft_c, NP);
    cudaEventRecord(evGC, s2);
    cudaStreamWaitEvent(s2, evA, 0);
    micro_gather<<<GB, 256, 0, s2>>>(ssort, offsets + 1 * 50000,
                                     elP_aP, erA_aP, PP, ft_wb, NA);
    gemm_author_fused<<<GG, 256, FUSE_SMEM, s2>>>(feats_author, W_res_author, b_res_author,
                                                  ft_wb, W_rel_wb, res_w_author, out, NA);
    cudaEventRecord(evS2, s2);

    // ---- main: npscore, gather writes, fused paper (res + rf + attention) ----
    npscore_k<<<NPB, 256>>>(feats_paper, Wnp, npscore, NP);
    cudaStreamWaitEvent(0, evP, 0);
    micro_gather<<<GB, 256, 0, 0>>>(ssort, offsets + 0 * 50000,
                                    elA_aA, erP_aA, PA, ft_w, NP);
    cudaStreamWaitEvent(0, evGC, 0);
    gemm_rf_fused3<<<GG, 256, FUSE3_SMEM>>>(feats_paper, W_res_paper, b_res_paper,
                                            ft_w, W_rel_writes, ft_c, W_rel_cites,
                                            npscore, attn_macro, res_w_paper,
                                            out + (size_t)NA * KD, NP);

    // ---- join ----
    cudaStreamWaitEvent(0, evS2, 0);
    join_k<<<1, 1>>>();
}